// round 7
// baseline (speedup 1.0000x reference)
#include <cuda_runtime.h>
#include <cuda_bf16.h>
#include <cstdint>

#define MTOK 8192
#define DDIM 2048
#define FDIM 8192
#define RR   16

// ---------------- device scratch (allocation-free) ----------------
__device__ __align__(16) int8_t g_x1q1[(size_t)MTOK * DDIM];
__device__ __align__(16) int8_t g_x1q0[(size_t)MTOK * DDIM];
__device__ __align__(16) int8_t g_x3q1[(size_t)MTOK * FDIM];
__device__ __align__(16) int8_t g_x3q0[(size_t)MTOK * FDIM];
__device__ __align__(16) int8_t g_wgq1[(size_t)FDIM * DDIM];
__device__ __align__(16) int8_t g_wgq0[(size_t)FDIM * DDIM];
__device__ __align__(16) int8_t g_wuq1[(size_t)FDIM * DDIM];
__device__ __align__(16) int8_t g_wuq0[(size_t)FDIM * DDIM];
__device__ __align__(16) int8_t g_wdq1[(size_t)DDIM * FDIM];
__device__ __align__(16) int8_t g_wdq0[(size_t)DDIM * FDIM];
__device__ float g_scx1[MTOK], g_scx3[MTOK];
__device__ float g_scwg[FDIM], g_scwu[FDIM], g_scwd[DDIM];
__device__ int   g_cmg[FDIM], g_cmu[FDIM], g_cmd[DDIM];
__device__ __align__(1024) float g_yg[(size_t)MTOK * FDIM];
__device__ __align__(1024) float g_yu[(size_t)MTOK * FDIM];
__device__ __align__(16) __nv_bfloat16 g_lgh[FDIM * RR], g_lgl[FDIM * RR];
__device__ __align__(16) __nv_bfloat16 g_luh[FDIM * RR], g_lul[FDIM * RR];
__device__ __align__(16) __nv_bfloat16 g_ldh[DDIM * RR], g_ldl[DDIM * RR];
__device__ __align__(16) __nv_bfloat16 g_tgh[MTOK * RR], g_tgl[MTOK * RR];
__device__ __align__(16) __nv_bfloat16 g_tuh[MTOK * RR], g_tul[MTOK * RR];
__device__ __align__(16) __nv_bfloat16 g_tdh[MTOK * RR], g_tdl[MTOK * RR];

// ---------------- PTX helpers ----------------
__device__ __forceinline__ uint32_t smem_u32(const void* p) {
    uint32_t a;
    asm("{ .reg .u64 t; cvta.to.shared.u64 t, %1; cvt.u32.u64 %0, t; }" : "=r"(a) : "l"(p));
    return a;
}
#define CPA(dst, src) \
    asm volatile("cp.async.cg.shared.global [%0], [%1], 16;\n" :: "r"(dst), "l"(src))
#define CPC() asm volatile("cp.async.commit_group;\n" ::: "memory")
#define CPW(n) asm volatile("cp.async.wait_group %0;\n" :: "n"(n) : "memory")
#define LDSM4(R, addr)                                                          \
    asm volatile("ldmatrix.sync.aligned.m8n8.x4.shared.b16 {%0,%1,%2,%3}, [%4];\n" \
        : "=r"((R)[0]), "=r"((R)[1]), "=r"((R)[2]), "=r"((R)[3]) : "r"(addr))
#define MMA16816(D, A, B0, B1)                                                  \
    asm volatile("mma.sync.aligned.m16n8k16.row.col.f32.bf16.bf16.f32 "         \
        "{%0,%1,%2,%3}, {%4,%5,%6,%7}, {%8,%9}, {%0,%1,%2,%3};\n"               \
        : "+f"((D)[0]), "+f"((D)[1]), "+f"((D)[2]), "+f"((D)[3])                \
        : "r"((A)[0]), "r"((A)[1]), "r"((A)[2]), "r"((A)[3]), "r"(B0), "r"(B1))
#define IMMA16832(D, A, B0, B1)                                                 \
    asm volatile("mma.sync.aligned.m16n8k32.row.col.s32.s8.s8.s32 "             \
        "{%0,%1,%2,%3}, {%4,%5,%6,%7}, {%8,%9}, {%0,%1,%2,%3};\n"               \
        : "+r"((D)[0]), "+r"((D)[1]), "+r"((D)[2]), "+r"((D)[3])                \
        : "r"((A)[0]), "r"((A)[1]), "r"((A)[2]), "r"((A)[3]), "r"(B0), "r"(B1))

// SMEM per stage: A1(10240) A0(10240) B1(10240) B0(10240); rows 128 x 64B, stride 80B
#define RSTR 80
#define OFF_A1 0
#define OFF_A0 10240
#define OFF_B1 20480
#define OFF_B0 30720
#define STG 40960
#define SA_OFF (3 * STG)
#define GEMM_SMEM (3 * STG + 1024)

// ---------------- per-row 2-limb int8 quantization (optionally fused relu-gate) ----------------
// Y==null:  v = X[row][k]
// Y!=null:  v = relu(X[row][k]) * Y[row][k]
__global__ __launch_bounds__(256)
void quant_rows(const float* __restrict__ X, const float* __restrict__ Y, int K,
                int8_t* __restrict__ q1, int8_t* __restrict__ q0, float* __restrict__ sc)
{
    __shared__ float red[8];
    __shared__ float s_sh;
    int row = blockIdx.x, tid = threadIdx.x;
    const float4* x4 = (const float4*)(X + (size_t)row * K);
    const float4* y4 = Y ? (const float4*)(Y + (size_t)row * K) : nullptr;

    float mx = 0.f;
    for (int i = tid; i < K / 4; i += 256) {
        float4 g = x4[i];
        if (Y) {
            float4 u = y4[i];
            g.x = fmaxf(g.x, 0.f) * u.x; g.y = fmaxf(g.y, 0.f) * u.y;
            g.z = fmaxf(g.z, 0.f) * u.z; g.w = fmaxf(g.w, 0.f) * u.w;
        }
        mx = fmaxf(mx, fmaxf(fmaxf(fabsf(g.x), fabsf(g.y)), fmaxf(fabsf(g.z), fabsf(g.w))));
    }
#pragma unroll
    for (int o = 16; o > 0; o >>= 1) mx = fmaxf(mx, __shfl_xor_sync(~0u, mx, o));
    if ((tid & 31) == 0) red[tid >> 5] = mx;
    __syncthreads();
    if (tid == 0) {
        float m = red[0];
#pragma unroll
        for (int w = 1; w < 8; w++) m = fmaxf(m, red[w]);
        float s = m / 127.f + 1e-30f;
        s_sh = s;
        sc[row] = s;
    }
    __syncthreads();
    float rs = 1.f / s_sh;

    for (int i = tid; i < K / 4; i += 256) {
        float4 g = x4[i];
        if (Y) {
            float4 u = y4[i];
            g.x = fmaxf(g.x, 0.f) * u.x; g.y = fmaxf(g.y, 0.f) * u.y;
            g.z = fmaxf(g.z, 0.f) * u.z; g.w = fmaxf(g.w, 0.f) * u.w;
        }
        float vv[4] = {g.x, g.y, g.z, g.w};
        char c1[4], c0[4];
#pragma unroll
        for (int q = 0; q < 4; q++) {
            float u = vv[q] * rs;
            int a = __float2int_rn(u);
            float r = u - (float)a;
            int b = __float2int_rn(r * 254.f);
            c1[q] = (char)a; c0[q] = (char)b;
        }
        *(char4*)(q1 + (size_t)row * K + i * 4) = *(char4*)c1;
        *(char4*)(q0 + (size_t)row * K + i * 4) = *(char4*)c0;
    }
}

// ---------------- column max (atomicMax on non-negative float bits; idempotent) ----------------
__global__ __launch_bounds__(256)
void colmax_kernel(const float* __restrict__ W, int K, int N, int* __restrict__ cm)
{
    int n = blockIdx.x * 256 + threadIdx.x;
    int kc = K / gridDim.y;
    int k0 = blockIdx.y * kc;
    float m = 0.f;
    for (int k = k0; k < k0 + kc; k++)
        m = fmaxf(m, fabsf(W[(size_t)k * N + n]));
    atomicMax(cm + n, __float_as_int(m));
}

// ---------------- transpose + quantize: W [K,N] -> q1T,q0T [N,K], scb[N] ----------------
__global__ __launch_bounds__(256)
void quant_transpose(const float* __restrict__ src, int R, int C,
                     const int* __restrict__ cm,
                     int8_t* __restrict__ d1, int8_t* __restrict__ d0,
                     float* __restrict__ scb)
{
    __shared__ float t[32][33];
    int tx = threadIdx.x, ty = threadIdx.y;
    int x = blockIdx.x * 32 + tx, y0 = blockIdx.y * 32;
#pragma unroll
    for (int j = 0; j < 32; j += 8)
        t[ty + j][tx] = src[(size_t)(y0 + ty + j) * C + x];
    __syncthreads();
    int x2 = y0 + tx, y2 = blockIdx.x * 32;
#pragma unroll
    for (int j = 0; j < 32; j += 8) {
        int n = y2 + ty + j;
        float s = __int_as_float(cm[n]) / 127.f + 1e-30f;
        if (blockIdx.y == 0 && tx == 0) scb[n] = s;
        float u = t[tx][ty + j] / s;
        int a = __float2int_rn(u);
        float r = u - (float)a;
        int b = __float2int_rn(r * 254.f);
        d1[(size_t)n * R + x2] = (char)a;
        d0[(size_t)n * R + x2] = (char)b;
    }
}

// ---------------- Lb [16,N] -> [N,16] bf16 hi/lo ----------------
__global__ __launch_bounds__(256)
void lb_transpose(const float* __restrict__ Lb, int N,
                  __nv_bfloat16* __restrict__ dh, __nv_bfloat16* __restrict__ dl)
{
    int n = blockIdx.x * 256 + threadIdx.x;
    if (n >= N) return;
#pragma unroll
    for (int r = 0; r < RR; r++) {
        float v = Lb[(size_t)r * N + n];
        __nv_bfloat16 h = __float2bfloat16_rn(v);
        dh[(size_t)n * RR + r] = h;
        dl[(size_t)n * RR + r] = __float2bfloat16_rn(v - __bfloat162float(h));
    }
}

// ---------------- LoRA-A: T = X @ A, bf16 hi/lo out; X = fp32 or quantized ----------------
__global__ __launch_bounds__(256)
void lora_a_kernel(const float* __restrict__ Xf,
                   const int8_t* __restrict__ Xq1, const int8_t* __restrict__ Xq0,
                   const float* __restrict__ Xsc,
                   int K,
                   const float* __restrict__ A0, const float* __restrict__ A1,
                   __nv_bfloat16* __restrict__ T0h, __nv_bfloat16* __restrict__ T0l,
                   __nv_bfloat16* __restrict__ T1h, __nv_bfloat16* __restrict__ T1l)
{
    __shared__ float sA0[256 * 17], sA1[256 * 17];
    int tid = threadIdx.x, lane = tid & 31;
    int m = blockIdx.x * 8 + (tid >> 5);
    const bool dual = (A1 != nullptr);
    float rowsc = Xf ? 0.f : Xsc[m];
    float a0[RR], a1[RR];
#pragma unroll
    for (int r = 0; r < RR; r++) { a0[r] = 0.f; a1[r] = 0.f; }

    for (int kt = 0; kt < K; kt += 256) {
        __syncthreads();
#pragma unroll
        for (int t = 0; t < 16; t++) {
            int i = tid + t * 256, row = i >> 4, r = i & 15;
            sA0[row * 17 + r] = A0[(size_t)(kt + row) * RR + r];
            if (dual) sA1[row * 17 + r] = A1[(size_t)(kt + row) * RR + r];
        }
        __syncthreads();
#pragma unroll
        for (int j = 0; j < 8; j++) {
            int k = j * 32 + lane;
            float x;
            if (Xf) x = Xf[(size_t)m * K + kt + k];
            else {
                int v1 = (int)Xq1[(size_t)m * K + kt + k];
                int v0 = (int)Xq0[(size_t)m * K + kt + k];
                x = rowsc * ((float)v1 + (float)v0 * (1.f / 254.f));
            }
#pragma unroll
            for (int r = 0; r < RR; r++) a0[r] += x * sA0[k * 17 + r];
            if (dual) {
#pragma unroll
                for (int r = 0; r < RR; r++) a1[r] += x * sA1[k * 17 + r];
            }
        }
    }
#pragma unroll
    for (int r = 0; r < RR; r++)
#pragma unroll
        for (int o = 16; o > 0; o >>= 1) {
            a0[r] += __shfl_xor_sync(~0u, a0[r], o);
            a1[r] += __shfl_xor_sync(~0u, a1[r], o);
        }
    if (lane == 0) {
#pragma unroll
        for (int r = 0; r < RR; r++) {
            __nv_bfloat16 h = __float2bfloat16_rn(a0[r]);
            T0h[(size_t)m * RR + r] = h;
            T0l[(size_t)m * RR + r] = __float2bfloat16_rn(a0[r] - __bfloat162float(h));
            if (dual) {
                __nv_bfloat16 h1 = __float2bfloat16_rn(a1[r]);
                T1h[(size_t)m * RR + r] = h1;
                T1l[(size_t)m * RR + r] = __float2bfloat16_rn(a1[r] - __bfloat162float(h1));
            }
        }
    }
}

// ---------------- int8 2-limb IMMA GEMM + bf16 LoRA chunk + bias ----------------
// C[m,n] = sa[m]*sb[n]*(acc1 + accX/254) + T@L^T + bias[n]
// A q1/q0 [M,K], B q1/q0 [N,K] (weights transposed & quantized per out-row).
__global__ __launch_bounds__(256, 1)
void gemm_i8(const int8_t* __restrict__ Aq1, const int8_t* __restrict__ Aq0,
             const float* __restrict__ Asc,
             const int8_t* __restrict__ Bq1, const int8_t* __restrict__ Bq0,
             const float* __restrict__ Bsc,
             const __nv_bfloat16* __restrict__ Th, const __nv_bfloat16* __restrict__ Tl,
             const __nv_bfloat16* __restrict__ Lh, const __nv_bfloat16* __restrict__ Ll,
             const float* __restrict__ bias,
             float* __restrict__ C,
             int N, int K)
{
    extern __shared__ char dsm[];
    const uint32_t sb = smem_u32(dsm);
    const int tid = threadIdx.x, lane = tid & 31, wid = tid >> 5;
    const int wm = wid >> 2, wn = wid & 3;            // 2 x 4 warps; warp tile 64m x 32n
    const int bm = blockIdx.y * 128, bn = blockIdx.x * 128;

    int acc1[4][4][4], accX[4][4][4];
#pragma unroll
    for (int a = 0; a < 4; a++)
#pragma unroll
        for (int b = 0; b < 4; b++)
#pragma unroll
            for (int c = 0; c < 4; c++) { acc1[a][b][c] = 0; accX[a][b][c] = 0; }

    auto load_stage = [&](int st, int k0) {
        uint32_t s0 = sb + (uint32_t)st * STG;
#pragma unroll
        for (int j = 0; j < 2; j++) {                 // 512 chunks per region pair
            int c = tid + j * 256;
            int row = c >> 2, cg = (c & 3) * 16;
            uint32_t d = (uint32_t)(row * RSTR + cg);
            CPA(s0 + OFF_A1 + d, Aq1 + (size_t)(bm + row) * K + k0 + cg);
            CPA(s0 + OFF_A0 + d, Aq0 + (size_t)(bm + row) * K + k0 + cg);
            CPA(s0 + OFF_B1 + d, Bq1 + (size_t)(bn + row) * K + k0 + cg);
            CPA(s0 + OFF_B0 + d, Bq0 + (size_t)(bn + row) * K + k0 + cg);
        }
    };

    const int rowb = lane & 15;
    const int cb = (lane >> 4) * 16;

    auto step = [&](uint32_t s0, int ks) {
        uint32_t a1f[4][4], a0f[4][4], b1f[2][4], b0f[2][4];
#pragma unroll
        for (int mi = 0; mi < 4; mi++)
            LDSM4(a1f[mi], s0 + OFF_A1 + (uint32_t)((wm * 64 + mi * 16 + rowb) * RSTR) + ks + cb);
#pragma unroll
        for (int nb = 0; nb < 2; nb++)
            LDSM4(b1f[nb], s0 + OFF_B1 + (uint32_t)((wn * 32 + nb * 16 + rowb) * RSTR) + ks + cb);
#pragma unroll
        for (int mi = 0; mi < 4; mi++)
#pragma unroll
            for (int ni = 0; ni < 4; ni++)
                IMMA16832(acc1[mi][ni], a1f[mi], b1f[ni >> 1][ni & 1], b1f[ni >> 1][(ni & 1) + 2]);
#pragma unroll
        for (int nb = 0; nb < 2; nb++)
            LDSM4(b0f[nb], s0 + OFF_B0 + (uint32_t)((wn * 32 + nb * 16 + rowb) * RSTR) + ks + cb);
#pragma unroll
        for (int mi = 0; mi < 4; mi++)
#pragma unroll
            for (int ni = 0; ni < 4; ni++)
                IMMA16832(accX[mi][ni], a1f[mi], b0f[ni >> 1][ni & 1], b0f[ni >> 1][(ni & 1) + 2]);
#pragma unroll
        for (int mi = 0; mi < 4; mi++)
            LDSM4(a0f[mi], s0 + OFF_A0 + (uint32_t)((wm * 64 + mi * 16 + rowb) * RSTR) + ks + cb);
#pragma unroll
        for (int mi = 0; mi < 4; mi++)
#pragma unroll
            for (int ni = 0; ni < 4; ni++)
                IMMA16832(accX[mi][ni], a0f[mi], b1f[ni >> 1][ni & 1], b1f[ni >> 1][(ni & 1) + 2]);
    };

    const int KC = K / 64;
    load_stage(0, 0); CPC();
    load_stage(1, 64); CPC();

    for (int c = 0; c < KC; c++) {
        if (c + 1 < KC) { CPW(1); } else { CPW(0); }
        __syncthreads();
        if (c + 2 < KC) { load_stage((c + 2) % 3, (c + 2) * 64); CPC(); }
        uint32_t s0 = sb + (uint32_t)(c % 3) * STG;
        step(s0, 0);
        step(s0, 32);
    }

    // ---- LoRA bf16 k16 chunk into separate fp32 accumulator ----
    float accL[4][4][4];
#pragma unroll
    for (int a = 0; a < 4; a++)
#pragma unroll
        for (int b = 0; b < 4; b++)
#pragma unroll
            for (int c = 0; c < 4; c++) accL[a][b][c] = 0.f;

    __syncthreads();
    {
        int row = tid >> 1, hf = tid & 1;             // 128 rows x 32B (16 bf16)
        uint32_t d = (uint32_t)(row * RSTR + hf * 16);
        *(uint4*)(dsm + OFF_A1 + d) = *(const uint4*)(Th + (size_t)(bm + row) * RR + hf * 8);
        *(uint4*)(dsm + OFF_A0 + d) = *(const uint4*)(Tl + (size_t)(bm + row) * RR + hf * 8);
        *(uint4*)(dsm + OFF_B1 + d) = *(const uint4*)(Lh + (size_t)(bn + row) * RR + hf * 8);
        *(uint4*)(dsm + OFF_B0 + d) = *(const uint4*)(Ll + (size_t)(bn + row) * RR + hf * 8);
        // scale rows/cols into smem
        float* sA = (float*)(dsm + SA_OFF);
        float* sB = (float*)(dsm + SA_OFF + 512);
        if (tid < 128) sA[tid] = Asc[bm + tid];
        else           sB[tid - 128] = Bsc[bn + tid - 128];
        __syncthreads();

        uint32_t ah[4][4], al[4][4], bh[2][4], bl[2][4];
#pragma unroll
        for (int mi = 0; mi < 4; mi++) {
            LDSM4(ah[mi], sb + OFF_A1 + (uint32_t)((wm * 64 + mi * 16 + rowb) * RSTR) + cb);
            LDSM4(al[mi], sb + OFF_A0 + (uint32_t)((wm * 64 + mi * 16 + rowb) * RSTR) + cb);
        }
#pragma unroll
        for (int nb = 0; nb < 2; nb++) {
            LDSM4(bh[nb], sb + OFF_B1 + (uint32_t)((wn * 32 + nb * 16 + rowb) * RSTR) + cb);
            LDSM4(bl[nb], sb + OFF_B0 + (uint32_t)((wn * 32 + nb * 16 + rowb) * RSTR) + cb);
        }
#pragma unroll
        for (int mi = 0; mi < 4; mi++)
#pragma unroll
            for (int ni = 0; ni < 4; ni++) {
                MMA16816(accL[mi][ni], ah[mi], bh[ni >> 1][ni & 1], bh[ni >> 1][(ni & 1) + 2]);
                MMA16816(accL[mi][ni], ah[mi], bl[ni >> 1][ni & 1], bl[ni >> 1][(ni & 1) + 2]);
                MMA16816(accL[mi][ni], al[mi], bh[ni >> 1][ni & 1], bh[ni >> 1][(ni & 1) + 2]);
            }
    }

    // ---- epilogue ----
    const float* sA = (const float*)(dsm + SA_OFF);
    const float* sB = (const float*)(dsm + SA_OFF + 512);
#pragma unroll
    for (int mi = 0; mi < 4; mi++) {
        int ml = wm * 64 + mi * 16 + (lane >> 2);
#pragma unroll
        for (int ni = 0; ni < 4; ni++) {
            int nl = wn * 32 + ni * 8 + (lane & 3) * 2;
            float b0v = bias[bn + nl], b1v = bias[bn + nl + 1];
            float sb0 = sB[nl], sb1 = sB[nl + 1];
#pragma unroll
            for (int h2 = 0; h2 < 2; h2++) {
                int m = ml + h2 * 8;
                float sav = sA[m];
                float v0 = sav * sb0 * ((float)acc1[mi][ni][h2 * 2 + 0] +
                                        (float)accX[mi][ni][h2 * 2 + 0] * (1.f / 254.f))
                           + accL[mi][ni][h2 * 2 + 0] + b0v;
                float v1 = sav * sb1 * ((float)acc1[mi][ni][h2 * 2 + 1] +
                                        (float)accX[mi][ni][h2 * 2 + 1] * (1.f / 254.f))
                           + accL[mi][ni][h2 * 2 + 1] + b1v;
                *(float2*)(C + (size_t)(bm + m) * N + bn + nl) = make_float2(v0, v1);
            }
        }
    }
}

// ---------------- launcher ----------------
extern "C" void kernel_launch(void* const* d_in, const int* in_sizes, int n_in,
                              void* d_out, int out_size)
{
    const float* x1     = (const float*)d_in[0];
    const float* w_gate = (const float*)d_in[1];
    const float* b_gate = (const float*)d_in[2];
    const float* wga    = (const float*)d_in[3];
    const float* wgb    = (const float*)d_in[4];
    const float* w_up   = (const float*)d_in[5];
    const float* b_up   = (const float*)d_in[6];
    const float* wua    = (const float*)d_in[7];
    const float* wub    = (const float*)d_in[8];
    const float* w_down = (const float*)d_in[9];
    const float* b_down = (const float*)d_in[10];
    const float* wda    = (const float*)d_in[11];
    const float* wdb    = (const float*)d_in[12];
    float* out = (float*)d_out;

#define SYM(p, s) void* p; cudaGetSymbolAddress(&p, s)
    SYM(x1q1, g_x1q1); SYM(x1q0, g_x1q0); SYM(x3q1, g_x3q1); SYM(x3q0, g_x3q0);
    SYM(wgq1, g_wgq1); SYM(wgq0, g_wgq0); SYM(wuq1, g_wuq1); SYM(wuq0, g_wuq0);
    SYM(wdq1, g_wdq1); SYM(wdq0, g_wdq0);
    SYM(scx1, g_scx1); SYM(scx3, g_scx3);
    SYM(scwg, g_scwg); SYM(scwu, g_scwu); SYM(scwd, g_scwd);
    SYM(cmg, g_cmg); SYM(cmu, g_cmu); SYM(cmd, g_cmd);
    SYM(yg, g_yg); SYM(yu, g_yu);
    SYM(lgh, g_lgh); SYM(lgl, g_lgl); SYM(luh, g_luh); SYM(lul, g_lul);
    SYM(ldh, g_ldh); SYM(ldl, g_ldl);
    SYM(tgh, g_tgh); SYM(tgl, g_tgl); SYM(tuh, g_tuh); SYM(tul, g_tul);
    SYM(tdh, g_tdh); SYM(tdl, g_tdl);
#undef SYM
#define BF(p) ((__nv_bfloat16*)(p))
#define I8(p) ((int8_t*)(p))
#define F32(p) ((float*)(p))

    cudaFuncSetAttribute(gemm_i8, cudaFuncAttributeMaxDynamicSharedMemorySize, GEMM_SMEM);

    // quantize x1 (per-row 2-limb)
    quant_rows<<<MTOK, 256>>>(x1, nullptr, DDIM, I8(x1q1), I8(x1q0), F32(scx1));

    // weight colmax (idempotent atomicMax) + quantizing transpose
    colmax_kernel<<<dim3(FDIM / 256, 16), 256>>>(w_gate, DDIM, FDIM, (int*)cmg);
    colmax_kernel<<<dim3(FDIM / 256, 16), 256>>>(w_up,   DDIM, FDIM, (int*)cmu);
    colmax_kernel<<<dim3(DDIM / 256, 16), 256>>>(w_down, FDIM, DDIM, (int*)cmd);
    quant_transpose<<<dim3(FDIM / 32, DDIM / 32), dim3(32, 8)>>>(
        w_gate, DDIM, FDIM, (const int*)cmg, I8(wgq1), I8(wgq0), F32(scwg));
    quant_transpose<<<dim3(FDIM / 32, DDIM / 32), dim3(32, 8)>>>(
        w_up,   DDIM, FDIM, (const int*)cmu, I8(wuq1), I8(wuq0), F32(scwu));
    quant_transpose<<<dim3(DDIM / 32, FDIM / 32), dim3(32, 8)>>>(
        w_down, FDIM, DDIM, (const int*)cmd, I8(wdq1), I8(wdq0), F32(scwd));

    // LoRA B transposes (bf16 hi/lo)
    lb_transpose<<<FDIM / 256, 256>>>(wgb, FDIM, BF(lgh), BF(lgl));
    lb_transpose<<<FDIM / 256, 256>>>(wub, FDIM, BF(luh), BF(lul));
    lb_transpose<<<DDIM / 256, 256>>>(wdb, DDIM, BF(ldh), BF(ldl));

    // LoRA-A for gate + up (fp32 x1)
    lora_a_kernel<<<MTOK / 8, 256>>>(x1, nullptr, nullptr, nullptr, DDIM, wga, wua,
                                     BF(tgh), BF(tgl), BF(tuh), BF(tul));

    // gate GEMM -> yg ; up GEMM -> yu
    gemm_i8<<<dim3(FDIM / 128, MTOK / 128), 256, GEMM_SMEM>>>(
        I8(x1q1), I8(x1q0), F32(scx1), I8(wgq1), I8(wgq0), F32(scwg),
        BF(tgh), BF(tgl), BF(lgh), BF(lgl), b_gate, F32(yg), FDIM, DDIM);
    gemm_i8<<<dim3(FDIM / 128, MTOK / 128), 256, GEMM_SMEM>>>(
        I8(x1q1), I8(x1q0), F32(scx1), I8(wuq1), I8(wuq0), F32(scwu),
        BF(tuh), BF(tul), BF(luh), BF(lul), b_up, F32(yu), FDIM, DDIM);

    // x3 = relu(yg)*yu, quantize per-row
    quant_rows<<<MTOK, 256>>>(F32(yg), F32(yu), FDIM, I8(x3q1), I8(x3q0), F32(scx3));

    // LoRA-A for down (reads quantized x3)
    lora_a_kernel<<<MTOK / 8, 256>>>(nullptr, I8(x3q1), I8(x3q0), F32(scx3), FDIM, wda, nullptr,
                                     BF(tdh), BF(tdl), nullptr, nullptr);

    // down GEMM -> out
    gemm_i8<<<dim3(DDIM / 128, MTOK / 128), 256, GEMM_SMEM>>>(
        I8(x3q1), I8(x3q0), F32(scx3), I8(wdq1), I8(wdq0), F32(scwd),
        BF(tdh), BF(tdl), BF(ldh), BF(ldl), b_down, out, DDIM, FDIM);
}

// round 8
// speedup vs baseline: 1.0017x; 1.0017x over previous
#include <cuda_runtime.h>
#include <cuda_bf16.h>
#include <cstdint>

#define MTOK 8192
#define DDIM 2048
#define FDIM 8192
#define RR   16

// ---------------- device scratch (allocation-free) ----------------
__device__ __align__(16) int8_t g_x1q1[(size_t)MTOK * DDIM];
__device__ __align__(16) int8_t g_x1q0[(size_t)MTOK * DDIM];
__device__ __align__(16) int8_t g_x3q1[(size_t)MTOK * FDIM];
__device__ __align__(16) int8_t g_x3q0[(size_t)MTOK * FDIM];
__device__ __align__(16) int8_t g_wgq1[(size_t)FDIM * DDIM];
__device__ __align__(16) int8_t g_wgq0[(size_t)FDIM * DDIM];
__device__ __align__(16) int8_t g_wuq1[(size_t)FDIM * DDIM];
__device__ __align__(16) int8_t g_wuq0[(size_t)FDIM * DDIM];
__device__ __align__(16) int8_t g_wdq1[(size_t)DDIM * FDIM];
__device__ __align__(16) int8_t g_wdq0[(size_t)DDIM * FDIM];
__device__ float g_scx1[MTOK], g_scx3[MTOK];
__device__ float g_scwg[FDIM], g_scwu[FDIM], g_scwd[DDIM];
__device__ int   g_cmg[FDIM], g_cmu[FDIM], g_cmd[DDIM];
__device__ __align__(1024) float g_yg[(size_t)MTOK * FDIM];
__device__ __align__(1024) float g_yu[(size_t)MTOK * FDIM];
__device__ __align__(16) __nv_bfloat16 g_lgh[FDIM * RR], g_lgl[FDIM * RR];
__device__ __align__(16) __nv_bfloat16 g_luh[FDIM * RR], g_lul[FDIM * RR];
__device__ __align__(16) __nv_bfloat16 g_ldh[DDIM * RR], g_ldl[DDIM * RR];
__device__ __align__(16) __nv_bfloat16 g_tgh[MTOK * RR], g_tgl[MTOK * RR];
__device__ __align__(16) __nv_bfloat16 g_tuh[MTOK * RR], g_tul[MTOK * RR];
__device__ __align__(16) __nv_bfloat16 g_tdh[MTOK * RR], g_tdl[MTOK * RR];

// ---------------- PTX helpers ----------------
__device__ __forceinline__ uint32_t smem_u32(const void* p) {
    uint32_t a;
    asm("{ .reg .u64 t; cvta.to.shared.u64 t, %1; cvt.u32.u64 %0, t; }" : "=r"(a) : "l"(p));
    return a;
}
#define CPA(dst, src) \
    asm volatile("cp.async.cg.shared.global [%0], [%1], 16;\n" :: "r"(dst), "l"(src))
#define CPC() asm volatile("cp.async.commit_group;\n" ::: "memory")
#define CPW(n) asm volatile("cp.async.wait_group %0;\n" :: "n"(n) : "memory")
#define LDSM4(R, addr)                                                          \
    asm volatile("ldmatrix.sync.aligned.m8n8.x4.shared.b16 {%0,%1,%2,%3}, [%4];\n" \
        : "=r"((R)[0]), "=r"((R)[1]), "=r"((R)[2]), "=r"((R)[3]) : "r"(addr))
#define MMA16816(D, A, B0, B1)                                                  \
    asm volatile("mma.sync.aligned.m16n8k16.row.col.f32.bf16.bf16.f32 "         \
        "{%0,%1,%2,%3}, {%4,%5,%6,%7}, {%8,%9}, {%0,%1,%2,%3};\n"               \
        : "+f"((D)[0]), "+f"((D)[1]), "+f"((D)[2]), "+f"((D)[3])                \
        : "r"((A)[0]), "r"((A)[1]), "r"((A)[2]), "r"((A)[3]), "r"(B0), "r"(B1))
#define IMMA16832(D, A, B0, B1)                                                 \
    asm volatile("mma.sync.aligned.m16n8k32.row.col.s32.s8.s8.s32 "             \
        "{%0,%1,%2,%3}, {%4,%5,%6,%7}, {%8,%9}, {%0,%1,%2,%3};\n"               \
        : "+r"((D)[0]), "+r"((D)[1]), "+r"((D)[2]), "+r"((D)[3])                \
        : "r"((A)[0]), "r"((A)[1]), "r"((A)[2]), "r"((A)[3]), "r"(B0), "r"(B1))

// SMEM per stage: A1(10240) A0(10240) B1(10240) B0(10240); rows 128 x 64B, stride 80B
#define RSTR 80
#define OFF_A1 0
#define OFF_A0 10240
#define OFF_B1 20480
#define OFF_B0 30720
#define STG 40960
#define SA_OFF (3 * STG)
#define GEMM_SMEM (3 * STG + 1024)

// ---------------- per-row 2-limb int8 quantization (optionally fused relu-gate) ----------------
// Y==null:  v = X[row][k]
// Y!=null:  v = relu(X[row][k]) * Y[row][k]
__global__ __launch_bounds__(256)
void quant_rows(const float* __restrict__ X, const float* __restrict__ Y, int K,
                int8_t* __restrict__ q1, int8_t* __restrict__ q0, float* __restrict__ sc)
{
    __shared__ float red[8];
    __shared__ float s_sh;
    int row = blockIdx.x, tid = threadIdx.x;
    const float4* x4 = (const float4*)(X + (size_t)row * K);
    const float4* y4 = Y ? (const float4*)(Y + (size_t)row * K) : nullptr;

    float mx = 0.f;
    for (int i = tid; i < K / 4; i += 256) {
        float4 g = x4[i];
        if (Y) {
            float4 u = y4[i];
            g.x = fmaxf(g.x, 0.f) * u.x; g.y = fmaxf(g.y, 0.f) * u.y;
            g.z = fmaxf(g.z, 0.f) * u.z; g.w = fmaxf(g.w, 0.f) * u.w;
        }
        mx = fmaxf(mx, fmaxf(fmaxf(fabsf(g.x), fabsf(g.y)), fmaxf(fabsf(g.z), fabsf(g.w))));
    }
#pragma unroll
    for (int o = 16; o > 0; o >>= 1) mx = fmaxf(mx, __shfl_xor_sync(~0u, mx, o));
    if ((tid & 31) == 0) red[tid >> 5] = mx;
    __syncthreads();
    if (tid == 0) {
        float m = red[0];
#pragma unroll
        for (int w = 1; w < 8; w++) m = fmaxf(m, red[w]);
        float s = m / 127.f + 1e-30f;
        s_sh = s;
        sc[row] = s;
    }
    __syncthreads();
    float rs = 1.f / s_sh;

    for (int i = tid; i < K / 4; i += 256) {
        float4 g = x4[i];
        if (Y) {
            float4 u = y4[i];
            g.x = fmaxf(g.x, 0.f) * u.x; g.y = fmaxf(g.y, 0.f) * u.y;
            g.z = fmaxf(g.z, 0.f) * u.z; g.w = fmaxf(g.w, 0.f) * u.w;
        }
        float vv[4] = {g.x, g.y, g.z, g.w};
        char c1[4], c0[4];
#pragma unroll
        for (int q = 0; q < 4; q++) {
            float u = vv[q] * rs;
            int a = __float2int_rn(u);
            float r = u - (float)a;
            int b = __float2int_rn(r * 254.f);
            c1[q] = (char)a; c0[q] = (char)b;
        }
        *(char4*)(q1 + (size_t)row * K + i * 4) = *(char4*)c1;
        *(char4*)(q0 + (size_t)row * K + i * 4) = *(char4*)c0;
    }
}

// ---------------- column max (atomicMax on non-negative float bits; idempotent) ----------------
__global__ __launch_bounds__(256)
void colmax_kernel(const float* __restrict__ W, int K, int N, int* __restrict__ cm)
{
    int n = blockIdx.x * 256 + threadIdx.x;
    int kc = K / gridDim.y;
    int k0 = blockIdx.y * kc;
    float m = 0.f;
    for (int k = k0; k < k0 + kc; k++)
        m = fmaxf(m, fabsf(W[(size_t)k * N + n]));
    atomicMax(cm + n, __float_as_int(m));
}

// ---------------- transpose + quantize: W [K,N] -> q1T,q0T [N,K], scb[N] ----------------
__global__ __launch_bounds__(256)
void quant_transpose(const float* __restrict__ src, int R, int C,
                     const int* __restrict__ cm,
                     int8_t* __restrict__ d1, int8_t* __restrict__ d0,
                     float* __restrict__ scb)
{
    __shared__ float t[32][33];
    int tx = threadIdx.x, ty = threadIdx.y;
    int x = blockIdx.x * 32 + tx, y0 = blockIdx.y * 32;
#pragma unroll
    for (int j = 0; j < 32; j += 8)
        t[ty + j][tx] = src[(size_t)(y0 + ty + j) * C + x];
    __syncthreads();
    int x2 = y0 + tx, y2 = blockIdx.x * 32;
#pragma unroll
    for (int j = 0; j < 32; j += 8) {
        int n = y2 + ty + j;
        float s = __int_as_float(cm[n]) / 127.f + 1e-30f;
        if (blockIdx.y == 0 && tx == 0) scb[n] = s;
        float u = t[tx][ty + j] / s;
        int a = __float2int_rn(u);
        float r = u - (float)a;
        int b = __float2int_rn(r * 254.f);
        d1[(size_t)n * R + x2] = (char)a;
        d0[(size_t)n * R + x2] = (char)b;
    }
}

// ---------------- Lb [16,N] -> [N,16] bf16 hi/lo ----------------
__global__ __launch_bounds__(256)
void lb_transpose(const float* __restrict__ Lb, int N,
                  __nv_bfloat16* __restrict__ dh, __nv_bfloat16* __restrict__ dl)
{
    int n = blockIdx.x * 256 + threadIdx.x;
    if (n >= N) return;
#pragma unroll
    for (int r = 0; r < RR; r++) {
        float v = Lb[(size_t)r * N + n];
        __nv_bfloat16 h = __float2bfloat16_rn(v);
        dh[(size_t)n * RR + r] = h;
        dl[(size_t)n * RR + r] = __float2bfloat16_rn(v - __bfloat162float(h));
    }
}

// ---------------- LoRA-A: T = X @ A, bf16 hi/lo out; X = fp32 or quantized ----------------
__global__ __launch_bounds__(256)
void lora_a_kernel(const float* __restrict__ Xf,
                   const int8_t* __restrict__ Xq1, const int8_t* __restrict__ Xq0,
                   const float* __restrict__ Xsc,
                   int K,
                   const float* __restrict__ A0, const float* __restrict__ A1,
                   __nv_bfloat16* __restrict__ T0h, __nv_bfloat16* __restrict__ T0l,
                   __nv_bfloat16* __restrict__ T1h, __nv_bfloat16* __restrict__ T1l)
{
    __shared__ float sA0[256 * 17], sA1[256 * 17];
    int tid = threadIdx.x, lane = tid & 31;
    int m = blockIdx.x * 8 + (tid >> 5);
    const bool dual = (A1 != nullptr);
    float rowsc = Xf ? 0.f : Xsc[m];
    float a0[RR], a1[RR];
#pragma unroll
    for (int r = 0; r < RR; r++) { a0[r] = 0.f; a1[r] = 0.f; }

    for (int kt = 0; kt < K; kt += 256) {
        __syncthreads();
#pragma unroll
        for (int t = 0; t < 16; t++) {
            int i = tid + t * 256, row = i >> 4, r = i & 15;
            sA0[row * 17 + r] = A0[(size_t)(kt + row) * RR + r];
            if (dual) sA1[row * 17 + r] = A1[(size_t)(kt + row) * RR + r];
        }
        __syncthreads();
#pragma unroll
        for (int j = 0; j < 8; j++) {
            int k = j * 32 + lane;
            float x;
            if (Xf) x = Xf[(size_t)m * K + kt + k];
            else {
                int v1 = (int)Xq1[(size_t)m * K + kt + k];
                int v0 = (int)Xq0[(size_t)m * K + kt + k];
                x = rowsc * ((float)v1 + (float)v0 * (1.f / 254.f));
            }
#pragma unroll
            for (int r = 0; r < RR; r++) a0[r] += x * sA0[k * 17 + r];
            if (dual) {
#pragma unroll
                for (int r = 0; r < RR; r++) a1[r] += x * sA1[k * 17 + r];
            }
        }
    }
#pragma unroll
    for (int r = 0; r < RR; r++)
#pragma unroll
        for (int o = 16; o > 0; o >>= 1) {
            a0[r] += __shfl_xor_sync(~0u, a0[r], o);
            a1[r] += __shfl_xor_sync(~0u, a1[r], o);
        }
    if (lane == 0) {
#pragma unroll
        for (int r = 0; r < RR; r++) {
            __nv_bfloat16 h = __float2bfloat16_rn(a0[r]);
            T0h[(size_t)m * RR + r] = h;
            T0l[(size_t)m * RR + r] = __float2bfloat16_rn(a0[r] - __bfloat162float(h));
            if (dual) {
                __nv_bfloat16 h1 = __float2bfloat16_rn(a1[r]);
                T1h[(size_t)m * RR + r] = h1;
                T1l[(size_t)m * RR + r] = __float2bfloat16_rn(a1[r] - __bfloat162float(h1));
            }
        }
    }
}

// ---------------- int8 2-limb IMMA GEMM + bf16 LoRA chunk + bias ----------------
// C[m,n] = sa[m]*sb[n]*(acc1 + accX/254) + T@L^T + bias[n]
// A q1/q0 [M,K], B q1/q0 [N,K] (weights transposed & quantized per out-row).
__global__ __launch_bounds__(256, 1)
void gemm_i8(const int8_t* __restrict__ Aq1, const int8_t* __restrict__ Aq0,
             const float* __restrict__ Asc,
             const int8_t* __restrict__ Bq1, const int8_t* __restrict__ Bq0,
             const float* __restrict__ Bsc,
             const __nv_bfloat16* __restrict__ Th, const __nv_bfloat16* __restrict__ Tl,
             const __nv_bfloat16* __restrict__ Lh, const __nv_bfloat16* __restrict__ Ll,
             const float* __restrict__ bias,
             float* __restrict__ C,
             int N, int K)
{
    extern __shared__ char dsm[];
    const uint32_t sb = smem_u32(dsm);
    const int tid = threadIdx.x, lane = tid & 31, wid = tid >> 5;
    const int wm = wid >> 2, wn = wid & 3;            // 2 x 4 warps; warp tile 64m x 32n
    const int bm = blockIdx.y * 128, bn = blockIdx.x * 128;

    int acc1[4][4][4], accX[4][4][4];
#pragma unroll
    for (int a = 0; a < 4; a++)
#pragma unroll
        for (int b = 0; b < 4; b++)
#pragma unroll
            for (int c = 0; c < 4; c++) { acc1[a][b][c] = 0; accX[a][b][c] = 0; }

    auto load_stage = [&](int st, int k0) {
        uint32_t s0 = sb + (uint32_t)st * STG;
#pragma unroll
        for (int j = 0; j < 2; j++) {                 // 512 chunks per region pair
            int c = tid + j * 256;
            int row = c >> 2, cg = (c & 3) * 16;
            uint32_t d = (uint32_t)(row * RSTR + cg);
            CPA(s0 + OFF_A1 + d, Aq1 + (size_t)(bm + row) * K + k0 + cg);
            CPA(s0 + OFF_A0 + d, Aq0 + (size_t)(bm + row) * K + k0 + cg);
            CPA(s0 + OFF_B1 + d, Bq1 + (size_t)(bn + row) * K + k0 + cg);
            CPA(s0 + OFF_B0 + d, Bq0 + (size_t)(bn + row) * K + k0 + cg);
        }
    };

    const int rowb = lane & 15;
    const int cb = (lane >> 4) * 16;

    auto step = [&](uint32_t s0, int ks) {
        uint32_t a1f[4][4], a0f[4][4], b1f[2][4], b0f[2][4];
#pragma unroll
        for (int mi = 0; mi < 4; mi++)
            LDSM4(a1f[mi], s0 + OFF_A1 + (uint32_t)((wm * 64 + mi * 16 + rowb) * RSTR) + ks + cb);
#pragma unroll
        for (int nb = 0; nb < 2; nb++)
            LDSM4(b1f[nb], s0 + OFF_B1 + (uint32_t)((wn * 32 + nb * 16 + rowb) * RSTR) + ks + cb);
#pragma unroll
        for (int mi = 0; mi < 4; mi++)
#pragma unroll
            for (int ni = 0; ni < 4; ni++)
                IMMA16832(acc1[mi][ni], a1f[mi], b1f[ni >> 1][ni & 1], b1f[ni >> 1][(ni & 1) + 2]);
#pragma unroll
        for (int nb = 0; nb < 2; nb++)
            LDSM4(b0f[nb], s0 + OFF_B0 + (uint32_t)((wn * 32 + nb * 16 + rowb) * RSTR) + ks + cb);
#pragma unroll
        for (int mi = 0; mi < 4; mi++)
#pragma unroll
            for (int ni = 0; ni < 4; ni++)
                IMMA16832(accX[mi][ni], a1f[mi], b0f[ni >> 1][ni & 1], b0f[ni >> 1][(ni & 1) + 2]);
#pragma unroll
        for (int mi = 0; mi < 4; mi++)
            LDSM4(a0f[mi], s0 + OFF_A0 + (uint32_t)((wm * 64 + mi * 16 + rowb) * RSTR) + ks + cb);
#pragma unroll
        for (int mi = 0; mi < 4; mi++)
#pragma unroll
            for (int ni = 0; ni < 4; ni++)
                IMMA16832(accX[mi][ni], a0f[mi], b1f[ni >> 1][ni & 1], b1f[ni >> 1][(ni & 1) + 2]);
    };

    const int KC = K / 64;
    load_stage(0, 0); CPC();
    load_stage(1, 64); CPC();

    for (int c = 0; c < KC; c++) {
        if (c + 1 < KC) { CPW(1); } else { CPW(0); }
        __syncthreads();
        if (c + 2 < KC) { load_stage((c + 2) % 3, (c + 2) * 64); CPC(); }
        uint32_t s0 = sb + (uint32_t)(c % 3) * STG;
        step(s0, 0);
        step(s0, 32);
    }

    // ---- LoRA bf16 k16 chunk into separate fp32 accumulator ----
    float accL[4][4][4];
#pragma unroll
    for (int a = 0; a < 4; a++)
#pragma unroll
        for (int b = 0; b < 4; b++)
#pragma unroll
            for (int c = 0; c < 4; c++) accL[a][b][c] = 0.f;

    __syncthreads();
    {
        int row = tid >> 1, hf = tid & 1;             // 128 rows x 32B (16 bf16)
        uint32_t d = (uint32_t)(row * RSTR + hf * 16);
        *(uint4*)(dsm + OFF_A1 + d) = *(const uint4*)(Th + (size_t)(bm + row) * RR + hf * 8);
        *(uint4*)(dsm + OFF_A0 + d) = *(const uint4*)(Tl + (size_t)(bm + row) * RR + hf * 8);
        *(uint4*)(dsm + OFF_B1 + d) = *(const uint4*)(Lh + (size_t)(bn + row) * RR + hf * 8);
        *(uint4*)(dsm + OFF_B0 + d) = *(const uint4*)(Ll + (size_t)(bn + row) * RR + hf * 8);
        // scale rows/cols into smem
        float* sA = (float*)(dsm + SA_OFF);
        float* sB = (float*)(dsm + SA_OFF + 512);
        if (tid < 128) sA[tid] = Asc[bm + tid];
        else           sB[tid - 128] = Bsc[bn + tid - 128];
        __syncthreads();

        uint32_t ah[4][4], al[4][4], bh[2][4], bl[2][4];
#pragma unroll
        for (int mi = 0; mi < 4; mi++) {
            LDSM4(ah[mi], sb + OFF_A1 + (uint32_t)((wm * 64 + mi * 16 + rowb) * RSTR) + cb);
            LDSM4(al[mi], sb + OFF_A0 + (uint32_t)((wm * 64 + mi * 16 + rowb) * RSTR) + cb);
        }
#pragma unroll
        for (int nb = 0; nb < 2; nb++) {
            LDSM4(bh[nb], sb + OFF_B1 + (uint32_t)((wn * 32 + nb * 16 + rowb) * RSTR) + cb);
            LDSM4(bl[nb], sb + OFF_B0 + (uint32_t)((wn * 32 + nb * 16 + rowb) * RSTR) + cb);
        }
#pragma unroll
        for (int mi = 0; mi < 4; mi++)
#pragma unroll
            for (int ni = 0; ni < 4; ni++) {
                MMA16816(accL[mi][ni], ah[mi], bh[ni >> 1][ni & 1], bh[ni >> 1][(ni & 1) + 2]);
                MMA16816(accL[mi][ni], ah[mi], bl[ni >> 1][ni & 1], bl[ni >> 1][(ni & 1) + 2]);
                MMA16816(accL[mi][ni], al[mi], bh[ni >> 1][ni & 1], bh[ni >> 1][(ni & 1) + 2]);
            }
    }

    // ---- epilogue ----
    const float* sA = (const float*)(dsm + SA_OFF);
    const float* sB = (const float*)(dsm + SA_OFF + 512);
#pragma unroll
    for (int mi = 0; mi < 4; mi++) {
        int ml = wm * 64 + mi * 16 + (lane >> 2);
#pragma unroll
        for (int ni = 0; ni < 4; ni++) {
            int nl = wn * 32 + ni * 8 + (lane & 3) * 2;
            float b0v = bias[bn + nl], b1v = bias[bn + nl + 1];
            float sb0 = sB[nl], sb1 = sB[nl + 1];
#pragma unroll
            for (int h2 = 0; h2 < 2; h2++) {
                int m = ml + h2 * 8;
                float sav = sA[m];
                float v0 = sav * sb0 * ((float)acc1[mi][ni][h2 * 2 + 0] +
                                        (float)accX[mi][ni][h2 * 2 + 0] * (1.f / 254.f))
                           + accL[mi][ni][h2 * 2 + 0] + b0v;
                float v1 = sav * sb1 * ((float)acc1[mi][ni][h2 * 2 + 1] +
                                        (float)accX[mi][ni][h2 * 2 + 1] * (1.f / 254.f))
                           + accL[mi][ni][h2 * 2 + 1] + b1v;
                *(float2*)(C + (size_t)(bm + m) * N + bn + nl) = make_float2(v0, v1);
            }
        }
    }
}

// ---------------- launcher ----------------
extern "C" void kernel_launch(void* const* d_in, const int* in_sizes, int n_in,
                              void* d_out, int out_size)
{
    const float* x1     = (const float*)d_in[0];
    const float* w_gate = (const float*)d_in[1];
    const float* b_gate = (const float*)d_in[2];
    const float* wga    = (const float*)d_in[3];
    const float* wgb    = (const float*)d_in[4];
    const float* w_up   = (const float*)d_in[5];
    const float* b_up   = (const float*)d_in[6];
    const float* wua    = (const float*)d_in[7];
    const float* wub    = (const float*)d_in[8];
    const float* w_down = (const float*)d_in[9];
    const float* b_down = (const float*)d_in[10];
    const float* wda    = (const float*)d_in[11];
    const float* wdb    = (const float*)d_in[12];
    float* out = (float*)d_out;

#define SYM(p, s) void* p; cudaGetSymbolAddress(&p, s)
    SYM(x1q1, g_x1q1); SYM(x1q0, g_x1q0); SYM(x3q1, g_x3q1); SYM(x3q0, g_x3q0);
    SYM(wgq1, g_wgq1); SYM(wgq0, g_wgq0); SYM(wuq1, g_wuq1); SYM(wuq0, g_wuq0);
    SYM(wdq1, g_wdq1); SYM(wdq0, g_wdq0);
    SYM(scx1, g_scx1); SYM(scx3, g_scx3);
    SYM(scwg, g_scwg); SYM(scwu, g_scwu); SYM(scwd, g_scwd);
    SYM(cmg, g_cmg); SYM(cmu, g_cmu); SYM(cmd, g_cmd);
    SYM(yg, g_yg); SYM(yu, g_yu);
    SYM(lgh, g_lgh); SYM(lgl, g_lgl); SYM(luh, g_luh); SYM(lul, g_lul);
    SYM(ldh, g_ldh); SYM(ldl, g_ldl);
    SYM(tgh, g_tgh); SYM(tgl, g_tgl); SYM(tuh, g_tuh); SYM(tul, g_tul);
    SYM(tdh, g_tdh); SYM(tdl, g_tdl);
#undef SYM
#define BF(p) ((__nv_bfloat16*)(p))
#define I8(p) ((int8_t*)(p))
#define F32(p) ((float*)(p))

    cudaFuncSetAttribute(gemm_i8, cudaFuncAttributeMaxDynamicSharedMemorySize, GEMM_SMEM);

    // quantize x1 (per-row 2-limb)
    quant_rows<<<MTOK, 256>>>(x1, nullptr, DDIM, I8(x1q1), I8(x1q0), F32(scx1));

    // weight colmax (idempotent atomicMax) + quantizing transpose
    colmax_kernel<<<dim3(FDIM / 256, 16), 256>>>(w_gate, DDIM, FDIM, (int*)cmg);
    colmax_kernel<<<dim3(FDIM / 256, 16), 256>>>(w_up,   DDIM, FDIM, (int*)cmu);
    colmax_kernel<<<dim3(DDIM / 256, 16), 256>>>(w_down, FDIM, DDIM, (int*)cmd);
    quant_transpose<<<dim3(FDIM / 32, DDIM / 32), dim3(32, 8)>>>(
        w_gate, DDIM, FDIM, (const int*)cmg, I8(wgq1), I8(wgq0), F32(scwg));
    quant_transpose<<<dim3(FDIM / 32, DDIM / 32), dim3(32, 8)>>>(
        w_up,   DDIM, FDIM, (const int*)cmu, I8(wuq1), I8(wuq0), F32(scwu));
    quant_transpose<<<dim3(DDIM / 32, FDIM / 32), dim3(32, 8)>>>(
        w_down, FDIM, DDIM, (const int*)cmd, I8(wdq1), I8(wdq0), F32(scwd));

    // LoRA B transposes (bf16 hi/lo)
    lb_transpose<<<FDIM / 256, 256>>>(wgb, FDIM, BF(lgh), BF(lgl));
    lb_transpose<<<FDIM / 256, 256>>>(wub, FDIM, BF(luh), BF(lul));
    lb_transpose<<<DDIM / 256, 256>>>(wdb, DDIM, BF(ldh), BF(ldl));

    // LoRA-A for gate + up (fp32 x1)
    lora_a_kernel<<<MTOK / 8, 256>>>(x1, nullptr, nullptr, nullptr, DDIM, wga, wua,
                                     BF(tgh), BF(tgl), BF(tuh), BF(tul));

    // gate GEMM -> yg ; up GEMM -> yu
    gemm_i8<<<dim3(FDIM / 128, MTOK / 128), 256, GEMM_SMEM>>>(
        I8(x1q1), I8(x1q0), F32(scx1), I8(wgq1), I8(wgq0), F32(scwg),
        BF(tgh), BF(tgl), BF(lgh), BF(lgl), b_gate, F32(yg), FDIM, DDIM);
    gemm_i8<<<dim3(FDIM / 128, MTOK / 128), 256, GEMM_SMEM>>>(
        I8(x1q1), I8(x1q0), F32(scx1), I8(wuq1), I8(wuq0), F32(scwu),
        BF(tuh), BF(tul), BF(luh), BF(lul), b_up, F32(yu), FDIM, DDIM);

    // x3 = relu(yg)*yu, quantize per-row
    quant_rows<<<MTOK, 256>>>(F32(yg), F32(yu), FDIM, I8(x3q1), I8(x3q0), F32(scx3));

    // LoRA-A for down (reads quantized x3)
    lora_a_kernel<<<MTOK / 8, 256>>>(nullptr, I8(x3q1), I8(x3q0), F32(scx3), FDIM, wda, nullptr,
                                     BF(tdh), BF(tdl), nullptr, nullptr);

    // down GEMM -> out
    gemm_i8<<<dim3(DDIM / 128, MTOK / 128), 256, GEMM_SMEM>>>(
        I8(x3q1), I8(x3q0), F32(scx3), I8(wdq1), I8(wdq0), F32(scwd),
        BF(tdh), BF(tdl), BF(ldh), BF(ldl), b_down, out, DDIM, FDIM);
}

// round 9
// speedup vs baseline: 2.2395x; 2.2358x over previous
#include <cuda_runtime.h>
#include <cuda_bf16.h>
#include <cstdint>

#define MTOK 8192
#define DDIM 2048
#define FDIM 8192
#define RR   16

// ---------------- device scratch (allocation-free) ----------------
__device__ __align__(1024) __nv_bfloat16 g_x1h[(size_t)MTOK * DDIM];
__device__ __align__(1024) __nv_bfloat16 g_x1l[(size_t)MTOK * DDIM];
__device__ __align__(1024) __nv_bfloat16 g_x3h[(size_t)MTOK * FDIM];
__device__ __align__(1024) __nv_bfloat16 g_x3l[(size_t)MTOK * FDIM];
__device__ __align__(1024) __nv_bfloat16 g_wgh[(size_t)FDIM * DDIM];
__device__ __align__(1024) __nv_bfloat16 g_wgl[(size_t)FDIM * DDIM];
__device__ __align__(1024) __nv_bfloat16 g_wuh[(size_t)FDIM * DDIM];
__device__ __align__(1024) __nv_bfloat16 g_wul[(size_t)FDIM * DDIM];
__device__ __align__(1024) __nv_bfloat16 g_wdh[(size_t)DDIM * FDIM];
__device__ __align__(1024) __nv_bfloat16 g_wdl[(size_t)DDIM * FDIM];
__device__ __align__(1024) __nv_bfloat16 g_lgh[FDIM * RR], g_lgl[FDIM * RR];
__device__ __align__(1024) __nv_bfloat16 g_luh[FDIM * RR], g_lul[FDIM * RR];
__device__ __align__(1024) __nv_bfloat16 g_ldh[DDIM * RR], g_ldl[DDIM * RR];
__device__ __align__(1024) __nv_bfloat16 g_tgh[MTOK * RR], g_tgl[MTOK * RR];
__device__ __align__(1024) __nv_bfloat16 g_tuh[MTOK * RR], g_tul[MTOK * RR];
__device__ __align__(1024) __nv_bfloat16 g_tdh[MTOK * RR], g_tdl[MTOK * RR];
// LoRA-A transposed [16,K] h/l + fp32 T accumulators
__device__ __align__(1024) __nv_bfloat16 g_gaTh[RR * DDIM], g_gaTl[RR * DDIM];
__device__ __align__(1024) __nv_bfloat16 g_uaTh[RR * DDIM], g_uaTl[RR * DDIM];
__device__ __align__(1024) __nv_bfloat16 g_daTh[RR * FDIM], g_daTl[RR * FDIM];
__device__ __align__(1024) float g_Tgf[MTOK * RR], g_Tuf[MTOK * RR], g_Tdf[MTOK * RR];

// ---------------- PTX helpers ----------------
__device__ __forceinline__ uint32_t smem_u32(const void* p) {
    uint32_t a;
    asm("{ .reg .u64 t; cvta.to.shared.u64 t, %1; cvt.u32.u64 %0, t; }" : "=r"(a) : "l"(p));
    return a;
}
#define CPA(dst, src) \
    asm volatile("cp.async.cg.shared.global [%0], [%1], 16;\n" :: "r"(dst), "l"(src))
#define CPC() asm volatile("cp.async.commit_group;\n" ::: "memory")
#define CPW(n) asm volatile("cp.async.wait_group %0;\n" :: "n"(n) : "memory")
#define LDSM4(R, addr)                                                          \
    asm volatile("ldmatrix.sync.aligned.m8n8.x4.shared.b16 {%0,%1,%2,%3}, [%4];\n" \
        : "=r"((R)[0]), "=r"((R)[1]), "=r"((R)[2]), "=r"((R)[3]) : "r"(addr))
#define MMA16816(D, A, B0, B1)                                                  \
    asm volatile("mma.sync.aligned.m16n8k16.row.col.f32.bf16.bf16.f32 "         \
        "{%0,%1,%2,%3}, {%4,%5,%6,%7}, {%8,%9}, {%0,%1,%2,%3};\n"               \
        : "+f"((D)[0]), "+f"((D)[1]), "+f"((D)[2]), "+f"((D)[3])                \
        : "r"((A)[0]), "r"((A)[1]), "r"((A)[2]), "r"((A)[3]), "r"(B0), "r"(B1))

// SMEM per stage: Ah(10240) Al(10240) Bh(20480) Bl(20480) = 61440; 3 stages
#define ASTRIDE 40
#define STG_BYTES 61440
#define A_OFF(h) ((h) * 10240)
#define B_OFF(h) (20480 + (h) * 20480)
#define GEMM_SMEM (3 * STG_BYTES)

// ---------------- fp32 -> bf16 hi/lo ----------------
__global__ __launch_bounds__(256)
void convert_hl(const float* __restrict__ s, size_t n,
                __nv_bfloat16* __restrict__ h, __nv_bfloat16* __restrict__ l)
{
    size_t i = ((size_t)blockIdx.x * 256 + threadIdx.x) * 4;
    if (i >= n) return;
    float4 v = *reinterpret_cast<const float4*>(s + i);
    float vv[4] = {v.x, v.y, v.z, v.w};
    __nv_bfloat16 hb[4], lb[4];
#pragma unroll
    for (int q = 0; q < 4; q++) {
        hb[q] = __float2bfloat16_rn(vv[q]);
        lb[q] = __float2bfloat16_rn(vv[q] - __bfloat162float(hb[q]));
    }
    *reinterpret_cast<uint2*>(h + i) = *reinterpret_cast<uint2*>(hb);
    *reinterpret_cast<uint2*>(l + i) = *reinterpret_cast<uint2*>(lb);
}

// ---------------- transpose fp32 [R,C] -> bf16 hi/lo [C,R] ----------------
__global__ __launch_bounds__(256)
void transpose_hl(const float* __restrict__ src, int R, int C,
                  __nv_bfloat16* __restrict__ dh, __nv_bfloat16* __restrict__ dl)
{
    __shared__ float t[32][33];
    int tx = threadIdx.x, ty = threadIdx.y;
    int x = blockIdx.x * 32 + tx, y0 = blockIdx.y * 32;
#pragma unroll
    for (int j = 0; j < 32; j += 8)
        t[ty + j][tx] = src[(size_t)(y0 + ty + j) * C + x];
    __syncthreads();
    int x2 = y0 + tx, y2 = blockIdx.x * 32;
#pragma unroll
    for (int j = 0; j < 32; j += 8) {
        float v = t[tx][ty + j];
        __nv_bfloat16 h = __float2bfloat16_rn(v);
        dh[(size_t)(y2 + ty + j) * R + x2] = h;
        dl[(size_t)(y2 + ty + j) * R + x2] = __float2bfloat16_rn(v - __bfloat162float(h));
    }
}

// ---------------- Lb [16,N] -> [N,16] hi/lo ----------------
__global__ __launch_bounds__(256)
void lb_transpose(const float* __restrict__ Lb, int N,
                  __nv_bfloat16* __restrict__ dh, __nv_bfloat16* __restrict__ dl)
{
    int n = blockIdx.x * 256 + threadIdx.x;
    if (n >= N) return;
#pragma unroll
    for (int r = 0; r < RR; r++) {
        float v = Lb[(size_t)r * N + n];
        __nv_bfloat16 h = __float2bfloat16_rn(v);
        dh[(size_t)n * RR + r] = h;
        dl[(size_t)n * RR + r] = __float2bfloat16_rn(v - __bfloat162float(h));
    }
}

// ---------------- A [K,16] -> At [16,K] hi/lo ----------------
__global__ __launch_bounds__(256)
void at_transpose(const float* __restrict__ A, int K,
                  __nv_bfloat16* __restrict__ dh, __nv_bfloat16* __restrict__ dl)
{
    int k = blockIdx.x * 256 + threadIdx.x;
    if (k >= K) return;
#pragma unroll
    for (int r = 0; r < RR; r++) {
        float v = A[(size_t)k * RR + r];
        __nv_bfloat16 h = __float2bfloat16_rn(v);
        dh[(size_t)r * K + k] = h;
        dl[(size_t)r * K + k] = __float2bfloat16_rn(v - __bfloat162float(h));
    }
}

// ---------------- zero the three T accumulators ----------------
__global__ __launch_bounds__(256)
void zero_t(float* a, float* b, float* c)
{
    int i = blockIdx.x * 256 + threadIdx.x;
    if (i < MTOK * RR) { a[i] = 0.f; b[i] = 0.f; c[i] = 0.f; }
}

// ---------------- skinny HMMA GEMM: T[M,16] += Xh/l[M,K] @ At[16,K]^T ----------------
// grid (ksplit, M/128); 3-combo bf16 h/l; fp32 atomicAdd epilogue.
#define LXS 48
#define LSTG 14336
__global__ __launch_bounds__(256)
void lora_gemm(const __nv_bfloat16* __restrict__ Xh, const __nv_bfloat16* __restrict__ Xl,
               const __nv_bfloat16* __restrict__ Ath, const __nv_bfloat16* __restrict__ Atl,
               float* __restrict__ T, int K, int kslice)
{
    __shared__ __align__(128) char sm[3 * LSTG];
    const uint32_t sb = smem_u32(sm);
    const int tid = threadIdx.x, lane = tid & 31, w = tid >> 5;
    const int bm = blockIdx.y * 128;
    const int k0 = blockIdx.x * kslice;

    float acc[2][4];
#pragma unroll
    for (int a = 0; a < 2; a++)
#pragma unroll
        for (int b = 0; b < 4; b++) acc[a][b] = 0.f;

    auto load = [&](int st, int kk) {
        uint32_t s0 = sb + (uint32_t)st * LSTG;
#pragma unroll
        for (int j = 0; j < 2; j++) {           // X h/l: 128 rows x 32B
            int c = tid + j * 256;
            int row = c >> 2, pc = c & 1, limb = (c >> 1) & 1;
            const __nv_bfloat16* src = (limb ? Xl : Xh) + (size_t)(bm + row) * K + kk + pc * 8;
            CPA(s0 + (uint32_t)(limb * 6144 + row * LXS + pc * 16), src);
        }
        if (tid < 64) {                          // At h/l: 16 rows x 32B
            int row = tid >> 2, pc = tid & 1, limb = (tid >> 1) & 1;
            const __nv_bfloat16* src = (limb ? Atl : Ath) + (size_t)row * K + kk + pc * 8;
            CPA(s0 + (uint32_t)(12288 + limb * 768 + row * LXS + pc * 16), src);
        }
    };

    const int iters = kslice / 16;
    load(0, k0); CPC();
    load(1, k0 + 16); CPC();

    for (int it = 0; it < iters; it++) {
        if (it + 1 < iters) { CPW(1); } else { CPW(0); }
        __syncthreads();
        if (it + 2 < iters) { load((it + 2) % 3, k0 + (it + 2) * 16); CPC(); }
        uint32_t s0 = sb + (uint32_t)(it % 3) * LSTG;
        uint32_t ah[4], al[4], bh[4], bl[4];
        uint32_t xoff = (uint32_t)((w * 16 + (lane & 15)) * LXS + (lane >> 4) * 16);
        uint32_t boff = (uint32_t)(((lane & 15)) * LXS + (lane >> 4) * 16);
        LDSM4(ah, s0 + xoff);
        LDSM4(al, s0 + 6144 + xoff);
        LDSM4(bh, s0 + 12288 + boff);
        LDSM4(bl, s0 + 12288 + 768 + boff);
#pragma unroll
        for (int ni = 0; ni < 2; ni++) {
            MMA16816(acc[ni], ah, bh[ni], bh[ni + 2]);
            MMA16816(acc[ni], ah, bl[ni], bl[ni + 2]);
            MMA16816(acc[ni], al, bh[ni], bh[ni + 2]);
        }
    }

#pragma unroll
    for (int ni = 0; ni < 2; ni++)
#pragma unroll
        for (int h2 = 0; h2 < 2; h2++) {
            int row = bm + w * 16 + (lane >> 2) + h2 * 8;
            int col = ni * 8 + (lane & 3) * 2;
            atomicAdd(&T[(size_t)row * RR + col],     acc[ni][h2 * 2 + 0]);
            atomicAdd(&T[(size_t)row * RR + col + 1], acc[ni][h2 * 2 + 1]);
        }
}

// ---------------- unified HMMA GEMM (verbatim R6) ----------------
template <int MODE>
__global__ __launch_bounds__(256, 1)
void gemm_mma(const __nv_bfloat16* __restrict__ Ah, const __nv_bfloat16* __restrict__ Al,
              const __nv_bfloat16* __restrict__ B0h, const __nv_bfloat16* __restrict__ B0l,
              const __nv_bfloat16* __restrict__ B1h, const __nv_bfloat16* __restrict__ B1l,
              const __nv_bfloat16* __restrict__ T0h, const __nv_bfloat16* __restrict__ T0l,
              const __nv_bfloat16* __restrict__ T1h, const __nv_bfloat16* __restrict__ T1l,
              const __nv_bfloat16* __restrict__ L0h, const __nv_bfloat16* __restrict__ L0l,
              const __nv_bfloat16* __restrict__ L1h, const __nv_bfloat16* __restrict__ L1l,
              const float* __restrict__ bias0, const float* __restrict__ bias1,
              float* __restrict__ Cf,
              __nv_bfloat16* __restrict__ Xh, __nv_bfloat16* __restrict__ Xl,
              int N, int K)
{
    extern __shared__ char dsm[];
    const uint32_t sb = smem_u32(dsm);
    const int tid = threadIdx.x, lane = tid & 31, wid = tid >> 5;
    const int wm = wid >> 2, wn = wid & 3;
    const int bm = blockIdx.y * 128;
    const int bn = blockIdx.x * (MODE == 0 ? 256 : 128);

    float acc[2][4][4][4];
#pragma unroll
    for (int o = 0; o < 2; o++)
#pragma unroll
        for (int a = 0; a < 4; a++)
#pragma unroll
            for (int b = 0; b < 4; b++)
#pragma unroll
                for (int c = 0; c < 4; c++) acc[o][a][b][c] = 0.f;

    auto load_stage = [&](int st, int k0) {
        uint32_t s0 = sb + (uint32_t)st * STG_BYTES;
#pragma unroll
        for (int j = 0; j < 2; j++) {
            int c = tid + j * 256;
            int row = c >> 2, cg = (c & 3) * 8;
            uint32_t d = (uint32_t)(row * ASTRIDE + cg) * 2;
            CPA(s0 + A_OFF(0) + d, Ah + (size_t)(bm + row) * K + k0 + cg);
            CPA(s0 + A_OFF(1) + d, Al + (size_t)(bm + row) * K + k0 + cg);
        }
#pragma unroll
        for (int j = 0; j < 4; j++) {
            int c = tid + j * 256;
            int row = c >> 2, cg = (c & 3) * 8;
            int rr = (MODE == 0) ? row : (row & 127);
            const __nv_bfloat16* ph = (row < 128) ? B0h : B1h;
            const __nv_bfloat16* pl = (row < 128) ? B0l : B1l;
            uint32_t d = (uint32_t)(row * ASTRIDE + cg) * 2;
            CPA(s0 + B_OFF(0) + d, ph + (size_t)(bn + rr) * K + k0 + cg);
            CPA(s0 + B_OFF(1) + d, pl + (size_t)(bn + rr) * K + k0 + cg);
        }
    };

    const int ar = lane & 15;
    const int koff = (lane >> 4) * 8;

    auto compute_ks = [&](uint32_t s0, int kbase) {
        const int kc = kbase + koff;
        uint32_t ah[4][4], al[4][4], b0[2][4], b1[2][4];
#pragma unroll
        for (int mi = 0; mi < 4; mi++)
            LDSM4(ah[mi], s0 + A_OFF(0) + (uint32_t)((wm * 64 + mi * 16 + ar) * ASTRIDE + kc) * 2);
#pragma unroll
        for (int nb = 0; nb < 2; nb++) {
            LDSM4(b0[nb], s0 + B_OFF(0) + (uint32_t)((wn * 32 + nb * 16 + ar) * ASTRIDE + kc) * 2);
            LDSM4(b1[nb], s0 + B_OFF(0) + (uint32_t)((128 + wn * 32 + nb * 16 + ar) * ASTRIDE + kc) * 2);
        }
#pragma unroll
        for (int mi = 0; mi < 4; mi++)
#pragma unroll
            for (int ni = 0; ni < 4; ni++) {
                MMA16816(acc[0][mi][ni], ah[mi], b0[ni >> 1][ni & 1], b0[ni >> 1][(ni & 1) + 2]);
                MMA16816(acc[1][mi][ni], ah[mi], b1[ni >> 1][ni & 1], b1[ni >> 1][(ni & 1) + 2]);
            }
#pragma unroll
        for (int mi = 0; mi < 4; mi++)
            LDSM4(al[mi], s0 + A_OFF(1) + (uint32_t)((wm * 64 + mi * 16 + ar) * ASTRIDE + kc) * 2);
#pragma unroll
        for (int mi = 0; mi < 4; mi++)
#pragma unroll
            for (int ni = 0; ni < 4; ni++) {
                MMA16816(acc[0][mi][ni], al[mi], b0[ni >> 1][ni & 1], b0[ni >> 1][(ni & 1) + 2]);
                MMA16816(acc[1][mi][ni], al[mi], b1[ni >> 1][ni & 1], b1[ni >> 1][(ni & 1) + 2]);
            }
#pragma unroll
        for (int nb = 0; nb < 2; nb++) {
            LDSM4(b0[nb], s0 + B_OFF(1) + (uint32_t)((wn * 32 + nb * 16 + ar) * ASTRIDE + kc) * 2);
            LDSM4(b1[nb], s0 + B_OFF(1) + (uint32_t)((128 + wn * 32 + nb * 16 + ar) * ASTRIDE + kc) * 2);
        }
#pragma unroll
        for (int mi = 0; mi < 4; mi++)
#pragma unroll
            for (int ni = 0; ni < 4; ni++) {
                MMA16816(acc[0][mi][ni], ah[mi], b0[ni >> 1][ni & 1], b0[ni >> 1][(ni & 1) + 2]);
                MMA16816(acc[1][mi][ni], ah[mi], b1[ni >> 1][ni & 1], b1[ni >> 1][(ni & 1) + 2]);
            }
    };

    const int KC = K / 32;
    load_stage(0, 0); CPC();
    load_stage(1, 32); CPC();

    for (int c = 0; c < KC; c++) {
        if (c + 1 < KC) { CPW(1); } else { CPW(0); }
        __syncthreads();
        if (c + 2 < KC) { load_stage((c + 2) % 3, (c + 2) * 32); CPC(); }
        uint32_t s0 = sb + (uint32_t)(c % 3) * STG_BYTES;
        compute_ks(s0, 0);
        compute_ks(s0, 16);
    }

    // ---- LoRA k16 chunk: T0 in stage0 A region, T1 in stage1 A region ----
    __syncthreads();
    {
        int row = tid >> 1, cg = (tid & 1) * 8;
        uint32_t d = (uint32_t)(row * ASTRIDE + cg) * 2;
        *(uint4*)(dsm + A_OFF(0) + d) = *(const uint4*)(T0h + (size_t)(bm + row) * RR + cg);
        *(uint4*)(dsm + A_OFF(1) + d) = *(const uint4*)(T0l + (size_t)(bm + row) * RR + cg);
        *(uint4*)(dsm + STG_BYTES + A_OFF(0) + d) = *(const uint4*)(T1h + (size_t)(bm + row) * RR + cg);
        *(uint4*)(dsm + STG_BYTES + A_OFF(1) + d) = *(const uint4*)(T1l + (size_t)(bm + row) * RR + cg);
#pragma unroll
        for (int j = 0; j < 2; j++) {
            int c = tid + j * 256;
            int brow = c >> 1, bcg = (c & 1) * 8;
            int rr = (MODE == 0) ? brow : (brow & 127);
            const __nv_bfloat16* ph = (brow < 128) ? L0h : L1h;
            const __nv_bfloat16* pl = (brow < 128) ? L0l : L1l;
            uint32_t bd = (uint32_t)(brow * ASTRIDE + bcg) * 2;
            *(uint4*)(dsm + B_OFF(0) + bd) = *(const uint4*)(ph + (size_t)(bn + rr) * RR + bcg);
            *(uint4*)(dsm + B_OFF(1) + bd) = *(const uint4*)(pl + (size_t)(bn + rr) * RR + bcg);
        }
        __syncthreads();
#pragma unroll
        for (int o = 0; o < 2; o++) {
            uint32_t sA = sb + (uint32_t)o * STG_BYTES;
            uint32_t ah[4][4], al[4][4], bb[2][4];
#pragma unroll
            for (int mi = 0; mi < 4; mi++) {
                LDSM4(ah[mi], sA + A_OFF(0) + (uint32_t)((wm * 64 + mi * 16 + ar) * ASTRIDE + koff) * 2);
                LDSM4(al[mi], sA + A_OFF(1) + (uint32_t)((wm * 64 + mi * 16 + ar) * ASTRIDE + koff) * 2);
            }
#pragma unroll
            for (int nb = 0; nb < 2; nb++)
                LDSM4(bb[nb], sb + B_OFF(0) + (uint32_t)((o * 128 + wn * 32 + nb * 16 + ar) * ASTRIDE + koff) * 2);
#pragma unroll
            for (int mi = 0; mi < 4; mi++)
#pragma unroll
                for (int ni = 0; ni < 4; ni++) {
                    MMA16816(acc[o][mi][ni], ah[mi], bb[ni >> 1][ni & 1], bb[ni >> 1][(ni & 1) + 2]);
                    MMA16816(acc[o][mi][ni], al[mi], bb[ni >> 1][ni & 1], bb[ni >> 1][(ni & 1) + 2]);
                }
#pragma unroll
            for (int nb = 0; nb < 2; nb++)
                LDSM4(bb[nb], sb + B_OFF(1) + (uint32_t)((o * 128 + wn * 32 + nb * 16 + ar) * ASTRIDE + koff) * 2);
#pragma unroll
            for (int mi = 0; mi < 4; mi++)
#pragma unroll
                for (int ni = 0; ni < 4; ni++)
                    MMA16816(acc[o][mi][ni], ah[mi], bb[ni >> 1][ni & 1], bb[ni >> 1][(ni & 1) + 2]);
        }
    }

    // ---- epilogue ----
#pragma unroll
    for (int mi = 0; mi < 4; mi++) {
        int r0 = bm + wm * 64 + mi * 16 + (lane >> 2);
#pragma unroll
        for (int ni = 0; ni < 4; ni++) {
            int cl = wn * 32 + ni * 8 + (lane & 3) * 2;
            if (MODE == 1) {
                float bg0 = bias0[bn + cl], bg1 = bias0[bn + cl + 1];
                float bu0 = bias1[bn + cl], bu1 = bias1[bn + cl + 1];
#pragma unroll
                for (int h2 = 0; h2 < 2; h2++) {
                    int r = r0 + h2 * 8;
                    float g0 = acc[0][mi][ni][h2 * 2 + 0] + bg0;
                    float g1 = acc[0][mi][ni][h2 * 2 + 1] + bg1;
                    float u0 = acc[1][mi][ni][h2 * 2 + 0] + bu0;
                    float u1 = acc[1][mi][ni][h2 * 2 + 1] + bu1;
                    float v0 = fmaxf(g0, 0.f) * u0;
                    float v1 = fmaxf(g1, 0.f) * u1;
                    __nv_bfloat16 h0 = __float2bfloat16_rn(v0);
                    __nv_bfloat16 h1 = __float2bfloat16_rn(v1);
                    __nv_bfloat16 l0 = __float2bfloat16_rn(v0 - __bfloat162float(h0));
                    __nv_bfloat16 l1 = __float2bfloat16_rn(v1 - __bfloat162float(h1));
                    size_t off = (size_t)r * N + bn + cl;
                    *(__nv_bfloat162*)(Xh + off) = __halves2bfloat162(h0, h1);
                    *(__nv_bfloat162*)(Xl + off) = __halves2bfloat162(l0, l1);
                }
            } else {
#pragma unroll
                for (int o = 0; o < 2; o++) {
                    int col = bn + o * 128 + cl;
                    float b0 = bias0[col], b1 = bias0[col + 1];
#pragma unroll
                    for (int h2 = 0; h2 < 2; h2++) {
                        int r = r0 + h2 * 8;
                        size_t off = (size_t)r * N + col;
                        *(float2*)(Cf + off) = make_float2(
                            acc[o][mi][ni][h2 * 2 + 0] + b0,
                            acc[o][mi][ni][h2 * 2 + 1] + b1);
                    }
                }
            }
        }
    }
}

// ---------------- launcher ----------------
extern "C" void kernel_launch(void* const* d_in, const int* in_sizes, int n_in,
                              void* d_out, int out_size)
{
    const float* x1     = (const float*)d_in[0];
    const float* w_gate = (const float*)d_in[1];
    const float* b_gate = (const float*)d_in[2];
    const float* wga    = (const float*)d_in[3];
    const float* wgb    = (const float*)d_in[4];
    const float* w_up   = (const float*)d_in[5];
    const float* b_up   = (const float*)d_in[6];
    const float* wua    = (const float*)d_in[7];
    const float* wub    = (const float*)d_in[8];
    const float* w_down = (const float*)d_in[9];
    const float* b_down = (const float*)d_in[10];
    const float* wda    = (const float*)d_in[11];
    const float* wdb    = (const float*)d_in[12];
    float* out = (float*)d_out;

#define SYM(p, s) void* p; cudaGetSymbolAddress(&p, s)
    SYM(x1h, g_x1h); SYM(x1l, g_x1l); SYM(x3h, g_x3h); SYM(x3l, g_x3l);
    SYM(wgh, g_wgh); SYM(wgl, g_wgl); SYM(wuh, g_wuh); SYM(wul, g_wul);
    SYM(wdh, g_wdh); SYM(wdl, g_wdl);
    SYM(lgh, g_lgh); SYM(lgl, g_lgl); SYM(luh, g_luh); SYM(lul, g_lul);
    SYM(ldh, g_ldh); SYM(ldl, g_ldl);
    SYM(tgh, g_tgh); SYM(tgl, g_tgl); SYM(tuh, g_tuh); SYM(tul, g_tul);
    SYM(tdh, g_tdh); SYM(tdl, g_tdl);
    SYM(gaTh, g_gaTh); SYM(gaTl, g_gaTl); SYM(uaTh, g_uaTh); SYM(uaTl, g_uaTl);
    SYM(daTh, g_daTh); SYM(daTl, g_daTl);
    SYM(Tgf, g_Tgf); SYM(Tuf, g_Tuf); SYM(Tdf, g_Tdf);
#undef SYM
#define BF(p) ((__nv_bfloat16*)(p))
#define F32(p) ((float*)(p))

    cudaFuncSetAttribute(gemm_mma<0>, cudaFuncAttributeMaxDynamicSharedMemorySize, GEMM_SMEM);
    cudaFuncSetAttribute(gemm_mma<1>, cudaFuncAttributeMaxDynamicSharedMemorySize, GEMM_SMEM);

    // conversions / transposes
    convert_hl<<<(int)((size_t)MTOK * DDIM / 1024), 256>>>(x1, (size_t)MTOK * DDIM, BF(x1h), BF(x1l));
    transpose_hl<<<dim3(FDIM / 32, DDIM / 32), dim3(32, 8)>>>(w_gate, DDIM, FDIM, BF(wgh), BF(wgl));
    transpose_hl<<<dim3(FDIM / 32, DDIM / 32), dim3(32, 8)>>>(w_up,   DDIM, FDIM, BF(wuh), BF(wul));
    transpose_hl<<<dim3(DDIM / 32, FDIM / 32), dim3(32, 8)>>>(w_down, FDIM, DDIM, BF(wdh), BF(wdl));
    lb_transpose<<<FDIM / 256, 256>>>(wgb, FDIM, BF(lgh), BF(lgl));
    lb_transpose<<<FDIM / 256, 256>>>(wub, FDIM, BF(luh), BF(lul));
    lb_transpose<<<DDIM / 256, 256>>>(wdb, DDIM, BF(ldh), BF(ldl));
    at_transpose<<<DDIM / 256, 256>>>(wga, DDIM, BF(gaTh), BF(gaTl));
    at_transpose<<<DDIM / 256, 256>>>(wua, DDIM, BF(uaTh), BF(uaTl));
    at_transpose<<<FDIM / 256, 256>>>(wda, FDIM, BF(daTh), BF(daTl));
    zero_t<<<(MTOK * RR) / 256, 256>>>(F32(Tgf), F32(Tuf), F32(Tdf));

    // LoRA-A gate + up via skinny tensor GEMM (K=2048, ksplit=2)
    lora_gemm<<<dim3(2, MTOK / 128), 256>>>(BF(x1h), BF(x1l), BF(gaTh), BF(gaTl),
                                            F32(Tgf), DDIM, DDIM / 2);
    lora_gemm<<<dim3(2, MTOK / 128), 256>>>(BF(x1h), BF(x1l), BF(uaTh), BF(uaTl),
                                            F32(Tuf), DDIM, DDIM / 2);
    convert_hl<<<(MTOK * RR) / 1024, 256>>>(F32(Tgf), MTOK * RR, BF(tgh), BF(tgl));
    convert_hl<<<(MTOK * RR) / 1024, 256>>>(F32(Tuf), MTOK * RR, BF(tuh), BF(tul));

    // fused gate+up -> x3 bf16 hi/lo
    gemm_mma<1><<<dim3(FDIM / 128, MTOK / 128), 256, GEMM_SMEM>>>(
        BF(x1h), BF(x1l),
        BF(wgh), BF(wgl), BF(wuh), BF(wul),
        BF(tgh), BF(tgl), BF(tuh), BF(tul),
        BF(lgh), BF(lgl), BF(luh), BF(lul),
        b_gate, b_up,
        nullptr, BF(x3h), BF(x3l), FDIM, DDIM);

    // LoRA-A down via skinny tensor GEMM (K=8192, ksplit=4)
    lora_gemm<<<dim3(4, MTOK / 128), 256>>>(BF(x3h), BF(x3l), BF(daTh), BF(daTl),
                                            F32(Tdf), FDIM, FDIM / 4);
    convert_hl<<<(MTOK * RR) / 1024, 256>>>(F32(Tdf), MTOK * RR, BF(tdh), BF(tdl));

    // down GEMM -> out (fp32)
    gemm_mma<0><<<dim3(DDIM / 256, MTOK / 128), 256, GEMM_SMEM>>>(
        BF(x3h), BF(x3l),
        BF(wdh), BF(wdl), BF(wdh), BF(wdl),
        BF(tdh), BF(tdl), BF(tdh), BF(tdl),
        BF(ldh), BF(ldl), BF(ldh), BF(ldl),
        b_down, nullptr,
        out, nullptr, nullptr, DDIM, FDIM);
}

// round 10
// speedup vs baseline: 2.2402x; 1.0003x over previous
#include <cuda_runtime.h>
#include <cuda_bf16.h>
#include <cstdint>

#define MTOK 8192
#define DDIM 2048
#define FDIM 8192
#define RR   16

// ---------------- device scratch (allocation-free) ----------------
__device__ __align__(1024) __nv_bfloat16 g_x1h[(size_t)MTOK * DDIM];
__device__ __align__(1024) __nv_bfloat16 g_x1l[(size_t)MTOK * DDIM];
__device__ __align__(1024) __nv_bfloat16 g_x3h[(size_t)MTOK * FDIM];
__device__ __align__(1024) __nv_bfloat16 g_x3l[(size_t)MTOK * FDIM];
__device__ __align__(1024) __nv_bfloat16 g_wgh[(size_t)FDIM * DDIM];
__device__ __align__(1024) __nv_bfloat16 g_wgl[(size_t)FDIM * DDIM];
__device__ __align__(1024) __nv_bfloat16 g_wuh[(size_t)FDIM * DDIM];
__device__ __align__(1024) __nv_bfloat16 g_wul[(size_t)FDIM * DDIM];
__device__ __align__(1024) __nv_bfloat16 g_wdh[(size_t)DDIM * FDIM];
__device__ __align__(1024) __nv_bfloat16 g_wdl[(size_t)DDIM * FDIM];
__device__ __align__(1024) __nv_bfloat16 g_lgh[FDIM * RR], g_lgl[FDIM * RR];
__device__ __align__(1024) __nv_bfloat16 g_luh[FDIM * RR], g_lul[FDIM * RR];
__device__ __align__(1024) __nv_bfloat16 g_ldh[DDIM * RR], g_ldl[DDIM * RR];
__device__ __align__(1024) __nv_bfloat16 g_tgh[MTOK * RR], g_tgl[MTOK * RR];
__device__ __align__(1024) __nv_bfloat16 g_tuh[MTOK * RR], g_tul[MTOK * RR];
__device__ __align__(1024) __nv_bfloat16 g_tdh[MTOK * RR], g_tdl[MTOK * RR];
// LoRA-A transposed [16,K] h/l + fp32 T accumulators
__device__ __align__(1024) __nv_bfloat16 g_gaTh[RR * DDIM], g_gaTl[RR * DDIM];
__device__ __align__(1024) __nv_bfloat16 g_uaTh[RR * DDIM], g_uaTl[RR * DDIM];
__device__ __align__(1024) __nv_bfloat16 g_daTh[RR * FDIM], g_daTl[RR * FDIM];
__device__ __align__(1024) float g_Tgf[MTOK * RR], g_Tuf[MTOK * RR], g_Tdf[MTOK * RR];

// ---------------- PTX helpers ----------------
__device__ __forceinline__ uint32_t smem_u32(const void* p) {
    uint32_t a;
    asm("{ .reg .u64 t; cvta.to.shared.u64 t, %1; cvt.u32.u64 %0, t; }" : "=r"(a) : "l"(p));
    return a;
}
#define CPA(dst, src) \
    asm volatile("cp.async.cg.shared.global [%0], [%1], 16;\n" :: "r"(dst), "l"(src))
#define CPC() asm volatile("cp.async.commit_group;\n" ::: "memory")
#define CPW(n) asm volatile("cp.async.wait_group %0;\n" :: "n"(n) : "memory")
#define LDSM4(R, addr)                                                          \
    asm volatile("ldmatrix.sync.aligned.m8n8.x4.shared.b16 {%0,%1,%2,%3}, [%4];\n" \
        : "=r"((R)[0]), "=r"((R)[1]), "=r"((R)[2]), "=r"((R)[3]) : "r"(addr))
#define MMA16816(D, A, B0, B1)                                                  \
    asm volatile("mma.sync.aligned.m16n8k16.row.col.f32.bf16.bf16.f32 "         \
        "{%0,%1,%2,%3}, {%4,%5,%6,%7}, {%8,%9}, {%0,%1,%2,%3};\n"               \
        : "+f"((D)[0]), "+f"((D)[1]), "+f"((D)[2]), "+f"((D)[3])                \
        : "r"((A)[0]), "r"((A)[1]), "r"((A)[2]), "r"((A)[3]), "r"(B0), "r"(B1))

// SMEM per stage: Ah(10240) Al(10240) Bh(20480) Bl(20480) = 61440; 3 stages
#define ASTRIDE 40
#define STG_BYTES 61440
#define A_OFF(h) ((h) * 10240)
#define B_OFF(h) (20480 + (h) * 20480)
#define GEMM_SMEM (3 * STG_BYTES)

// ---------------- fp32 -> bf16 hi/lo ----------------
__global__ __launch_bounds__(256)
void convert_hl(const float* __restrict__ s, size_t n,
                __nv_bfloat16* __restrict__ h, __nv_bfloat16* __restrict__ l)
{
    size_t i = ((size_t)blockIdx.x * 256 + threadIdx.x) * 4;
    if (i >= n) return;
    float4 v = *reinterpret_cast<const float4*>(s + i);
    float vv[4] = {v.x, v.y, v.z, v.w};
    __nv_bfloat16 hb[4], lb[4];
#pragma unroll
    for (int q = 0; q < 4; q++) {
        hb[q] = __float2bfloat16_rn(vv[q]);
        lb[q] = __float2bfloat16_rn(vv[q] - __bfloat162float(hb[q]));
    }
    *reinterpret_cast<uint2*>(h + i) = *reinterpret_cast<uint2*>(hb);
    *reinterpret_cast<uint2*>(l + i) = *reinterpret_cast<uint2*>(lb);
}

// ---------------- transpose fp32 [R,C] -> bf16 hi/lo [C,R] ----------------
__global__ __launch_bounds__(256)
void transpose_hl(const float* __restrict__ src, int R, int C,
                  __nv_bfloat16* __restrict__ dh, __nv_bfloat16* __restrict__ dl)
{
    __shared__ float t[32][33];
    int tx = threadIdx.x, ty = threadIdx.y;
    int x = blockIdx.x * 32 + tx, y0 = blockIdx.y * 32;
#pragma unroll
    for (int j = 0; j < 32; j += 8)
        t[ty + j][tx] = src[(size_t)(y0 + ty + j) * C + x];
    __syncthreads();
    int x2 = y0 + tx, y2 = blockIdx.x * 32;
#pragma unroll
    for (int j = 0; j < 32; j += 8) {
        float v = t[tx][ty + j];
        __nv_bfloat16 h = __float2bfloat16_rn(v);
        dh[(size_t)(y2 + ty + j) * R + x2] = h;
        dl[(size_t)(y2 + ty + j) * R + x2] = __float2bfloat16_rn(v - __bfloat162float(h));
    }
}

// ---------------- Lb [16,N] -> [N,16] hi/lo ----------------
__global__ __launch_bounds__(256)
void lb_transpose(const float* __restrict__ Lb, int N,
                  __nv_bfloat16* __restrict__ dh, __nv_bfloat16* __restrict__ dl)
{
    int n = blockIdx.x * 256 + threadIdx.x;
    if (n >= N) return;
#pragma unroll
    for (int r = 0; r < RR; r++) {
        float v = Lb[(size_t)r * N + n];
        __nv_bfloat16 h = __float2bfloat16_rn(v);
        dh[(size_t)n * RR + r] = h;
        dl[(size_t)n * RR + r] = __float2bfloat16_rn(v - __bfloat162float(h));
    }
}

// ---------------- A [K,16] -> At [16,K] hi/lo ----------------
__global__ __launch_bounds__(256)
void at_transpose(const float* __restrict__ A, int K,
                  __nv_bfloat16* __restrict__ dh, __nv_bfloat16* __restrict__ dl)
{
    int k = blockIdx.x * 256 + threadIdx.x;
    if (k >= K) return;
#pragma unroll
    for (int r = 0; r < RR; r++) {
        float v = A[(size_t)k * RR + r];
        __nv_bfloat16 h = __float2bfloat16_rn(v);
        dh[(size_t)r * K + k] = h;
        dl[(size_t)r * K + k] = __float2bfloat16_rn(v - __bfloat162float(h));
    }
}

// ---------------- zero the three T accumulators ----------------
__global__ __launch_bounds__(256)
void zero_t(float* a, float* b, float* c)
{
    int i = blockIdx.x * 256 + threadIdx.x;
    if (i < MTOK * RR) { a[i] = 0.f; b[i] = 0.f; c[i] = 0.f; }
}

// ---------------- skinny HMMA GEMM: T[M,16] += Xh/l[M,K] @ At[16,K]^T ----------------
// grid (ksplit, M/128); 3-combo bf16 h/l; fp32 atomicAdd epilogue.
#define LXS 48
#define LSTG 14336
__global__ __launch_bounds__(256)
void lora_gemm(const __nv_bfloat16* __restrict__ Xh, const __nv_bfloat16* __restrict__ Xl,
               const __nv_bfloat16* __restrict__ Ath, const __nv_bfloat16* __restrict__ Atl,
               float* __restrict__ T, int K, int kslice)
{
    __shared__ __align__(128) char sm[3 * LSTG];
    const uint32_t sb = smem_u32(sm);
    const int tid = threadIdx.x, lane = tid & 31, w = tid >> 5;
    const int bm = blockIdx.y * 128;
    const int k0 = blockIdx.x * kslice;

    float acc[2][4];
#pragma unroll
    for (int a = 0; a < 2; a++)
#pragma unroll
        for (int b = 0; b < 4; b++) acc[a][b] = 0.f;

    auto load = [&](int st, int kk) {
        uint32_t s0 = sb + (uint32_t)st * LSTG;
#pragma unroll
        for (int j = 0; j < 2; j++) {           // X h/l: 128 rows x 32B
            int c = tid + j * 256;
            int row = c >> 2, pc = c & 1, limb = (c >> 1) & 1;
            const __nv_bfloat16* src = (limb ? Xl : Xh) + (size_t)(bm + row) * K + kk + pc * 8;
            CPA(s0 + (uint32_t)(limb * 6144 + row * LXS + pc * 16), src);
        }
        if (tid < 64) {                          // At h/l: 16 rows x 32B
            int row = tid >> 2, pc = tid & 1, limb = (tid >> 1) & 1;
            const __nv_bfloat16* src = (limb ? Atl : Ath) + (size_t)row * K + kk + pc * 8;
            CPA(s0 + (uint32_t)(12288 + limb * 768 + row * LXS + pc * 16), src);
        }
    };

    const int iters = kslice / 16;
    load(0, k0); CPC();
    load(1, k0 + 16); CPC();

    for (int it = 0; it < iters; it++) {
        if (it + 1 < iters) { CPW(1); } else { CPW(0); }
        __syncthreads();
        if (it + 2 < iters) { load((it + 2) % 3, k0 + (it + 2) * 16); CPC(); }
        uint32_t s0 = sb + (uint32_t)(it % 3) * LSTG;
        uint32_t ah[4], al[4], bh[4], bl[4];
        uint32_t xoff = (uint32_t)((w * 16 + (lane & 15)) * LXS + (lane >> 4) * 16);
        uint32_t boff = (uint32_t)(((lane & 15)) * LXS + (lane >> 4) * 16);
        LDSM4(ah, s0 + xoff);
        LDSM4(al, s0 + 6144 + xoff);
        LDSM4(bh, s0 + 12288 + boff);
        LDSM4(bl, s0 + 12288 + 768 + boff);
#pragma unroll
        for (int ni = 0; ni < 2; ni++) {
            MMA16816(acc[ni], ah, bh[ni], bh[ni + 2]);
            MMA16816(acc[ni], ah, bl[ni], bl[ni + 2]);
            MMA16816(acc[ni], al, bh[ni], bh[ni + 2]);
        }
    }

#pragma unroll
    for (int ni = 0; ni < 2; ni++)
#pragma unroll
        for (int h2 = 0; h2 < 2; h2++) {
            int row = bm + w * 16 + (lane >> 2) + h2 * 8;
            int col = ni * 8 + (lane & 3) * 2;
            atomicAdd(&T[(size_t)row * RR + col],     acc[ni][h2 * 2 + 0]);
            atomicAdd(&T[(size_t)row * RR + col + 1], acc[ni][h2 * 2 + 1]);
        }
}

// ---------------- unified HMMA GEMM (verbatim R6) ----------------
template <int MODE>
__global__ __launch_bounds__(256, 1)
void gemm_mma(const __nv_bfloat16* __restrict__ Ah, const __nv_bfloat16* __restrict__ Al,
              const __nv_bfloat16* __restrict__ B0h, const __nv_bfloat16* __restrict__ B0l,
              const __nv_bfloat16* __restrict__ B1h, const __nv_bfloat16* __restrict__ B1l,
              const __nv_bfloat16* __restrict__ T0h, const __nv_bfloat16* __restrict__ T0l,
              const __nv_bfloat16* __restrict__ T1h, const __nv_bfloat16* __restrict__ T1l,
              const __nv_bfloat16* __restrict__ L0h, const __nv_bfloat16* __restrict__ L0l,
              const __nv_bfloat16* __restrict__ L1h, const __nv_bfloat16* __restrict__ L1l,
              const float* __restrict__ bias0, const float* __restrict__ bias1,
              float* __restrict__ Cf,
              __nv_bfloat16* __restrict__ Xh, __nv_bfloat16* __restrict__ Xl,
              int N, int K)
{
    extern __shared__ char dsm[];
    const uint32_t sb = smem_u32(dsm);
    const int tid = threadIdx.x, lane = tid & 31, wid = tid >> 5;
    const int wm = wid >> 2, wn = wid & 3;
    const int bm = blockIdx.y * 128;
    const int bn = blockIdx.x * (MODE == 0 ? 256 : 128);

    float acc[2][4][4][4];
#pragma unroll
    for (int o = 0; o < 2; o++)
#pragma unroll
        for (int a = 0; a < 4; a++)
#pragma unroll
            for (int b = 0; b < 4; b++)
#pragma unroll
                for (int c = 0; c < 4; c++) acc[o][a][b][c] = 0.f;

    auto load_stage = [&](int st, int k0) {
        uint32_t s0 = sb + (uint32_t)st * STG_BYTES;
#pragma unroll
        for (int j = 0; j < 2; j++) {
            int c = tid + j * 256;
            int row = c >> 2, cg = (c & 3) * 8;
            uint32_t d = (uint32_t)(row * ASTRIDE + cg) * 2;
            CPA(s0 + A_OFF(0) + d, Ah + (size_t)(bm + row) * K + k0 + cg);
            CPA(s0 + A_OFF(1) + d, Al + (size_t)(bm + row) * K + k0 + cg);
        }
#pragma unroll
        for (int j = 0; j < 4; j++) {
            int c = tid + j * 256;
            int row = c >> 2, cg = (c & 3) * 8;
            int rr = (MODE == 0) ? row : (row & 127);
            const __nv_bfloat16* ph = (row < 128) ? B0h : B1h;
            const __nv_bfloat16* pl = (row < 128) ? B0l : B1l;
            uint32_t d = (uint32_t)(row * ASTRIDE + cg) * 2;
            CPA(s0 + B_OFF(0) + d, ph + (size_t)(bn + rr) * K + k0 + cg);
            CPA(s0 + B_OFF(1) + d, pl + (size_t)(bn + rr) * K + k0 + cg);
        }
    };

    const int ar = lane & 15;
    const int koff = (lane >> 4) * 8;

    auto compute_ks = [&](uint32_t s0, int kbase) {
        const int kc = kbase + koff;
        uint32_t ah[4][4], al[4][4], b0[2][4], b1[2][4];
#pragma unroll
        for (int mi = 0; mi < 4; mi++)
            LDSM4(ah[mi], s0 + A_OFF(0) + (uint32_t)((wm * 64 + mi * 16 + ar) * ASTRIDE + kc) * 2);
#pragma unroll
        for (int nb = 0; nb < 2; nb++) {
            LDSM4(b0[nb], s0 + B_OFF(0) + (uint32_t)((wn * 32 + nb * 16 + ar) * ASTRIDE + kc) * 2);
            LDSM4(b1[nb], s0 + B_OFF(0) + (uint32_t)((128 + wn * 32 + nb * 16 + ar) * ASTRIDE + kc) * 2);
        }
#pragma unroll
        for (int mi = 0; mi < 4; mi++)
#pragma unroll
            for (int ni = 0; ni < 4; ni++) {
                MMA16816(acc[0][mi][ni], ah[mi], b0[ni >> 1][ni & 1], b0[ni >> 1][(ni & 1) + 2]);
                MMA16816(acc[1][mi][ni], ah[mi], b1[ni >> 1][ni & 1], b1[ni >> 1][(ni & 1) + 2]);
            }
#pragma unroll
        for (int mi = 0; mi < 4; mi++)
            LDSM4(al[mi], s0 + A_OFF(1) + (uint32_t)((wm * 64 + mi * 16 + ar) * ASTRIDE + kc) * 2);
#pragma unroll
        for (int mi = 0; mi < 4; mi++)
#pragma unroll
            for (int ni = 0; ni < 4; ni++) {
                MMA16816(acc[0][mi][ni], al[mi], b0[ni >> 1][ni & 1], b0[ni >> 1][(ni & 1) + 2]);
                MMA16816(acc[1][mi][ni], al[mi], b1[ni >> 1][ni & 1], b1[ni >> 1][(ni & 1) + 2]);
            }
#pragma unroll
        for (int nb = 0; nb < 2; nb++) {
            LDSM4(b0[nb], s0 + B_OFF(1) + (uint32_t)((wn * 32 + nb * 16 + ar) * ASTRIDE + kc) * 2);
            LDSM4(b1[nb], s0 + B_OFF(1) + (uint32_t)((128 + wn * 32 + nb * 16 + ar) * ASTRIDE + kc) * 2);
        }
#pragma unroll
        for (int mi = 0; mi < 4; mi++)
#pragma unroll
            for (int ni = 0; ni < 4; ni++) {
                MMA16816(acc[0][mi][ni], ah[mi], b0[ni >> 1][ni & 1], b0[ni >> 1][(ni & 1) + 2]);
                MMA16816(acc[1][mi][ni], ah[mi], b1[ni >> 1][ni & 1], b1[ni >> 1][(ni & 1) + 2]);
            }
    };

    const int KC = K / 32;
    load_stage(0, 0); CPC();
    load_stage(1, 32); CPC();

    for (int c = 0; c < KC; c++) {
        if (c + 1 < KC) { CPW(1); } else { CPW(0); }
        __syncthreads();
        if (c + 2 < KC) { load_stage((c + 2) % 3, (c + 2) * 32); CPC(); }
        uint32_t s0 = sb + (uint32_t)(c % 3) * STG_BYTES;
        compute_ks(s0, 0);
        compute_ks(s0, 16);
    }

    // ---- LoRA k16 chunk: T0 in stage0 A region, T1 in stage1 A region ----
    __syncthreads();
    {
        int row = tid >> 1, cg = (tid & 1) * 8;
        uint32_t d = (uint32_t)(row * ASTRIDE + cg) * 2;
        *(uint4*)(dsm + A_OFF(0) + d) = *(const uint4*)(T0h + (size_t)(bm + row) * RR + cg);
        *(uint4*)(dsm + A_OFF(1) + d) = *(const uint4*)(T0l + (size_t)(bm + row) * RR + cg);
        *(uint4*)(dsm + STG_BYTES + A_OFF(0) + d) = *(const uint4*)(T1h + (size_t)(bm + row) * RR + cg);
        *(uint4*)(dsm + STG_BYTES + A_OFF(1) + d) = *(const uint4*)(T1l + (size_t)(bm + row) * RR + cg);
#pragma unroll
        for (int j = 0; j < 2; j++) {
            int c = tid + j * 256;
            int brow = c >> 1, bcg = (c & 1) * 8;
            int rr = (MODE == 0) ? brow : (brow & 127);
            const __nv_bfloat16* ph = (brow < 128) ? L0h : L1h;
            const __nv_bfloat16* pl = (brow < 128) ? L0l : L1l;
            uint32_t bd = (uint32_t)(brow * ASTRIDE + bcg) * 2;
            *(uint4*)(dsm + B_OFF(0) + bd) = *(const uint4*)(ph + (size_t)(bn + rr) * RR + bcg);
            *(uint4*)(dsm + B_OFF(1) + bd) = *(const uint4*)(pl + (size_t)(bn + rr) * RR + bcg);
        }
        __syncthreads();
#pragma unroll
        for (int o = 0; o < 2; o++) {
            uint32_t sA = sb + (uint32_t)o * STG_BYTES;
            uint32_t ah[4][4], al[4][4], bb[2][4];
#pragma unroll
            for (int mi = 0; mi < 4; mi++) {
                LDSM4(ah[mi], sA + A_OFF(0) + (uint32_t)((wm * 64 + mi * 16 + ar) * ASTRIDE + koff) * 2);
                LDSM4(al[mi], sA + A_OFF(1) + (uint32_t)((wm * 64 + mi * 16 + ar) * ASTRIDE + koff) * 2);
            }
#pragma unroll
            for (int nb = 0; nb < 2; nb++)
                LDSM4(bb[nb], sb + B_OFF(0) + (uint32_t)((o * 128 + wn * 32 + nb * 16 + ar) * ASTRIDE + koff) * 2);
#pragma unroll
            for (int mi = 0; mi < 4; mi++)
#pragma unroll
                for (int ni = 0; ni < 4; ni++) {
                    MMA16816(acc[o][mi][ni], ah[mi], bb[ni >> 1][ni & 1], bb[ni >> 1][(ni & 1) + 2]);
                    MMA16816(acc[o][mi][ni], al[mi], bb[ni >> 1][ni & 1], bb[ni >> 1][(ni & 1) + 2]);
                }
#pragma unroll
            for (int nb = 0; nb < 2; nb++)
                LDSM4(bb[nb], sb + B_OFF(1) + (uint32_t)((o * 128 + wn * 32 + nb * 16 + ar) * ASTRIDE + koff) * 2);
#pragma unroll
            for (int mi = 0; mi < 4; mi++)
#pragma unroll
                for (int ni = 0; ni < 4; ni++)
                    MMA16816(acc[o][mi][ni], ah[mi], bb[ni >> 1][ni & 1], bb[ni >> 1][(ni & 1) + 2]);
        }
    }

    // ---- epilogue ----
#pragma unroll
    for (int mi = 0; mi < 4; mi++) {
        int r0 = bm + wm * 64 + mi * 16 + (lane >> 2);
#pragma unroll
        for (int ni = 0; ni < 4; ni++) {
            int cl = wn * 32 + ni * 8 + (lane & 3) * 2;
            if (MODE == 1) {
                float bg0 = bias0[bn + cl], bg1 = bias0[bn + cl + 1];
                float bu0 = bias1[bn + cl], bu1 = bias1[bn + cl + 1];
#pragma unroll
                for (int h2 = 0; h2 < 2; h2++) {
                    int r = r0 + h2 * 8;
                    float g0 = acc[0][mi][ni][h2 * 2 + 0] + bg0;
                    float g1 = acc[0][mi][ni][h2 * 2 + 1] + bg1;
                    float u0 = acc[1][mi][ni][h2 * 2 + 0] + bu0;
                    float u1 = acc[1][mi][ni][h2 * 2 + 1] + bu1;
                    float v0 = fmaxf(g0, 0.f) * u0;
                    float v1 = fmaxf(g1, 0.f) * u1;
                    __nv_bfloat16 h0 = __float2bfloat16_rn(v0);
                    __nv_bfloat16 h1 = __float2bfloat16_rn(v1);
                    __nv_bfloat16 l0 = __float2bfloat16_rn(v0 - __bfloat162float(h0));
                    __nv_bfloat16 l1 = __float2bfloat16_rn(v1 - __bfloat162float(h1));
                    size_t off = (size_t)r * N + bn + cl;
                    *(__nv_bfloat162*)(Xh + off) = __halves2bfloat162(h0, h1);
                    *(__nv_bfloat162*)(Xl + off) = __halves2bfloat162(l0, l1);
                }
            } else {
#pragma unroll
                for (int o = 0; o < 2; o++) {
                    int col = bn + o * 128 + cl;
                    float b0 = bias0[col], b1 = bias0[col + 1];
#pragma unroll
                    for (int h2 = 0; h2 < 2; h2++) {
                        int r = r0 + h2 * 8;
                        size_t off = (size_t)r * N + col;
                        *(float2*)(Cf + off) = make_float2(
                            acc[o][mi][ni][h2 * 2 + 0] + b0,
                            acc[o][mi][ni][h2 * 2 + 1] + b1);
                    }
                }
            }
        }
    }
}

// ---------------- launcher ----------------
extern "C" void kernel_launch(void* const* d_in, const int* in_sizes, int n_in,
                              void* d_out, int out_size)
{
    const float* x1     = (const float*)d_in[0];
    const float* w_gate = (const float*)d_in[1];
    const float* b_gate = (const float*)d_in[2];
    const float* wga    = (const float*)d_in[3];
    const float* wgb    = (const float*)d_in[4];
    const float* w_up   = (const float*)d_in[5];
    const float* b_up   = (const float*)d_in[6];
    const float* wua    = (const float*)d_in[7];
    const float* wub    = (const float*)d_in[8];
    const float* w_down = (const float*)d_in[9];
    const float* b_down = (const float*)d_in[10];
    const float* wda    = (const float*)d_in[11];
    const float* wdb    = (const float*)d_in[12];
    float* out = (float*)d_out;

#define SYM(p, s) void* p; cudaGetSymbolAddress(&p, s)
    SYM(x1h, g_x1h); SYM(x1l, g_x1l); SYM(x3h, g_x3h); SYM(x3l, g_x3l);
    SYM(wgh, g_wgh); SYM(wgl, g_wgl); SYM(wuh, g_wuh); SYM(wul, g_wul);
    SYM(wdh, g_wdh); SYM(wdl, g_wdl);
    SYM(lgh, g_lgh); SYM(lgl, g_lgl); SYM(luh, g_luh); SYM(lul, g_lul);
    SYM(ldh, g_ldh); SYM(ldl, g_ldl);
    SYM(tgh, g_tgh); SYM(tgl, g_tgl); SYM(tuh, g_tuh); SYM(tul, g_tul);
    SYM(tdh, g_tdh); SYM(tdl, g_tdl);
    SYM(gaTh, g_gaTh); SYM(gaTl, g_gaTl); SYM(uaTh, g_uaTh); SYM(uaTl, g_uaTl);
    SYM(daTh, g_daTh); SYM(daTl, g_daTl);
    SYM(Tgf, g_Tgf); SYM(Tuf, g_Tuf); SYM(Tdf, g_Tdf);
#undef SYM
#define BF(p) ((__nv_bfloat16*)(p))
#define F32(p) ((float*)(p))

    cudaFuncSetAttribute(gemm_mma<0>, cudaFuncAttributeMaxDynamicSharedMemorySize, GEMM_SMEM);
    cudaFuncSetAttribute(gemm_mma<1>, cudaFuncAttributeMaxDynamicSharedMemorySize, GEMM_SMEM);

    // conversions / transposes
    convert_hl<<<(int)((size_t)MTOK * DDIM / 1024), 256>>>(x1, (size_t)MTOK * DDIM, BF(x1h), BF(x1l));
    transpose_hl<<<dim3(FDIM / 32, DDIM / 32), dim3(32, 8)>>>(w_gate, DDIM, FDIM, BF(wgh), BF(wgl));
    transpose_hl<<<dim3(FDIM / 32, DDIM / 32), dim3(32, 8)>>>(w_up,   DDIM, FDIM, BF(wuh), BF(wul));
    transpose_hl<<<dim3(DDIM / 32, FDIM / 32), dim3(32, 8)>>>(w_down, FDIM, DDIM, BF(wdh), BF(wdl));
    lb_transpose<<<FDIM / 256, 256>>>(wgb, FDIM, BF(lgh), BF(lgl));
    lb_transpose<<<FDIM / 256, 256>>>(wub, FDIM, BF(luh), BF(lul));
    lb_transpose<<<DDIM / 256, 256>>>(wdb, DDIM, BF(ldh), BF(ldl));
    at_transpose<<<DDIM / 256, 256>>>(wga, DDIM, BF(gaTh), BF(gaTl));
    at_transpose<<<DDIM / 256, 256>>>(wua, DDIM, BF(uaTh), BF(uaTl));
    at_transpose<<<FDIM / 256, 256>>>(wda, FDIM, BF(daTh), BF(daTl));
    zero_t<<<(MTOK * RR) / 256, 256>>>(F32(Tgf), F32(Tuf), F32(Tdf));

    // LoRA-A gate + up via skinny tensor GEMM (K=2048, ksplit=2)
    lora_gemm<<<dim3(2, MTOK / 128), 256>>>(BF(x1h), BF(x1l), BF(gaTh), BF(gaTl),
                                            F32(Tgf), DDIM, DDIM / 2);
    lora_gemm<<<dim3(2, MTOK / 128), 256>>>(BF(x1h), BF(x1l), BF(uaTh), BF(uaTl),
                                            F32(Tuf), DDIM, DDIM / 2);
    convert_hl<<<(MTOK * RR) / 1024, 256>>>(F32(Tgf), MTOK * RR, BF(tgh), BF(tgl));
    convert_hl<<<(MTOK * RR) / 1024, 256>>>(F32(Tuf), MTOK * RR, BF(tuh), BF(tul));

    // fused gate+up -> x3 bf16 hi/lo
    gemm_mma<1><<<dim3(FDIM / 128, MTOK / 128), 256, GEMM_SMEM>>>(
        BF(x1h), BF(x1l),
        BF(wgh), BF(wgl), BF(wuh), BF(wul),
        BF(tgh), BF(tgl), BF(tuh), BF(tul),
        BF(lgh), BF(lgl), BF(luh), BF(lul),
        b_gate, b_up,
        nullptr, BF(x3h), BF(x3l), FDIM, DDIM);

    // LoRA-A down via skinny tensor GEMM (K=8192, ksplit=4)
    lora_gemm<<<dim3(4, MTOK / 128), 256>>>(BF(x3h), BF(x3l), BF(daTh), BF(daTl),
                                            F32(Tdf), FDIM, FDIM / 4);
    convert_hl<<<(MTOK * RR) / 1024, 256>>>(F32(Tdf), MTOK * RR, BF(tdh), BF(tdl));

    // down GEMM -> out (fp32)
    gemm_mma<0><<<dim3(DDIM / 256, MTOK / 128), 256, GEMM_SMEM>>>(
        BF(x3h), BF(x3l),
        BF(wdh), BF(wdl), BF(wdh), BF(wdl),
        BF(tdh), BF(tdl), BF(tdh), BF(tdl),
        BF(ldh), BF(ldl), BF(ldh), BF(ldl),
        b_down, nullptr,
        out, nullptr, nullptr, DDIM, FDIM);
}

// round 13
// speedup vs baseline: 2.5789x; 1.1512x over previous
#include <cuda_runtime.h>
#include <cuda_bf16.h>
#include <cuda_fp16.h>
#include <cstdint>

#define MTOK 8192
#define DDIM 2048
#define FDIM 8192
#define RR   16

// ---------------- device scratch (allocation-free) ----------------
__device__ __align__(1024) __nv_bfloat16 g_x1h[(size_t)MTOK * DDIM];
__device__ __align__(1024) __nv_bfloat16 g_x1l[(size_t)MTOK * DDIM];
__device__ __align__(1024) __half        g_x3h[(size_t)MTOK * FDIM];
__device__ __align__(1024) __half        g_x3l[(size_t)MTOK * FDIM];
__device__ __align__(1024) __nv_bfloat16 g_wgh[(size_t)FDIM * DDIM];
__device__ __align__(1024) __nv_bfloat16 g_wgl[(size_t)FDIM * DDIM];
__device__ __align__(1024) __nv_bfloat16 g_wuh[(size_t)FDIM * DDIM];
__device__ __align__(1024) __nv_bfloat16 g_wul[(size_t)FDIM * DDIM];
__device__ __align__(1024) __half        g_wdT[(size_t)DDIM * FDIM];   // fp16 single limb
__device__ __align__(1024) __nv_bfloat16 g_lgh[FDIM * RR], g_lgl[FDIM * RR];
__device__ __align__(1024) __nv_bfloat16 g_luh[FDIM * RR], g_lul[FDIM * RR];
__device__ __align__(1024) __half        g_ldh[DDIM * RR], g_ldl[DDIM * RR];
__device__ __align__(1024) __nv_bfloat16 g_tgh[MTOK * RR], g_tgl[MTOK * RR];
__device__ __align__(1024) __nv_bfloat16 g_tuh[MTOK * RR], g_tul[MTOK * RR];
__device__ __align__(1024) __half        g_tdh[MTOK * RR], g_tdl[MTOK * RR];
__device__ __align__(1024) __nv_bfloat16 g_gaTh[RR * DDIM], g_gaTl[RR * DDIM];
__device__ __align__(1024) __nv_bfloat16 g_uaTh[RR * DDIM], g_uaTl[RR * DDIM];
__device__ __align__(1024) __half        g_daTh[RR * FDIM], g_daTl[RR * FDIM];
__device__ __align__(1024) float g_Tgf[MTOK * RR], g_Tuf[MTOK * RR], g_Tdf[MTOK * RR];

// ---------------- PTX helpers ----------------
__device__ __forceinline__ uint32_t smem_u32(const void* p) {
    uint32_t a;
    asm("{ .reg .u64 t; cvta.to.shared.u64 t, %1; cvt.u32.u64 %0, t; }" : "=r"(a) : "l"(p));
    return a;
}
#define CPA(dst, src) \
    asm volatile("cp.async.cg.shared.global [%0], [%1], 16;\n" :: "r"(dst), "l"(src))
#define CPC() asm volatile("cp.async.commit_group;\n" ::: "memory")
#define CPW(n) asm volatile("cp.async.wait_group %0;\n" :: "n"(n) : "memory")
#define LDSM4(R, addr)                                                          \
    asm volatile("ldmatrix.sync.aligned.m8n8.x4.shared.b16 {%0,%1,%2,%3}, [%4];\n" \
        : "=r"((R)[0]), "=r"((R)[1]), "=r"((R)[2]), "=r"((R)[3]) : "r"(addr))
#define MMA16816(D, A, B0, B1)                                                  \
    asm volatile("mma.sync.aligned.m16n8k16.row.col.f32.bf16.bf16.f32 "         \
        "{%0,%1,%2,%3}, {%4,%5,%6,%7}, {%8,%9}, {%0,%1,%2,%3};\n"               \
        : "+f"((D)[0]), "+f"((D)[1]), "+f"((D)[2]), "+f"((D)[3])                \
        : "r"((A)[0]), "r"((A)[1]), "r"((A)[2]), "r"((A)[3]), "r"(B0), "r"(B1))
#define MMA16816H(D, A, B0, B1)                                                 \
    asm volatile("mma.sync.aligned.m16n8k16.row.col.f32.f16.f16.f32 "           \
        "{%0,%1,%2,%3}, {%4,%5,%6,%7}, {%8,%9}, {%0,%1,%2,%3};\n"               \
        : "+f"((D)[0]), "+f"((D)[1]), "+f"((D)[2]), "+f"((D)[3])                \
        : "r"((A)[0]), "r"((A)[1]), "r"((A)[2]), "r"((A)[3]), "r"(B0), "r"(B1))

// gate+up kernel SMEM: Ah(10240) Al(10240) Bh(20480) Bl(20480) = 61440; 3 stages
#define ASTRIDE 40
#define STG_BYTES 61440
#define A_OFF(h) ((h) * 10240)
#define B_OFF(h) (20480 + (h) * 20480)
#define GEMM_SMEM (3 * STG_BYTES)
// down kernel SMEM: Ah(10240) Al(10240) B(10240) = 30720; 3 stages
#define DOFF_AH 0
#define DOFF_AL 10240
#define DOFF_B  20480
#define DSTG 30720
#define DOWN_SMEM (3 * DSTG)

// ---------------- fp32 -> bf16 hi/lo ----------------
__global__ __launch_bounds__(256)
void convert_hl(const float* __restrict__ s, size_t n,
                __nv_bfloat16* __restrict__ h, __nv_bfloat16* __restrict__ l)
{
    size_t i = ((size_t)blockIdx.x * 256 + threadIdx.x) * 4;
    if (i >= n) return;
    float4 v = *reinterpret_cast<const float4*>(s + i);
    float vv[4] = {v.x, v.y, v.z, v.w};
    __nv_bfloat16 hb[4], lb[4];
#pragma unroll
    for (int q = 0; q < 4; q++) {
        hb[q] = __float2bfloat16_rn(vv[q]);
        lb[q] = __float2bfloat16_rn(vv[q] - __bfloat162float(hb[q]));
    }
    *reinterpret_cast<uint2*>(h + i) = *reinterpret_cast<uint2*>(hb);
    *reinterpret_cast<uint2*>(l + i) = *reinterpret_cast<uint2*>(lb);
}

// ---------------- fp32 -> fp16 hi/lo ----------------
__global__ __launch_bounds__(256)
void convert_hl_f16(const float* __restrict__ s, size_t n,
                    __half* __restrict__ h, __half* __restrict__ l)
{
    size_t i = ((size_t)blockIdx.x * 256 + threadIdx.x) * 4;
    if (i >= n) return;
    float4 v = *reinterpret_cast<const float4*>(s + i);
    float vv[4] = {v.x, v.y, v.z, v.w};
    __half hb[4], lb[4];
#pragma unroll
    for (int q = 0; q < 4; q++) {
        hb[q] = __float2half_rn(vv[q]);
        lb[q] = __float2half_rn(vv[q] - __half2float(hb[q]));
    }
    *reinterpret_cast<uint2*>(h + i) = *reinterpret_cast<uint2*>(hb);
    *reinterpret_cast<uint2*>(l + i) = *reinterpret_cast<uint2*>(lb);
}

// ---------------- transpose fp32 [R,C] -> bf16 hi/lo [C,R] ----------------
__global__ __launch_bounds__(256)
void transpose_hl(const float* __restrict__ src, int R, int C,
                  __nv_bfloat16* __restrict__ dh, __nv_bfloat16* __restrict__ dl)
{
    __shared__ float t[32][33];
    int tx = threadIdx.x, ty = threadIdx.y;
    int x = blockIdx.x * 32 + tx, y0 = blockIdx.y * 32;
#pragma unroll
    for (int j = 0; j < 32; j += 8)
        t[ty + j][tx] = src[(size_t)(y0 + ty + j) * C + x];
    __syncthreads();
    int x2 = y0 + tx, y2 = blockIdx.x * 32;
#pragma unroll
    for (int j = 0; j < 32; j += 8) {
        float v = t[tx][ty + j];
        __nv_bfloat16 h = __float2bfloat16_rn(v);
        dh[(size_t)(y2 + ty + j) * R + x2] = h;
        dl[(size_t)(y2 + ty + j) * R + x2] = __float2bfloat16_rn(v - __bfloat162float(h));
    }
}

// ---------------- transpose fp32 [R,C] -> fp16 single [C,R] ----------------
__global__ __launch_bounds__(256)
void transpose_f16(const float* __restrict__ src, int R, int C,
                   __half* __restrict__ dh)
{
    __shared__ float t[32][33];
    int tx = threadIdx.x, ty = threadIdx.y;
    int x = blockIdx.x * 32 + tx, y0 = blockIdx.y * 32;
#pragma unroll
    for (int j = 0; j < 32; j += 8)
        t[ty + j][tx] = src[(size_t)(y0 + ty + j) * C + x];
    __syncthreads();
    int x2 = y0 + tx, y2 = blockIdx.x * 32;
#pragma unroll
    for (int j = 0; j < 32; j += 8)
        dh[(size_t)(y2 + ty + j) * R + x2] = __float2half_rn(t[tx][ty + j]);
}

// ---------------- Lb [16,N] -> [N,16] bf16 hi/lo ----------------
__global__ __launch_bounds__(256)
void lb_transpose(const float* __restrict__ Lb, int N,
                  __nv_bfloat16* __restrict__ dh, __nv_bfloat16* __restrict__ dl)
{
    int n = blockIdx.x * 256 + threadIdx.x;
    if (n >= N) return;
#pragma unroll
    for (int r = 0; r < RR; r++) {
        float v = Lb[(size_t)r * N + n];
        __nv_bfloat16 h = __float2bfloat16_rn(v);
        dh[(size_t)n * RR + r] = h;
        dl[(size_t)n * RR + r] = __float2bfloat16_rn(v - __bfloat162float(h));
    }
}

// ---------------- Lb [16,N] -> [N,16] fp16 hi/lo ----------------
__global__ __launch_bounds__(256)
void lb_transpose_f16(const float* __restrict__ Lb, int N,
                      __half* __restrict__ dh, __half* __restrict__ dl)
{
    int n = blockIdx.x * 256 + threadIdx.x;
    if (n >= N) return;
#pragma unroll
    for (int r = 0; r < RR; r++) {
        float v = Lb[(size_t)r * N + n];
        __half h = __float2half_rn(v);
        dh[(size_t)n * RR + r] = h;
        dl[(size_t)n * RR + r] = __float2half_rn(v - __half2float(h));
    }
}

// ---------------- A [K,16] -> At [16,K] bf16 hi/lo ----------------
__global__ __launch_bounds__(256)
void at_transpose(const float* __restrict__ A, int K,
                  __nv_bfloat16* __restrict__ dh, __nv_bfloat16* __restrict__ dl)
{
    int k = blockIdx.x * 256 + threadIdx.x;
    if (k >= K) return;
#pragma unroll
    for (int r = 0; r < RR; r++) {
        float v = A[(size_t)k * RR + r];
        __nv_bfloat16 h = __float2bfloat16_rn(v);
        dh[(size_t)r * K + k] = h;
        dl[(size_t)r * K + k] = __float2bfloat16_rn(v - __bfloat162float(h));
    }
}

// ---------------- A [K,16] -> At [16,K] fp16 hi/lo ----------------
__global__ __launch_bounds__(256)
void at_transpose_f16(const float* __restrict__ A, int K,
                      __half* __restrict__ dh, __half* __restrict__ dl)
{
    int k = blockIdx.x * 256 + threadIdx.x;
    if (k >= K) return;
#pragma unroll
    for (int r = 0; r < RR; r++) {
        float v = A[(size_t)k * RR + r];
        __half h = __float2half_rn(v);
        dh[(size_t)r * K + k] = h;
        dl[(size_t)r * K + k] = __float2half_rn(v - __half2float(h));
    }
}

// ---------------- zero the three T accumulators ----------------
__global__ __launch_bounds__(256)
void zero_t(float* a, float* b, float* c)
{
    int i = blockIdx.x * 256 + threadIdx.x;
    if (i < MTOK * RR) { a[i] = 0.f; b[i] = 0.f; c[i] = 0.f; }
}

// ---------------- skinny tensor GEMM: T[M,16] += X[M,K] @ At[16,K]^T ----------------
// byte-level loads (dtype-agnostic); MMA dtype selected by template.
#define LXS 48
#define LSTG 14336
template <bool F16>
__global__ __launch_bounds__(256)
void lora_gemm(const void* __restrict__ Xh_, const void* __restrict__ Xl_,
               const void* __restrict__ Ath_, const void* __restrict__ Atl_,
               float* __restrict__ T, int K, int kslice)
{
    const char* Xh = (const char*)Xh_;   const char* Xl = (const char*)Xl_;
    const char* Ath = (const char*)Ath_; const char* Atl = (const char*)Atl_;
    __shared__ __align__(128) char sm[3 * LSTG];
    const uint32_t sb = smem_u32(sm);
    const int tid = threadIdx.x, lane = tid & 31, w = tid >> 5;
    const int bm = blockIdx.y * 128;
    const int k0 = blockIdx.x * kslice;

    float acc[2][4];
#pragma unroll
    for (int a = 0; a < 2; a++)
#pragma unroll
        for (int b = 0; b < 4; b++) acc[a][b] = 0.f;

    auto load = [&](int st, int kk) {
        uint32_t s0 = sb + (uint32_t)st * LSTG;
#pragma unroll
        for (int j = 0; j < 2; j++) {
            int c = tid + j * 256;
            int row = c >> 2, pc = c & 1, limb = (c >> 1) & 1;
            const char* src = (limb ? Xl : Xh) + ((size_t)(bm + row) * K + kk) * 2 + pc * 16;
            CPA(s0 + (uint32_t)(limb * 6144 + row * LXS + pc * 16), src);
        }
        if (tid < 64) {
            int row = tid >> 2, pc = tid & 1, limb = (tid >> 1) & 1;
            const char* src = (limb ? Atl : Ath) + ((size_t)row * K + kk) * 2 + pc * 16;
            CPA(s0 + (uint32_t)(12288 + limb * 768 + row * LXS + pc * 16), src);
        }
    };

    const int iters = kslice / 16;
    load(0, k0); CPC();
    load(1, k0 + 16); CPC();

    for (int it = 0; it < iters; it++) {
        if (it + 1 < iters) { CPW(1); } else { CPW(0); }
        __syncthreads();
        if (it + 2 < iters) { load((it + 2) % 3, k0 + (it + 2) * 16); CPC(); }
        uint32_t s0 = sb + (uint32_t)(it % 3) * LSTG;
        uint32_t ah[4], al[4], bh[4], bl[4];
        uint32_t xoff = (uint32_t)((w * 16 + (lane & 15)) * LXS + (lane >> 4) * 16);
        uint32_t boff = (uint32_t)(((lane & 15)) * LXS + (lane >> 4) * 16);
        LDSM4(ah, s0 + xoff);
        LDSM4(al, s0 + 6144 + xoff);
        LDSM4(bh, s0 + 12288 + boff);
        LDSM4(bl, s0 + 12288 + 768 + boff);
#pragma unroll
        for (int ni = 0; ni < 2; ni++) {
            if (F16) {
                MMA16816H(acc[ni], ah, bh[ni], bh[ni + 2]);
                MMA16816H(acc[ni], ah, bl[ni], bl[ni + 2]);
                MMA16816H(acc[ni], al, bh[ni], bh[ni + 2]);
            } else {
                MMA16816(acc[ni], ah, bh[ni], bh[ni + 2]);
                MMA16816(acc[ni], ah, bl[ni], bl[ni + 2]);
                MMA16816(acc[ni], al, bh[ni], bh[ni + 2]);
            }
        }
    }

#pragma unroll
    for (int ni = 0; ni < 2; ni++)
#pragma unroll
        for (int h2 = 0; h2 < 2; h2++) {
            int row = bm + w * 16 + (lane >> 2) + h2 * 8;
            int col = ni * 8 + (lane & 3) * 2;
            atomicAdd(&T[(size_t)row * RR + col],     acc[ni][h2 * 2 + 0]);
            atomicAdd(&T[(size_t)row * RR + col + 1], acc[ni][h2 * 2 + 1]);
        }
}

// ---------------- fused gate+up HMMA GEMM (bf16 3-combo), x3 out as fp16 h/l ----------------
__global__ __launch_bounds__(256, 1)
void gemm_gateup(const __nv_bfloat16* __restrict__ Ah, const __nv_bfloat16* __restrict__ Al,
                 const __nv_bfloat16* __restrict__ B0h, const __nv_bfloat16* __restrict__ B0l,
                 const __nv_bfloat16* __restrict__ B1h, const __nv_bfloat16* __restrict__ B1l,
                 const __nv_bfloat16* __restrict__ T0h, const __nv_bfloat16* __restrict__ T0l,
                 const __nv_bfloat16* __restrict__ T1h, const __nv_bfloat16* __restrict__ T1l,
                 const __nv_bfloat16* __restrict__ L0h, const __nv_bfloat16* __restrict__ L0l,
                 const __nv_bfloat16* __restrict__ L1h, const __nv_bfloat16* __restrict__ L1l,
                 const float* __restrict__ bias0, const float* __restrict__ bias1,
                 __half* __restrict__ Xh, __half* __restrict__ Xl,
                 int N, int K)
{
    extern __shared__ char dsm[];
    const uint32_t sb = smem_u32(dsm);
    const int tid = threadIdx.x, lane = tid & 31, wid = tid >> 5;
    const int wm = wid >> 2, wn = wid & 3;
    const int bm = blockIdx.y * 128;
    const int bn = blockIdx.x * 128;

    float acc[2][4][4][4];
#pragma unroll
    for (int o = 0; o < 2; o++)
#pragma unroll
        for (int a = 0; a < 4; a++)
#pragma unroll
            for (int b = 0; b < 4; b++)
#pragma unroll
                for (int c = 0; c < 4; c++) acc[o][a][b][c] = 0.f;

    auto load_stage = [&](int st, int k0) {
        uint32_t s0 = sb + (uint32_t)st * STG_BYTES;
#pragma unroll
        for (int j = 0; j < 2; j++) {
            int c = tid + j * 256;
            int row = c >> 2, cg = (c & 3) * 8;
            uint32_t d = (uint32_t)(row * ASTRIDE + cg) * 2;
            CPA(s0 + A_OFF(0) + d, Ah + (size_t)(bm + row) * K + k0 + cg);
            CPA(s0 + A_OFF(1) + d, Al + (size_t)(bm + row) * K + k0 + cg);
        }
#pragma unroll
        for (int j = 0; j < 4; j++) {
            int c = tid + j * 256;
            int row = c >> 2, cg = (c & 3) * 8;
            int rr = row & 127;
            const __nv_bfloat16* ph = (row < 128) ? B0h : B1h;
            const __nv_bfloat16* pl = (row < 128) ? B0l : B1l;
            uint32_t d = (uint32_t)(row * ASTRIDE + cg) * 2;
            CPA(s0 + B_OFF(0) + d, ph + (size_t)(bn + rr) * K + k0 + cg);
            CPA(s0 + B_OFF(1) + d, pl + (size_t)(bn + rr) * K + k0 + cg);
        }
    };

    const int ar = lane & 15;
    const int koff = (lane >> 4) * 8;

    auto compute_ks = [&](uint32_t s0, int kbase) {
        const int kc = kbase + koff;
        uint32_t ah[4][4], al[4][4], b0[2][4], b1[2][4];
#pragma unroll
        for (int mi = 0; mi < 4; mi++)
            LDSM4(ah[mi], s0 + A_OFF(0) + (uint32_t)((wm * 64 + mi * 16 + ar) * ASTRIDE + kc) * 2);
#pragma unroll
        for (int nb = 0; nb < 2; nb++) {
            LDSM4(b0[nb], s0 + B_OFF(0) + (uint32_t)((wn * 32 + nb * 16 + ar) * ASTRIDE + kc) * 2);
            LDSM4(b1[nb], s0 + B_OFF(0) + (uint32_t)((128 + wn * 32 + nb * 16 + ar) * ASTRIDE + kc) * 2);
        }
#pragma unroll
        for (int mi = 0; mi < 4; mi++)
#pragma unroll
            for (int ni = 0; ni < 4; ni++) {
                MMA16816(acc[0][mi][ni], ah[mi], b0[ni >> 1][ni & 1], b0[ni >> 1][(ni & 1) + 2]);
                MMA16816(acc[1][mi][ni], ah[mi], b1[ni >> 1][ni & 1], b1[ni >> 1][(ni & 1) + 2]);
            }
#pragma unroll
        for (int mi = 0; mi < 4; mi++)
            LDSM4(al[mi], s0 + A_OFF(1) + (uint32_t)((wm * 64 + mi * 16 + ar) * ASTRIDE + kc) * 2);
#pragma unroll
        for (int mi = 0; mi < 4; mi++)
#pragma unroll
            for (int ni = 0; ni < 4; ni++) {
                MMA16816(acc[0][mi][ni], al[mi], b0[ni >> 1][ni & 1], b0[ni >> 1][(ni & 1) + 2]);
                MMA16816(acc[1][mi][ni], al[mi], b1[ni >> 1][ni & 1], b1[ni >> 1][(ni & 1) + 2]);
            }
#pragma unroll
        for (int nb = 0; nb < 2; nb++) {
            LDSM4(b0[nb], s0 + B_OFF(1) + (uint32_t)((wn * 32 + nb * 16 + ar) * ASTRIDE + kc) * 2);
            LDSM4(b1[nb], s0 + B_OFF(1) + (uint32_t)((128 + wn * 32 + nb * 16 + ar) * ASTRIDE + kc) * 2);
        }
#pragma unroll
        for (int mi = 0; mi < 4; mi++)
#pragma unroll
            for (int ni = 0; ni < 4; ni++) {
                MMA16816(acc[0][mi][ni], ah[mi], b0[ni >> 1][ni & 1], b0[ni >> 1][(ni & 1) + 2]);
                MMA16816(acc[1][mi][ni], ah[mi], b1[ni >> 1][ni & 1], b1[ni >> 1][(ni & 1) + 2]);
            }
    };

    const int KC = K / 32;
    load_stage(0, 0); CPC();
    load_stage(1, 32); CPC();

    for (int c = 0; c < KC; c++) {
        if (c + 1 < KC) { CPW(1); } else { CPW(0); }
        __syncthreads();
        if (c + 2 < KC) { load_stage((c + 2) % 3, (c + 2) * 32); CPC(); }
        uint32_t s0 = sb + (uint32_t)(c % 3) * STG_BYTES;
        compute_ks(s0, 0);
        compute_ks(s0, 16);
    }

    // ---- LoRA k16 chunk: T0 in stage0 A region, T1 in stage1 A region ----
    __syncthreads();
    {
        int row = tid >> 1, cg = (tid & 1) * 8;
        uint32_t d = (uint32_t)(row * ASTRIDE + cg) * 2;
        *(uint4*)(dsm + A_OFF(0) + d) = *(const uint4*)(T0h + (size_t)(bm + row) * RR + cg);
        *(uint4*)(dsm + A_OFF(1) + d) = *(const uint4*)(T0l + (size_t)(bm + row) * RR + cg);
        *(uint4*)(dsm + STG_BYTES + A_OFF(0) + d) = *(const uint4*)(T1h + (size_t)(bm + row) * RR + cg);
        *(uint4*)(dsm + STG_BYTES + A_OFF(1) + d) = *(const uint4*)(T1l + (size_t)(bm + row) * RR + cg);
#pragma unroll
        for (int j = 0; j < 2; j++) {
            int c = tid + j * 256;
            int brow = c >> 1, bcg = (c & 1) * 8;
            int rr = brow & 127;
            const __nv_bfloat16* ph = (brow < 128) ? L0h : L1h;
            const __nv_bfloat16* pl = (brow < 128) ? L0l : L1l;
            uint32_t bd = (uint32_t)(brow * ASTRIDE + bcg) * 2;
            *(uint4*)(dsm + B_OFF(0) + bd) = *(const uint4*)(ph + (size_t)(bn + rr) * RR + bcg);
            *(uint4*)(dsm + B_OFF(1) + bd) = *(const uint4*)(pl + (size_t)(bn + rr) * RR + bcg);
        }
        __syncthreads();
#pragma unroll
        for (int o = 0; o < 2; o++) {
            uint32_t sA = sb + (uint32_t)o * STG_BYTES;
            uint32_t ah[4][4], al[4][4], bb[2][4];
#pragma unroll
            for (int mi = 0; mi < 4; mi++) {
                LDSM4(ah[mi], sA + A_OFF(0) + (uint32_t)((wm * 64 + mi * 16 + ar) * ASTRIDE + koff) * 2);
                LDSM4(al[mi], sA + A_OFF(1) + (uint32_t)((wm * 64 + mi * 16 + ar) * ASTRIDE + koff) * 2);
            }
#pragma unroll
            for (int nb = 0; nb < 2; nb++)
                LDSM4(bb[nb], sb + B_OFF(0) + (uint32_t)((o * 128 + wn * 32 + nb * 16 + ar) * ASTRIDE + koff) * 2);
#pragma unroll
            for (int mi = 0; mi < 4; mi++)
#pragma unroll
                for (int ni = 0; ni < 4; ni++) {
                    MMA16816(acc[o][mi][ni], ah[mi], bb[ni >> 1][ni & 1], bb[ni >> 1][(ni & 1) + 2]);
                    MMA16816(acc[o][mi][ni], al[mi], bb[ni >> 1][ni & 1], bb[ni >> 1][(ni & 1) + 2]);
                }
#pragma unroll
            for (int nb = 0; nb < 2; nb++)
                LDSM4(bb[nb], sb + B_OFF(1) + (uint32_t)((o * 128 + wn * 32 + nb * 16 + ar) * ASTRIDE + koff) * 2);
#pragma unroll
            for (int mi = 0; mi < 4; mi++)
#pragma unroll
                for (int ni = 0; ni < 4; ni++)
                    MMA16816(acc[o][mi][ni], ah[mi], bb[ni >> 1][ni & 1], bb[ni >> 1][(ni & 1) + 2]);
        }
    }

    // ---- epilogue: x3 = relu(y_g)*y_u as fp16 hi/lo ----
#pragma unroll
    for (int mi = 0; mi < 4; mi++) {
        int r0 = bm + wm * 64 + mi * 16 + (lane >> 2);
#pragma unroll
        for (int ni = 0; ni < 4; ni++) {
            int cl = wn * 32 + ni * 8 + (lane & 3) * 2;
            float bg0 = bias0[bn + cl], bg1 = bias0[bn + cl + 1];
            float bu0 = bias1[bn + cl], bu1 = bias1[bn + cl + 1];
#pragma unroll
            for (int h2 = 0; h2 < 2; h2++) {
                int r = r0 + h2 * 8;
                float g0 = acc[0][mi][ni][h2 * 2 + 0] + bg0;
                float g1 = acc[0][mi][ni][h2 * 2 + 1] + bg1;
                float u0 = acc[1][mi][ni][h2 * 2 + 0] + bu0;
                float u1 = acc[1][mi][ni][h2 * 2 + 1] + bu1;
                float v0 = fmaxf(g0, 0.f) * u0;
                float v1 = fmaxf(g1, 0.f) * u1;
                __half h0 = __float2half_rn(v0);
                __half h1 = __float2half_rn(v1);
                __half l0 = __float2half_rn(v0 - __half2float(h0));
                __half l1 = __float2half_rn(v1 - __half2float(h1));
                size_t off = (size_t)r * N + bn + cl;
                *(__half2*)(Xh + off) = __halves2half2(h0, h1);
                *(__half2*)(Xl + off) = __halves2half2(l0, l1);
            }
        }
    }
}

// ---------------- down GEMM: fp16 2-combo (A=x3 h/l, B=wd single) + fp16 LoRA ----------------
__global__ __launch_bounds__(256, 1)
void gemm_down(const __half* __restrict__ Ah, const __half* __restrict__ Al,
               const __half* __restrict__ B,
               const __half* __restrict__ Th, const __half* __restrict__ Tl,
               const __half* __restrict__ Lh, const __half* __restrict__ Ll,
               const float* __restrict__ bias,
               float* __restrict__ C,
               int N, int K)
{
    extern __shared__ char dsm[];
    const uint32_t sb = smem_u32(dsm);
    const int tid = threadIdx.x, lane = tid & 31, wid = tid >> 5;
    const int wm = wid >> 2, wn = wid & 3;            // 2 x 4 warps; warp tile 64m x 32n
    const int bm = blockIdx.y * 128, bn = blockIdx.x * 128;

    float acc[4][4][4];
#pragma unroll
    for (int a = 0; a < 4; a++)
#pragma unroll
        for (int b = 0; b < 4; b++)
#pragma unroll
            for (int c = 0; c < 4; c++) acc[a][b][c] = 0.f;

    auto load_stage = [&](int st, int k0) {
        uint32_t s0 = sb + (uint32_t)st * DSTG;
#pragma unroll
        for (int j = 0; j < 4; j++) {                 // A h/l: 1024 chunks of 16B
            int c = tid + j * 256;
            int limb = c >> 9, idx = c & 511;
            int row = idx >> 2, cg = (idx & 3) * 8;
            const __half* src = (limb ? Al : Ah) + (size_t)(bm + row) * K + k0 + cg;
            CPA(s0 + (uint32_t)(limb * 10240 + row * ASTRIDE * 2 + (idx & 3) * 16), src);
        }
#pragma unroll
        for (int j = 0; j < 2; j++) {                 // B: 512 chunks
            int c = tid + j * 256;
            int row = c >> 2, cg = (c & 3) * 8;
            CPA(s0 + DOFF_B + (uint32_t)(row * ASTRIDE * 2 + (c & 3) * 16),
                B + (size_t)(bn + row) * K + k0 + cg);
        }
    };

    const int ar = lane & 15;
    const int koff = (lane >> 4) * 8;

    auto compute_ks = [&](uint32_t s0, int kbase) {
        const int kc = kbase + koff;
        uint32_t ah[4][4], al[4][4], bb[2][4];
#pragma unroll
        for (int mi = 0; mi < 4; mi++)
            LDSM4(ah[mi], s0 + DOFF_AH + (uint32_t)((wm * 64 + mi * 16 + ar) * ASTRIDE + kc) * 2);
#pragma unroll
        for (int nb = 0; nb < 2; nb++)
            LDSM4(bb[nb], s0 + DOFF_B + (uint32_t)((wn * 32 + nb * 16 + ar) * ASTRIDE + kc) * 2);
#pragma unroll
        for (int mi = 0; mi < 4; mi++)
#pragma unroll
            for (int ni = 0; ni < 4; ni++)
                MMA16816H(acc[mi][ni], ah[mi], bb[ni >> 1][ni & 1], bb[ni >> 1][(ni & 1) + 2]);
#pragma unroll
        for (int mi = 0; mi < 4; mi++)
            LDSM4(al[mi], s0 + DOFF_AL + (uint32_t)((wm * 64 + mi * 16 + ar) * ASTRIDE + kc) * 2);
#pragma unroll
        for (int mi = 0; mi < 4; mi++)
#pragma unroll
            for (int ni = 0; ni < 4; ni++)
                MMA16816H(acc[mi][ni], al[mi], bb[ni >> 1][ni & 1], bb[ni >> 1][(ni & 1) + 2]);
    };

    const int KC = K / 32;
    load_stage(0, 0); CPC();
    load_stage(1, 32); CPC();

    for (int c = 0; c < KC; c++) {
        if (c + 1 < KC) { CPW(1); } else { CPW(0); }
        __syncthreads();
        if (c + 2 < KC) { load_stage((c + 2) % 3, (c + 2) * 32); CPC(); }
        uint32_t s0 = sb + (uint32_t)(c % 3) * DSTG;
        compute_ks(s0, 0);
        compute_ks(s0, 16);
    }

    // ---- LoRA k16 chunk: T h/l in stage0 A; Lh in stage0 B, Ll in stage1 B ----
    __syncthreads();
    {
        int row = tid >> 1, hf = tid & 1;
        uint32_t d = (uint32_t)(row * ASTRIDE * 2 + hf * 16);
        *(uint4*)(dsm + DOFF_AH + d) = *(const uint4*)(Th + (size_t)(bm + row) * RR + hf * 8);
        *(uint4*)(dsm + DOFF_AL + d) = *(const uint4*)(Tl + (size_t)(bm + row) * RR + hf * 8);
        *(uint4*)(dsm + DOFF_B + d)        = *(const uint4*)(Lh + (size_t)(bn + row) * RR + hf * 8);
        *(uint4*)(dsm + DSTG + DOFF_B + d) = *(const uint4*)(Ll + (size_t)(bn + row) * RR + hf * 8);
        __syncthreads();

        uint32_t ah[4][4], al[4][4], bh[2][4], bl[2][4];
#pragma unroll
        for (int mi = 0; mi < 4; mi++) {
            LDSM4(ah[mi], sb + DOFF_AH + (uint32_t)((wm * 64 + mi * 16 + ar) * ASTRIDE + koff) * 2);
            LDSM4(al[mi], sb + DOFF_AL + (uint32_t)((wm * 64 + mi * 16 + ar) * ASTRIDE + koff) * 2);
        }
#pragma unroll
        for (int nb = 0; nb < 2; nb++) {
            LDSM4(bh[nb], sb + DOFF_B + (uint32_t)((wn * 32 + nb * 16 + ar) * ASTRIDE + koff) * 2);
            LDSM4(bl[nb], sb + DSTG + DOFF_B + (uint32_t)((wn * 32 + nb * 16 + ar) * ASTRIDE + koff) * 2);
        }
#pragma unroll
        for (int mi = 0; mi < 4; mi++)
#pragma unroll
            for (int ni = 0; ni < 4; ni++) {
                MMA16816H(acc[mi][ni], ah[mi], bh[ni >> 1][ni & 1], bh[ni >> 1][(ni & 1) + 2]);
                MMA16816H(acc[mi][ni], ah[mi], bl[ni >> 1][ni & 1], bl[ni >> 1][(ni & 1) + 2]);
                MMA16816H(acc[mi][ni], al[mi], bh[ni >> 1][ni & 1], bh[ni >> 1][(ni & 1) + 2]);
            }
    }

    // ---- epilogue ----
#pragma unroll
    for (int mi = 0; mi < 4; mi++) {
        int r0 = bm + wm * 64 + mi * 16 + (lane >> 2);
#pragma unroll
        for (int ni = 0; ni < 4; ni++) {
            int cl = wn * 32 + ni * 8 + (lane & 3) * 2;
            float b0 = bias[bn + cl], b1 = bias[bn + cl + 1];
#pragma unroll
            for (int h2 = 0; h2 < 2; h2++) {
                int r = r0 + h2 * 8;
                size_t off = (size_t)r * N + bn + cl;
                *(float2*)(C + off) = make_float2(acc[mi][ni][h2 * 2 + 0] + b0,
                                                  acc[mi][ni][h2 * 2 + 1] + b1);
            }
        }
    }
}

// ---------------- launcher ----------------
extern "C" void kernel_launch(void* const* d_in, const int* in_sizes, int n_in,
                              void* d_out, int out_size)
{
    const float* x1     = (const float*)d_in[0];
    const float* w_gate = (const float*)d_in[1];
    const float* b_gate = (const float*)d_in[2];
    const float* wga    = (const float*)d_in[3];
    const float* wgb    = (const float*)d_in[4];
    const float* w_up   = (const float*)d_in[5];
    const float* b_up   = (const float*)d_in[6];
    const float* wua    = (const float*)d_in[7];
    const float* wub    = (const float*)d_in[8];
    const float* w_down = (const float*)d_in[9];
    const float* b_down = (const float*)d_in[10];
    const float* wda    = (const float*)d_in[11];
    const float* wdb    = (const float*)d_in[12];
    float* out = (float*)d_out;

#define SYM(p, s) void* p; cudaGetSymbolAddress(&p, s)
    SYM(x1h, g_x1h); SYM(x1l, g_x1l); SYM(x3h, g_x3h); SYM(x3l, g_x3l);
    SYM(wgh, g_wgh); SYM(wgl, g_wgl); SYM(wuh, g_wuh); SYM(wul, g_wul);
    SYM(wdT, g_wdT);
    SYM(lgh, g_lgh); SYM(lgl, g_lgl); SYM(luh, g_luh); SYM(lul, g_lul);
    SYM(ldh, g_ldh); SYM(ldl, g_ldl);
    SYM(tgh, g_tgh); SYM(tgl, g_tgl); SYM(tuh, g_tuh); SYM(tul, g_tul);
    SYM(tdh, g_tdh); SYM(tdl, g_tdl);
    SYM(gaTh, g_gaTh); SYM(gaTl, g_gaTl); SYM(uaTh, g_uaTh); SYM(uaTl, g_uaTl);
    SYM(daTh, g_daTh); SYM(daTl, g_daTl);
    SYM(Tgf, g_Tgf); SYM(Tuf, g_Tuf); SYM(Tdf, g_Tdf);
#undef SYM
#define BF(p) ((__nv_bfloat16*)(p))
#define HF(p) ((__half*)(p))
#define F32(p) ((float*)(p))

    cudaFuncSetAttribute(gemm_gateup, cudaFuncAttributeMaxDynamicSharedMemorySize, GEMM_SMEM);
    cudaFuncSetAttribute(gemm_down,   cudaFuncAttributeMaxDynamicSharedMemorySize, DOWN_SMEM);

    // conversions / transposes
    convert_hl<<<(int)((size_t)MTOK * DDIM / 1024), 256>>>(x1, (size_t)MTOK * DDIM, BF(x1h), BF(x1l));
    transpose_hl<<<dim3(FDIM / 32, DDIM / 32), dim3(32, 8)>>>(w_gate, DDIM, FDIM, BF(wgh), BF(wgl));
    transpose_hl<<<dim3(FDIM / 32, DDIM / 32), dim3(32, 8)>>>(w_up,   DDIM, FDIM, BF(wuh), BF(wul));
    transpose_f16<<<dim3(DDIM / 32, FDIM / 32), dim3(32, 8)>>>(w_down, FDIM, DDIM, HF(wdT));
    lb_transpose<<<FDIM / 256, 256>>>(wgb, FDIM, BF(lgh), BF(lgl));
    lb_transpose<<<FDIM / 256, 256>>>(wub, FDIM, BF(luh), BF(lul));
    lb_transpose_f16<<<DDIM / 256, 256>>>(wdb, DDIM, HF(ldh), HF(ldl));
    at_transpose<<<DDIM / 256, 256>>>(wga, DDIM, BF(gaTh), BF(gaTl));
    at_transpose<<<DDIM / 256, 256>>>(wua, DDIM, BF(uaTh), BF(uaTl));
    at_transpose_f16<<<FDIM / 256, 256>>>(wda, FDIM, HF(daTh), HF(daTl));
    zero_t<<<(MTOK * RR) / 256, 256>>>(F32(Tgf), F32(Tuf), F32(Tdf));

    // LoRA-A gate + up via skinny tensor GEMM (bf16)
    lora_gemm<false><<<dim3(2, MTOK / 128), 256>>>(x1h, x1l, gaTh, gaTl, F32(Tgf), DDIM, DDIM / 2);
    lora_gemm<false><<<dim3(2, MTOK / 128), 256>>>(x1h, x1l, uaTh, uaTl, F32(Tuf), DDIM, DDIM / 2);
    convert_hl<<<(MTOK * RR) / 1024, 256>>>(F32(Tgf), MTOK * RR, BF(tgh), BF(tgl));
    convert_hl<<<(MTOK * RR) / 1024, 256>>>(F32(Tuf), MTOK * RR, BF(tuh), BF(tul));

    // fused gate+up -> x3 fp16 hi/lo
    gemm_gateup<<<dim3(FDIM / 128, MTOK / 128), 256, GEMM_SMEM>>>(
        BF(x1h), BF(x1l),
        BF(wgh), BF(wgl), BF(wuh), BF(wul),
        BF(tgh), BF(tgl), BF(tuh), BF(tul),
        BF(lgh), BF(lgl), BF(luh), BF(lul),
        b_gate, b_up,
        HF(x3h), HF(x3l), FDIM, DDIM);

    // LoRA-A down via skinny tensor GEMM (fp16)
    lora_gemm<true><<<dim3(4, MTOK / 128), 256>>>(x3h, x3l, daTh, daTl, F32(Tdf), FDIM, FDIM / 4);
    convert_hl_f16<<<(MTOK * RR) / 1024, 256>>>(F32(Tdf), MTOK * RR, HF(tdh), HF(tdl));

    // down GEMM (fp16 2-combo, N128 tile) -> out
    gemm_down<<<dim3(DDIM / 128, MTOK / 128), 256, DOWN_SMEM>>>(
        HF(x3h), HF(x3l), HF(wdT),
        HF(tdh), HF(tdl), HF(ldh), HF(ldl),
        b_down, out, DDIM, FDIM);
}

// round 14
// speedup vs baseline: 3.3466x; 1.2977x over previous
#include <cuda_runtime.h>
#include <cuda_bf16.h>
#include <cuda_fp16.h>
#include <cstdint>

#define MTOK 8192
#define DDIM 2048
#define FDIM 8192
#define RR   16

// ---------------- device scratch (allocation-free) ----------------
__device__ __align__(1024) __half g_x1h[(size_t)MTOK * DDIM];
__device__ __align__(1024) __half g_x1l[(size_t)MTOK * DDIM];
__device__ __align__(1024) __half g_x3h[(size_t)MTOK * FDIM];
__device__ __align__(1024) __half g_x3l[(size_t)MTOK * FDIM];
__device__ __align__(1024) __half g_wgT[(size_t)FDIM * DDIM];   // fp16 single limb
__device__ __align__(1024) __half g_wuT[(size_t)FDIM * DDIM];
__device__ __align__(1024) __half g_wdT[(size_t)DDIM * FDIM];
__device__ __align__(1024) __half g_lgh[FDIM * RR], g_lgl[FDIM * RR];
__device__ __align__(1024) __half g_luh[FDIM * RR], g_lul[FDIM * RR];
__device__ __align__(1024) __half g_ldh[DDIM * RR], g_ldl[DDIM * RR];
__device__ __align__(1024) __half g_tgh[MTOK * RR], g_tgl[MTOK * RR];
__device__ __align__(1024) __half g_tuh[MTOK * RR], g_tul[MTOK * RR];
__device__ __align__(1024) __half g_tdh[MTOK * RR], g_tdl[MTOK * RR];
__device__ __align__(1024) __half g_gaTh[RR * DDIM], g_gaTl[RR * DDIM];
__device__ __align__(1024) __half g_uaTh[RR * DDIM], g_uaTl[RR * DDIM];
__device__ __align__(1024) __half g_daTh[RR * FDIM], g_daTl[RR * FDIM];
__device__ __align__(1024) float g_Tgf[MTOK * RR], g_Tuf[MTOK * RR], g_Tdf[MTOK * RR];

// ---------------- PTX helpers ----------------
__device__ __forceinline__ uint32_t smem_u32(const void* p) {
    uint32_t a;
    asm("{ .reg .u64 t; cvta.to.shared.u64 t, %1; cvt.u32.u64 %0, t; }" : "=r"(a) : "l"(p));
    return a;
}
#define CPA(dst, src) \
    asm volatile("cp.async.cg.shared.global [%0], [%1], 16;\n" :: "r"(dst), "l"(src))
#define CPC() asm volatile("cp.async.commit_group;\n" ::: "memory")
#define CPW(n) asm volatile("cp.async.wait_group %0;\n" :: "n"(n) : "memory")
#define LDSM4(R, addr)                                                          \
    asm volatile("ldmatrix.sync.aligned.m8n8.x4.shared.b16 {%0,%1,%2,%3}, [%4];\n" \
        : "=r"((R)[0]), "=r"((R)[1]), "=r"((R)[2]), "=r"((R)[3]) : "r"(addr))
#define MMA16816H(D, A, B0, B1)                                                 \
    asm volatile("mma.sync.aligned.m16n8k16.row.col.f32.f16.f16.f32 "           \
        "{%0,%1,%2,%3}, {%4,%5,%6,%7}, {%8,%9}, {%0,%1,%2,%3};\n"               \
        : "+f"((D)[0]), "+f"((D)[1]), "+f"((D)[2]), "+f"((D)[3])                \
        : "r"((A)[0]), "r"((A)[1]), "r"((A)[2]), "r"((A)[3]), "r"(B0), "r"(B1))

#define ASTRIDE 40
// gate+up SMEM per stage: AH(10240) AL(10240) B0(10240) B1(10240) = 40960; 3 stages
#define GOFF_AH 0
#define GOFF_AL 10240
#define GOFF_B0 20480
#define GOFF_B1 30720
#define GSTG 40960
#define GATEUP_SMEM (3 * GSTG)
// down SMEM per stage: AH(10240) AL(10240) B(10240) = 30720; 3 stages
#define DOFF_AH 0
#define DOFF_AL 10240
#define DOFF_B  20480
#define DSTG 30720
#define DOWN_SMEM (3 * DSTG)

// ---------------- fp32 -> fp16 hi/lo ----------------
__global__ __launch_bounds__(256)
void convert_hl_f16(const float* __restrict__ s, size_t n,
                    __half* __restrict__ h, __half* __restrict__ l)
{
    size_t i = ((size_t)blockIdx.x * 256 + threadIdx.x) * 4;
    if (i >= n) return;
    float4 v = *reinterpret_cast<const float4*>(s + i);
    float vv[4] = {v.x, v.y, v.z, v.w};
    __half hb[4], lb[4];
#pragma unroll
    for (int q = 0; q < 4; q++) {
        hb[q] = __float2half_rn(vv[q]);
        lb[q] = __float2half_rn(vv[q] - __half2float(hb[q]));
    }
    *reinterpret_cast<uint2*>(h + i) = *reinterpret_cast<uint2*>(hb);
    *reinterpret_cast<uint2*>(l + i) = *reinterpret_cast<uint2*>(lb);
}

// ---------------- transpose fp32 [R,C] -> fp16 single [C,R] ----------------
__global__ __launch_bounds__(256)
void transpose_f16(const float* __restrict__ src, int R, int C,
                   __half* __restrict__ dh)
{
    __shared__ float t[32][33];
    int tx = threadIdx.x, ty = threadIdx.y;
    int x = blockIdx.x * 32 + tx, y0 = blockIdx.y * 32;
#pragma unroll
    for (int j = 0; j < 32; j += 8)
        t[ty + j][tx] = src[(size_t)(y0 + ty + j) * C + x];
    __syncthreads();
    int x2 = y0 + tx, y2 = blockIdx.x * 32;
#pragma unroll
    for (int j = 0; j < 32; j += 8)
        dh[(size_t)(y2 + ty + j) * R + x2] = __float2half_rn(t[tx][ty + j]);
}

// ---------------- Lb [16,N] -> [N,16] fp16 hi/lo ----------------
__global__ __launch_bounds__(256)
void lb_transpose_f16(const float* __restrict__ Lb, int N,
                      __half* __restrict__ dh, __half* __restrict__ dl)
{
    int n = blockIdx.x * 256 + threadIdx.x;
    if (n >= N) return;
#pragma unroll
    for (int r = 0; r < RR; r++) {
        float v = Lb[(size_t)r * N + n];
        __half h = __float2half_rn(v);
        dh[(size_t)n * RR + r] = h;
        dl[(size_t)n * RR + r] = __float2half_rn(v - __half2float(h));
    }
}

// ---------------- A [K,16] -> At [16,K] fp16 hi/lo ----------------
__global__ __launch_bounds__(256)
void at_transpose_f16(const float* __restrict__ A, int K,
                      __half* __restrict__ dh, __half* __restrict__ dl)
{
    int k = blockIdx.x * 256 + threadIdx.x;
    if (k >= K) return;
#pragma unroll
    for (int r = 0; r < RR; r++) {
        float v = A[(size_t)k * RR + r];
        __half h = __float2half_rn(v);
        dh[(size_t)r * K + k] = h;
        dl[(size_t)r * K + k] = __float2half_rn(v - __half2float(h));
    }
}

// ---------------- zero the three T accumulators ----------------
__global__ __launch_bounds__(256)
void zero_t(float* a, float* b, float* c)
{
    int i = blockIdx.x * 256 + threadIdx.x;
    if (i < MTOK * RR) { a[i] = 0.f; b[i] = 0.f; c[i] = 0.f; }
}

// ---------------- skinny fp16 tensor GEMM: T[M,16] += X[M,K] @ At[16,K]^T ----------------
#define LXS 48
#define LSTG 14336
__global__ __launch_bounds__(256)
void lora_gemm(const __half* __restrict__ Xh_, const __half* __restrict__ Xl_,
               const __half* __restrict__ Ath_, const __half* __restrict__ Atl_,
               float* __restrict__ T, int K, int kslice)
{
    const char* Xh = (const char*)Xh_;   const char* Xl = (const char*)Xl_;
    const char* Ath = (const char*)Ath_; const char* Atl = (const char*)Atl_;
    __shared__ __align__(128) char sm[3 * LSTG];
    const uint32_t sb = smem_u32(sm);
    const int tid = threadIdx.x, lane = tid & 31, w = tid >> 5;
    const int bm = blockIdx.y * 128;
    const int k0 = blockIdx.x * kslice;

    float acc[2][4];
#pragma unroll
    for (int a = 0; a < 2; a++)
#pragma unroll
        for (int b = 0; b < 4; b++) acc[a][b] = 0.f;

    auto load = [&](int st, int kk) {
        uint32_t s0 = sb + (uint32_t)st * LSTG;
#pragma unroll
        for (int j = 0; j < 2; j++) {
            int c = tid + j * 256;
            int row = c >> 2, pc = c & 1, limb = (c >> 1) & 1;
            const char* src = (limb ? Xl : Xh) + ((size_t)(bm + row) * K + kk) * 2 + pc * 16;
            CPA(s0 + (uint32_t)(limb * 6144 + row * LXS + pc * 16), src);
        }
        if (tid < 64) {
            int row = tid >> 2, pc = tid & 1, limb = (tid >> 1) & 1;
            const char* src = (limb ? Atl : Ath) + ((size_t)row * K + kk) * 2 + pc * 16;
            CPA(s0 + (uint32_t)(12288 + limb * 768 + row * LXS + pc * 16), src);
        }
    };

    const int iters = kslice / 16;
    load(0, k0); CPC();
    load(1, k0 + 16); CPC();

    for (int it = 0; it < iters; it++) {
        if (it + 1 < iters) { CPW(1); } else { CPW(0); }
        __syncthreads();
        if (it + 2 < iters) { load((it + 2) % 3, k0 + (it + 2) * 16); CPC(); }
        uint32_t s0 = sb + (uint32_t)(it % 3) * LSTG;
        uint32_t ah[4], al[4], bh[4], bl[4];
        uint32_t xoff = (uint32_t)((w * 16 + (lane & 15)) * LXS + (lane >> 4) * 16);
        uint32_t boff = (uint32_t)(((lane & 15)) * LXS + (lane >> 4) * 16);
        LDSM4(ah, s0 + xoff);
        LDSM4(al, s0 + 6144 + xoff);
        LDSM4(bh, s0 + 12288 + boff);
        LDSM4(bl, s0 + 12288 + 768 + boff);
#pragma unroll
        for (int ni = 0; ni < 2; ni++) {
            MMA16816H(acc[ni], ah, bh[ni], bh[ni + 2]);
            MMA16816H(acc[ni], ah, bl[ni], bl[ni + 2]);
            MMA16816H(acc[ni], al, bh[ni], bh[ni + 2]);
        }
    }

#pragma unroll
    for (int ni = 0; ni < 2; ni++)
#pragma unroll
        for (int h2 = 0; h2 < 2; h2++) {
            int row = bm + w * 16 + (lane >> 2) + h2 * 8;
            int col = ni * 8 + (lane & 3) * 2;
            atomicAdd(&T[(size_t)row * RR + col],     acc[ni][h2 * 2 + 0]);
            atomicAdd(&T[(size_t)row * RR + col + 1], acc[ni][h2 * 2 + 1]);
        }
}

// ---------------- fused gate+up GEMM: fp16 2-combo dual-output ----------------
// A = x1 fp16 h/l; B0 = w_gate fp16 single; B1 = w_up fp16 single.
// y_g = A@B0 + bias0 + T0@L0^T ; y_u = A@B1 + bias1 + T1@L1^T
// x3 = relu(y_g) * y_u -> fp16 h/l
__global__ __launch_bounds__(256, 1)
void gemm_gateup(const __half* __restrict__ Ah, const __half* __restrict__ Al,
                 const __half* __restrict__ B0, const __half* __restrict__ B1,
                 const __half* __restrict__ T0h, const __half* __restrict__ T0l,
                 const __half* __restrict__ T1h, const __half* __restrict__ T1l,
                 const __half* __restrict__ L0h, const __half* __restrict__ L0l,
                 const __half* __restrict__ L1h, const __half* __restrict__ L1l,
                 const float* __restrict__ bias0, const float* __restrict__ bias1,
                 __half* __restrict__ Xh, __half* __restrict__ Xl,
                 int N, int K)
{
    extern __shared__ char dsm[];
    const uint32_t sb = smem_u32(dsm);
    const int tid = threadIdx.x, lane = tid & 31, wid = tid >> 5;
    const int wm = wid >> 2, wn = wid & 3;           // 2 x 4 warps; warp tile 64m x 32n
    const int bm = blockIdx.y * 128, bn = blockIdx.x * 128;

    float acc[2][4][4][4];
#pragma unroll
    for (int o = 0; o < 2; o++)
#pragma unroll
        for (int a = 0; a < 4; a++)
#pragma unroll
            for (int b = 0; b < 4; b++)
#pragma unroll
                for (int c = 0; c < 4; c++) acc[o][a][b][c] = 0.f;

    auto load_stage = [&](int st, int k0) {
        uint32_t s0 = sb + (uint32_t)st * GSTG;
#pragma unroll
        for (int j = 0; j < 4; j++) {                 // A h/l: 1024 chunks of 16B
            int c = tid + j * 256;
            int limb = c >> 9, idx = c & 511;
            int row = idx >> 2;
            const __half* src = (limb ? Al : Ah) + (size_t)(bm + row) * K + k0 + (idx & 3) * 8;
            CPA(s0 + (uint32_t)(limb * 10240 + row * ASTRIDE * 2 + (idx & 3) * 16), src);
        }
#pragma unroll
        for (int j = 0; j < 4; j++) {                 // B0 + B1: 1024 chunks
            int c = tid + j * 256;
            int wsel = c >> 9, idx = c & 511;
            int row = idx >> 2;
            const __half* src = (wsel ? B1 : B0) + (size_t)(bn + row) * K + k0 + (idx & 3) * 8;
            CPA(s0 + GOFF_B0 + (uint32_t)(wsel * 10240 + row * ASTRIDE * 2 + (idx & 3) * 16), src);
        }
    };

    const int ar = lane & 15;
    const int koff = (lane >> 4) * 8;

    auto compute_ks = [&](uint32_t s0, int kbase) {
        const int kc = kbase + koff;
        uint32_t ah[4][4], al[4][4], b0[2][4], b1[2][4];
#pragma unroll
        for (int mi = 0; mi < 4; mi++)
            LDSM4(ah[mi], s0 + GOFF_AH + (uint32_t)((wm * 64 + mi * 16 + ar) * ASTRIDE + kc) * 2);
#pragma unroll
        for (int nb = 0; nb < 2; nb++) {
            LDSM4(b0[nb], s0 + GOFF_B0 + (uint32_t)((wn * 32 + nb * 16 + ar) * ASTRIDE + kc) * 2);
            LDSM4(b1[nb], s0 + GOFF_B1 + (uint32_t)((wn * 32 + nb * 16 + ar) * ASTRIDE + kc) * 2);
        }
#pragma unroll
        for (int mi = 0; mi < 4; mi++)
#pragma unroll
            for (int ni = 0; ni < 4; ni++) {
                MMA16816H(acc[0][mi][ni], ah[mi], b0[ni >> 1][ni & 1], b0[ni >> 1][(ni & 1) + 2]);
                MMA16816H(acc[1][mi][ni], ah[mi], b1[ni >> 1][ni & 1], b1[ni >> 1][(ni & 1) + 2]);
            }
#pragma unroll
        for (int mi = 0; mi < 4; mi++)
            LDSM4(al[mi], s0 + GOFF_AL + (uint32_t)((wm * 64 + mi * 16 + ar) * ASTRIDE + kc) * 2);
#pragma unroll
        for (int mi = 0; mi < 4; mi++)
#pragma unroll
            for (int ni = 0; ni < 4; ni++) {
                MMA16816H(acc[0][mi][ni], al[mi], b0[ni >> 1][ni & 1], b0[ni >> 1][(ni & 1) + 2]);
                MMA16816H(acc[1][mi][ni], al[mi], b1[ni >> 1][ni & 1], b1[ni >> 1][(ni & 1) + 2]);
            }
    };

    const int KC = K / 32;
    load_stage(0, 0); CPC();
    load_stage(1, 32); CPC();

    for (int c = 0; c < KC; c++) {
        if (c + 1 < KC) { CPW(1); } else { CPW(0); }
        __syncthreads();
        if (c + 2 < KC) { load_stage((c + 2) % 3, (c + 2) * 32); CPC(); }
        uint32_t s0 = sb + (uint32_t)(c % 3) * GSTG;
        compute_ks(s0, 0);
        compute_ks(s0, 16);
    }

    // ---- LoRA k16: T_o h/l in stage-o A regions; L_o h in stage-o B0, L_o l in stage-o B1 ----
    __syncthreads();
    {
        int row = tid >> 1, hf = tid & 1;
        uint32_t d = (uint32_t)(row * ASTRIDE * 2 + hf * 16);
        *(uint4*)(dsm + GOFF_AH + d) = *(const uint4*)(T0h + (size_t)(bm + row) * RR + hf * 8);
        *(uint4*)(dsm + GOFF_AL + d) = *(const uint4*)(T0l + (size_t)(bm + row) * RR + hf * 8);
        *(uint4*)(dsm + GSTG + GOFF_AH + d) = *(const uint4*)(T1h + (size_t)(bm + row) * RR + hf * 8);
        *(uint4*)(dsm + GSTG + GOFF_AL + d) = *(const uint4*)(T1l + (size_t)(bm + row) * RR + hf * 8);
        *(uint4*)(dsm + GOFF_B0 + d) = *(const uint4*)(L0h + (size_t)(bn + row) * RR + hf * 8);
        *(uint4*)(dsm + GOFF_B1 + d) = *(const uint4*)(L0l + (size_t)(bn + row) * RR + hf * 8);
        *(uint4*)(dsm + GSTG + GOFF_B0 + d) = *(const uint4*)(L1h + (size_t)(bn + row) * RR + hf * 8);
        *(uint4*)(dsm + GSTG + GOFF_B1 + d) = *(const uint4*)(L1l + (size_t)(bn + row) * RR + hf * 8);
        __syncthreads();
#pragma unroll
        for (int o = 0; o < 2; o++) {
            uint32_t sS = sb + (uint32_t)o * GSTG;
            uint32_t ah[4][4], al[4][4], bh[2][4], bl[2][4];
#pragma unroll
            for (int mi = 0; mi < 4; mi++) {
                LDSM4(ah[mi], sS + GOFF_AH + (uint32_t)((wm * 64 + mi * 16 + ar) * ASTRIDE + koff) * 2);
                LDSM4(al[mi], sS + GOFF_AL + (uint32_t)((wm * 64 + mi * 16 + ar) * ASTRIDE + koff) * 2);
            }
#pragma unroll
            for (int nb = 0; nb < 2; nb++) {
                LDSM4(bh[nb], sS + GOFF_B0 + (uint32_t)((wn * 32 + nb * 16 + ar) * ASTRIDE + koff) * 2);
                LDSM4(bl[nb], sS + GOFF_B1 + (uint32_t)((wn * 32 + nb * 16 + ar) * ASTRIDE + koff) * 2);
            }
#pragma unroll
            for (int mi = 0; mi < 4; mi++)
#pragma unroll
                for (int ni = 0; ni < 4; ni++) {
                    MMA16816H(acc[o][mi][ni], ah[mi], bh[ni >> 1][ni & 1], bh[ni >> 1][(ni & 1) + 2]);
                    MMA16816H(acc[o][mi][ni], ah[mi], bl[ni >> 1][ni & 1], bl[ni >> 1][(ni & 1) + 2]);
                    MMA16816H(acc[o][mi][ni], al[mi], bh[ni >> 1][ni & 1], bh[ni >> 1][(ni & 1) + 2]);
                }
        }
    }

    // ---- epilogue: x3 = relu(y_g)*y_u as fp16 hi/lo ----
#pragma unroll
    for (int mi = 0; mi < 4; mi++) {
        int r0 = bm + wm * 64 + mi * 16 + (lane >> 2);
#pragma unroll
        for (int ni = 0; ni < 4; ni++) {
            int cl = wn * 32 + ni * 8 + (lane & 3) * 2;
            float bg0 = bias0[bn + cl], bg1 = bias0[bn + cl + 1];
            float bu0 = bias1[bn + cl], bu1 = bias1[bn + cl + 1];
#pragma unroll
            for (int h2 = 0; h2 < 2; h2++) {
                int r = r0 + h2 * 8;
                float g0 = acc[0][mi][ni][h2 * 2 + 0] + bg0;
                float g1 = acc[0][mi][ni][h2 * 2 + 1] + bg1;
                float u0 = acc[1][mi][ni][h2 * 2 + 0] + bu0;
                float u1 = acc[1][mi][ni][h2 * 2 + 1] + bu1;
                float v0 = fmaxf(g0, 0.f) * u0;
                float v1 = fmaxf(g1, 0.f) * u1;
                __half h0 = __float2half_rn(v0);
                __half h1 = __float2half_rn(v1);
                __half l0 = __float2half_rn(v0 - __half2float(h0));
                __half l1 = __float2half_rn(v1 - __half2float(h1));
                size_t off = (size_t)r * N + bn + cl;
                *(__half2*)(Xh + off) = __halves2half2(h0, h1);
                *(__half2*)(Xl + off) = __halves2half2(l0, l1);
            }
        }
    }
}

// ---------------- down GEMM: fp16 2-combo (verbatim R13) ----------------
__global__ __launch_bounds__(256, 1)
void gemm_down(const __half* __restrict__ Ah, const __half* __restrict__ Al,
               const __half* __restrict__ B,
               const __half* __restrict__ Th, const __half* __restrict__ Tl,
               const __half* __restrict__ Lh, const __half* __restrict__ Ll,
               const float* __restrict__ bias,
               float* __restrict__ C,
               int N, int K)
{
    extern __shared__ char dsm[];
    const uint32_t sb = smem_u32(dsm);
    const int tid = threadIdx.x, lane = tid & 31, wid = tid >> 5;
    const int wm = wid >> 2, wn = wid & 3;
    const int bm = blockIdx.y * 128, bn = blockIdx.x * 128;

    float acc[4][4][4];
#pragma unroll
    for (int a = 0; a < 4; a++)
#pragma unroll
        for (int b = 0; b < 4; b++)
#pragma unroll
            for (int c = 0; c < 4; c++) acc[a][b][c] = 0.f;

    auto load_stage = [&](int st, int k0) {
        uint32_t s0 = sb + (uint32_t)st * DSTG;
#pragma unroll
        for (int j = 0; j < 4; j++) {
            int c = tid + j * 256;
            int limb = c >> 9, idx = c & 511;
            int row = idx >> 2;
            const __half* src = (limb ? Al : Ah) + (size_t)(bm + row) * K + k0 + (idx & 3) * 8;
            CPA(s0 + (uint32_t)(limb * 10240 + row * ASTRIDE * 2 + (idx & 3) * 16), src);
        }
#pragma unroll
        for (int j = 0; j < 2; j++) {
            int c = tid + j * 256;
            int row = c >> 2;
            CPA(s0 + DOFF_B + (uint32_t)(row * ASTRIDE * 2 + (c & 3) * 16),
                B + (size_t)(bn + row) * K + k0 + (c & 3) * 8);
        }
    };

    const int ar = lane & 15;
    const int koff = (lane >> 4) * 8;

    auto compute_ks = [&](uint32_t s0, int kbase) {
        const int kc = kbase + koff;
        uint32_t ah[4][4], al[4][4], bb[2][4];
#pragma unroll
        for (int mi = 0; mi < 4; mi++)
            LDSM4(ah[mi], s0 + DOFF_AH + (uint32_t)((wm * 64 + mi * 16 + ar) * ASTRIDE + kc) * 2);
#pragma unroll
        for (int nb = 0; nb < 2; nb++)
            LDSM4(bb[nb], s0 + DOFF_B + (uint32_t)((wn * 32 + nb * 16 + ar) * ASTRIDE + kc) * 2);
#pragma unroll
        for (int mi = 0; mi < 4; mi++)
#pragma unroll
            for (int ni = 0; ni < 4; ni++)
                MMA16816H(acc[mi][ni], ah[mi], bb[ni >> 1][ni & 1], bb[ni >> 1][(ni & 1) + 2]);
#pragma unroll
        for (int mi = 0; mi < 4; mi++)
            LDSM4(al[mi], s0 + DOFF_AL + (uint32_t)((wm * 64 + mi * 16 + ar) * ASTRIDE + kc) * 2);
#pragma unroll
        for (int mi = 0; mi < 4; mi++)
#pragma unroll
            for (int ni = 0; ni < 4; ni++)
                MMA16816H(acc[mi][ni], al[mi], bb[ni >> 1][ni & 1], bb[ni >> 1][(ni & 1) + 2]);
    };

    const int KC = K / 32;
    load_stage(0, 0); CPC();
    load_stage(1, 32); CPC();

    for (int c = 0; c < KC; c++) {
        if (c + 1 < KC) { CPW(1); } else { CPW(0); }
        __syncthreads();
        if (c + 2 < KC) { load_stage((c + 2) % 3, (c + 2) * 32); CPC(); }
        uint32_t s0 = sb + (uint32_t)(c % 3) * DSTG;
        compute_ks(s0, 0);
        compute_ks(s0, 16);
    }

    // ---- LoRA k16 chunk ----
    __syncthreads();
    {
        int row = tid >> 1, hf = tid & 1;
        uint32_t d = (uint32_t)(row * ASTRIDE * 2 + hf * 16);
        *(uint4*)(dsm + DOFF_AH + d) = *(const uint4*)(Th + (size_t)(bm + row) * RR + hf * 8);
        *(uint4*)(dsm + DOFF_AL + d) = *(const uint4*)(Tl + (size_t)(bm + row) * RR + hf * 8);
        *(uint4*)(dsm + DOFF_B + d)        = *(const uint4*)(Lh + (size_t)(bn + row) * RR + hf * 8);
        *(uint4*)(dsm + DSTG + DOFF_B + d) = *(const uint4*)(Ll + (size_t)(bn + row) * RR + hf * 8);
        __syncthreads();

        uint32_t ah[4][4], al[4][4], bh[2][4], bl[2][4];
#pragma unroll
        for (int mi = 0; mi < 4; mi++) {
            LDSM4(ah[mi], sb + DOFF_AH + (uint32_t)((wm * 64 + mi * 16 + ar) * ASTRIDE + koff) * 2);
            LDSM4(al[mi], sb + DOFF_AL + (uint32_t)((wm * 64 + mi * 16 + ar) * ASTRIDE + koff) * 2);
        }
#pragma unroll
        for (int nb = 0; nb < 2; nb++) {
            LDSM4(bh[nb], sb + DOFF_B + (uint32_t)((wn * 32 + nb * 16 + ar) * ASTRIDE + koff) * 2);
            LDSM4(bl[nb], sb + DSTG + DOFF_B + (uint32_t)((wn * 32 + nb * 16 + ar) * ASTRIDE + koff) * 2);
        }
#pragma unroll
        for (int mi = 0; mi < 4; mi++)
#pragma unroll
            for (int ni = 0; ni < 4; ni++) {
                MMA16816H(acc[mi][ni], ah[mi], bh[ni >> 1][ni & 1], bh[ni >> 1][(ni & 1) + 2]);
                MMA16816H(acc[mi][ni], ah[mi], bl[ni >> 1][ni & 1], bl[ni >> 1][(ni & 1) + 2]);
                MMA16816H(acc[mi][ni], al[mi], bh[ni >> 1][ni & 1], bh[ni >> 1][(ni & 1) + 2]);
            }
    }

    // ---- epilogue ----
#pragma unroll
    for (int mi = 0; mi < 4; mi++) {
        int r0 = bm + wm * 64 + mi * 16 + (lane >> 2);
#pragma unroll
        for (int ni = 0; ni < 4; ni++) {
            int cl = wn * 32 + ni * 8 + (lane & 3) * 2;
            float b0 = bias[bn + cl], b1 = bias[bn + cl + 1];
#pragma unroll
            for (int h2 = 0; h2 < 2; h2++) {
                int r = r0 + h2 * 8;
                size_t off = (size_t)r * N + bn + cl;
                *(float2*)(C + off) = make_float2(acc[mi][ni][h2 * 2 + 0] + b0,
                                                  acc[mi][ni][h2 * 2 + 1] + b1);
            }
        }
    }
}

// ---------------- launcher ----------------
extern "C" void kernel_launch(void* const* d_in, const int* in_sizes, int n_in,
                              void* d_out, int out_size)
{
    const float* x1     = (const float*)d_in[0];
    const float* w_gate = (const float*)d_in[1];
    const float* b_gate = (const float*)d_in[2];
    const float* wga    = (const float*)d_in[3];
    const float* wgb    = (const float*)d_in[4];
    const float* w_up   = (const float*)d_in[5];
    const float* b_up   = (const float*)d_in[6];
    const float* wua    = (const float*)d_in[7];
    const float* wub    = (const float*)d_in[8];
    const float* w_down = (const float*)d_in[9];
    const float* b_down = (const float*)d_in[10];
    const float* wda    = (const float*)d_in[11];
    const float* wdb    = (const float*)d_in[12];
    float* out = (float*)d_out;

#define SYM(p, s) void* p; cudaGetSymbolAddress(&p, s)
    SYM(x1h, g_x1h); SYM(x1l, g_x1l); SYM(x3h, g_x3h); SYM(x3l, g_x3l);
    SYM(wgT, g_wgT); SYM(wuT, g_wuT); SYM(wdT, g_wdT);
    SYM(lgh, g_lgh); SYM(lgl, g_lgl); SYM(luh, g_luh); SYM(lul, g_lul);
    SYM(ldh, g_ldh); SYM(ldl, g_ldl);
    SYM(tgh, g_tgh); SYM(tgl, g_tgl); SYM(tuh, g_tuh); SYM(tul, g_tul);
    SYM(tdh, g_tdh); SYM(tdl, g_tdl);
    SYM(gaTh, g_gaTh); SYM(gaTl, g_gaTl); SYM(uaTh, g_uaTh); SYM(uaTl, g_uaTl);
    SYM(daTh, g_daTh); SYM(daTl, g_daTl);
    SYM(Tgf, g_Tgf); SYM(Tuf, g_Tuf); SYM(Tdf, g_Tdf);
#undef SYM
#define HF(p) ((__half*)(p))
#define F32(p) ((float*)(p))

    cudaFuncSetAttribute(gemm_gateup, cudaFuncAttributeMaxDynamicSharedMemorySize, GATEUP_SMEM);
    cudaFuncSetAttribute(gemm_down,   cudaFuncAttributeMaxDynamicSharedMemorySize, DOWN_SMEM);

    // conversions / transposes
    convert_hl_f16<<<(int)((size_t)MTOK * DDIM / 1024), 256>>>(x1, (size_t)MTOK * DDIM, HF(x1h), HF(x1l));
    transpose_f16<<<dim3(FDIM / 32, DDIM / 32), dim3(32, 8)>>>(w_gate, DDIM, FDIM, HF(wgT));
    transpose_f16<<<dim3(FDIM / 32, DDIM / 32), dim3(32, 8)>>>(w_up,   DDIM, FDIM, HF(wuT));
    transpose_f16<<<dim3(DDIM / 32, FDIM / 32), dim3(32, 8)>>>(w_down, FDIM, DDIM, HF(wdT));
    lb_transpose_f16<<<FDIM / 256, 256>>>(wgb, FDIM, HF(lgh), HF(lgl));
    lb_transpose_f16<<<FDIM / 256, 256>>>(wub, FDIM, HF(luh), HF(lul));
    lb_transpose_f16<<<DDIM / 256, 256>>>(wdb, DDIM, HF(ldh), HF(ldl));
    at_transpose_f16<<<DDIM / 256, 256>>>(wga, DDIM, HF(gaTh), HF(gaTl));
    at_transpose_f16<<<DDIM / 256, 256>>>(wua, DDIM, HF(uaTh), HF(uaTl));
    at_transpose_f16<<<FDIM / 256, 256>>>(wda, FDIM, HF(daTh), HF(daTl));
    zero_t<<<(MTOK * RR) / 256, 256>>>(F32(Tgf), F32(Tuf), F32(Tdf));

    // LoRA-A gate + up via skinny fp16 tensor GEMM
    lora_gemm<<<dim3(2, MTOK / 128), 256>>>(HF(x1h), HF(x1l), HF(gaTh), HF(gaTl),
                                            F32(Tgf), DDIM, DDIM / 2);
    lora_gemm<<<dim3(2, MTOK / 128), 256>>>(HF(x1h), HF(x1l), HF(uaTh), HF(uaTl),
                                            F32(Tuf), DDIM, DDIM / 2);
    convert_hl_f16<<<(MTOK * RR) / 1024, 256>>>(F32(Tgf), MTOK * RR, HF(tgh), HF(tgl));
    convert_hl_f16<<<(MTOK * RR) / 1024, 256>>>(F32(Tuf), MTOK * RR, HF(tuh), HF(tul));

    // fused gate+up (fp16 2-combo dual-output) -> x3 fp16 hi/lo
    gemm_gateup<<<dim3(FDIM / 128, MTOK / 128), 256, GATEUP_SMEM>>>(
        HF(x1h), HF(x1l), HF(wgT), HF(wuT),
        HF(tgh), HF(tgl), HF(tuh), HF(tul),
        HF(lgh), HF(lgl), HF(luh), HF(lul),
        b_gate, b_up,
        HF(x3h), HF(x3l), FDIM, DDIM);

    // LoRA-A down via skinny fp16 tensor GEMM
    lora_gemm<<<dim3(4, MTOK / 128), 256>>>(HF(x3h), HF(x3l), HF(daTh), HF(daTl),
                                            F32(Tdf), FDIM, FDIM / 4);
    convert_hl_f16<<<(MTOK * RR) / 1024, 256>>>(F32(Tdf), MTOK * RR, HF(tdh), HF(tdl));

    // down GEMM (fp16 2-combo) -> out
    gemm_down<<<dim3(DDIM / 128, MTOK / 128), 256, DOWN_SMEM>>>(
        HF(x3h), HF(x3l), HF(wdT),
        HF(tdh), HF(tdl), HF(ldh), HF(ldl),
        b_down, out, DDIM, FDIM);
}

// round 17
// speedup vs baseline: 5.8335x; 1.7431x over previous
#include <cuda_runtime.h>
#include <cuda_fp16.h>
#include <cstdint>

#define MTOK 8192
#define DDIM 2048
#define FDIM 8192
#define RR   16

// ---------------- device scratch (allocation-free) ----------------
__device__ __align__(1024) __half g_x1q[(size_t)MTOK * DDIM];   // single fp16
__device__ __align__(1024) __half g_x3q[(size_t)MTOK * FDIM];   // single fp16
__device__ __align__(1024) __half g_wgT[(size_t)FDIM * DDIM];
__device__ __align__(1024) __half g_wuT[(size_t)FDIM * DDIM];
__device__ __align__(1024) __half g_wdT[(size_t)DDIM * FDIM];
__device__ __align__(1024) __half g_lgh[FDIM * RR], g_lgl[FDIM * RR];
__device__ __align__(1024) __half g_luh[FDIM * RR], g_lul[FDIM * RR];
__device__ __align__(1024) __half g_ldh[DDIM * RR], g_ldl[DDIM * RR];
__device__ __align__(1024) __half g_tgh[MTOK * RR], g_tgl[MTOK * RR];
__device__ __align__(1024) __half g_tuh[MTOK * RR], g_tul[MTOK * RR];
__device__ __align__(1024) __half g_tdh[MTOK * RR], g_tdl[MTOK * RR];
__device__ __align__(1024) __half g_gaTh[RR * DDIM], g_gaTl[RR * DDIM];
__device__ __align__(1024) __half g_uaTh[RR * DDIM], g_uaTl[RR * DDIM];
__device__ __align__(1024) __half g_daTh[RR * FDIM], g_daTl[RR * FDIM];
__device__ __align__(1024) float g_Tgf[MTOK * RR], g_Tuf[MTOK * RR], g_Tdf[MTOK * RR];

// ---------------- PTX helpers ----------------
__device__ __forceinline__ uint32_t smem_u32(const void* p) {
    uint32_t a;
    asm("{ .reg .u64 t; cvta.to.shared.u64 t, %1; cvt.u32.u64 %0, t; }" : "=r"(a) : "l"(p));
    return a;
}
#define CPA(dst, src) \
    asm volatile("cp.async.cg.shared.global [%0], [%1], 16;\n" :: "r"(dst), "l"(src))
#define CPC() asm volatile("cp.async.commit_group;\n" ::: "memory")
#define CPW(n) asm volatile("cp.async.wait_group %0;\n" :: "n"(n) : "memory")
#define LDSM4(R, addr)                                                          \
    asm volatile("ldmatrix.sync.aligned.m8n8.x4.shared.b16 {%0,%1,%2,%3}, [%4];\n" \
        : "=r"((R)[0]), "=r"((R)[1]), "=r"((R)[2]), "=r"((R)[3]) : "r"(addr))
#define MMA16816H(D, A, B0, B1)                                                 \
    asm volatile("mma.sync.aligned.m16n8k16.row.col.f32.f16.f16.f32 "           \
        "{%0,%1,%2,%3}, {%4,%5,%6,%7}, {%8,%9}, {%0,%1,%2,%3};\n"               \
        : "+f"((D)[0]), "+f"((D)[1]), "+f"((D)[2]), "+f"((D)[3])                \
        : "r"((A)[0]), "r"((A)[1]), "r"((A)[2]), "r"((A)[3]), "r"(B0), "r"(B1))

#define ASTRIDE 40        // 80 bytes/row (64B data + pad)
// gate+up SMEM per stage: A(10240) B0(10240) B1(10240) = 30720; 3 stages (9 regions)
#define GSTG 30720
#define GATEUP_SMEM (3 * GSTG)
// down SMEM per stage: A(10240) B(10240) = 20480; 3 stages (6 regions)
#define DSTG 20480
#define DOWN_SMEM (3 * DSTG)

// ---------------- fp32 -> fp16 single ----------------
__global__ __launch_bounds__(256)
void convert_f16(const float* __restrict__ s, size_t n, __half* __restrict__ h)
{
    size_t i = ((size_t)blockIdx.x * 256 + threadIdx.x) * 4;
    if (i >= n) return;
    float4 v = *reinterpret_cast<const float4*>(s + i);
    __half hb[4] = {__float2half_rn(v.x), __float2half_rn(v.y),
                    __float2half_rn(v.z), __float2half_rn(v.w)};
    *reinterpret_cast<uint2*>(h + i) = *reinterpret_cast<uint2*>(hb);
}

// ---------------- fp32 -> fp16 hi/lo (for LoRA T) ----------------
__global__ __launch_bounds__(256)
void convert_hl_f16(const float* __restrict__ s, size_t n,
                    __half* __restrict__ h, __half* __restrict__ l)
{
    size_t i = ((size_t)blockIdx.x * 256 + threadIdx.x) * 4;
    if (i >= n) return;
    float4 v = *reinterpret_cast<const float4*>(s + i);
    float vv[4] = {v.x, v.y, v.z, v.w};
    __half hb[4], lb[4];
#pragma unroll
    for (int q = 0; q < 4; q++) {
        hb[q] = __float2half_rn(vv[q]);
        lb[q] = __float2half_rn(vv[q] - __half2float(hb[q]));
    }
    *reinterpret_cast<uint2*>(h + i) = *reinterpret_cast<uint2*>(hb);
    *reinterpret_cast<uint2*>(l + i) = *reinterpret_cast<uint2*>(lb);
}

// ---------------- transpose fp32 [R,C] -> fp16 single [C,R] ----------------
__global__ __launch_bounds__(256)
void transpose_f16(const float* __restrict__ src, int R, int C,
                   __half* __restrict__ dh)
{
    __shared__ float t[32][33];
    int tx = threadIdx.x, ty = threadIdx.y;
    int x = blockIdx.x * 32 + tx, y0 = blockIdx.y * 32;
#pragma unroll
    for (int j = 0; j < 32; j += 8)
        t[ty + j][tx] = src[(size_t)(y0 + ty + j) * C + x];
    __syncthreads();
    int x2 = y0 + tx, y2 = blockIdx.x * 32;
#pragma unroll
    for (int j = 0; j < 32; j += 8)
        dh[(size_t)(y2 + ty + j) * R + x2] = __float2half_rn(t[tx][ty + j]);
}

// ---------------- Lb [16,N] -> [N,16] fp16 hi/lo ----------------
__global__ __launch_bounds__(256)
void lb_transpose_f16(const float* __restrict__ Lb, int N,
                      __half* __restrict__ dh, __half* __restrict__ dl)
{
    int n = blockIdx.x * 256 + threadIdx.x;
    if (n >= N) return;
#pragma unroll
    for (int r = 0; r < RR; r++) {
        float v = Lb[(size_t)r * N + n];
        __half h = __float2half_rn(v);
        dh[(size_t)n * RR + r] = h;
        dl[(size_t)n * RR + r] = __float2half_rn(v - __half2float(h));
    }
}

// ---------------- A [K,16] -> At [16,K] fp16 hi/lo ----------------
__global__ __launch_bounds__(256)
void at_transpose_f16(const float* __restrict__ A, int K,
                      __half* __restrict__ dh, __half* __restrict__ dl)
{
    int k = blockIdx.x * 256 + threadIdx.x;
    if (k >= K) return;
#pragma unroll
    for (int r = 0; r < RR; r++) {
        float v = A[(size_t)k * RR + r];
        __half h = __float2half_rn(v);
        dh[(size_t)r * K + k] = h;
        dl[(size_t)r * K + k] = __float2half_rn(v - __half2float(h));
    }
}

// ---------------- zero the three T accumulators ----------------
__global__ __launch_bounds__(256)
void zero_t(float* a, float* b, float* c)
{
    int i = blockIdx.x * 256 + threadIdx.x;
    if (i < MTOK * RR) { a[i] = 0.f; b[i] = 0.f; c[i] = 0.f; }
}

// ---------------- skinny fp16 GEMM: T[M,16] += Xq[M,K] @ At[16,K]^T (At hi/lo) ----------------
#define LXS 48
#define LSTG 7680
__global__ __launch_bounds__(256)
void lora_gemm(const __half* __restrict__ Xq_,
               const __half* __restrict__ Ath_, const __half* __restrict__ Atl_,
               float* __restrict__ T, int K, int kslice)
{
    const char* Xq = (const char*)Xq_;
    const char* Ath = (const char*)Ath_; const char* Atl = (const char*)Atl_;
    __shared__ __align__(128) char sm[3 * LSTG];
    const uint32_t sb = smem_u32(sm);
    const int tid = threadIdx.x, lane = tid & 31, w = tid >> 5;
    const int bm = blockIdx.y * 128;
    const int k0 = blockIdx.x * kslice;

    float acc[2][4];
#pragma unroll
    for (int a = 0; a < 2; a++)
#pragma unroll
        for (int b = 0; b < 4; b++) acc[a][b] = 0.f;

    auto load = [&](int st, int kk) {
        uint32_t s0 = sb + (uint32_t)st * LSTG;
        {   // X: 128 rows x 32B = 256 chunks
            int row = tid >> 1, pc = tid & 1;
            const char* src = Xq + ((size_t)(bm + row) * K + kk) * 2 + pc * 16;
            CPA(s0 + (uint32_t)(row * LXS + pc * 16), src);
        }
        if (tid < 64) {  // At h/l: 16 rows x 32B x 2 limbs = 64 chunks
            int limb = tid >> 5, idx = tid & 31;
            int row = idx >> 1, pc = idx & 1;
            const char* src = (limb ? Atl : Ath) + ((size_t)row * K + kk) * 2 + pc * 16;
            CPA(s0 + (uint32_t)(6144 + limb * 768 + row * LXS + pc * 16), src);
        }
    };

    const int iters = kslice / 16;
    load(0, k0); CPC();
    load(1, k0 + 16); CPC();

    for (int it = 0; it < iters; it++) {
        if (it + 1 < iters) { CPW(1); } else { CPW(0); }
        __syncthreads();
        if (it + 2 < iters) { load((it + 2) % 3, k0 + (it + 2) * 16); CPC(); }
        uint32_t s0 = sb + (uint32_t)(it % 3) * LSTG;
        uint32_t ax[4], bh[4], bl[4];
        uint32_t xoff = (uint32_t)((w * 16 + (lane & 15)) * LXS + (lane >> 4) * 16);
        uint32_t boff = (uint32_t)((lane & 15) * LXS + (lane >> 4) * 16);
        LDSM4(ax, s0 + xoff);
        LDSM4(bh, s0 + 6144 + boff);
        LDSM4(bl, s0 + 6912 + boff);
#pragma unroll
        for (int ni = 0; ni < 2; ni++) {
            MMA16816H(acc[ni], ax, bh[ni], bh[ni + 2]);
            MMA16816H(acc[ni], ax, bl[ni], bl[ni + 2]);
        }
    }

#pragma unroll
    for (int ni = 0; ni < 2; ni++)
#pragma unroll
        for (int h2 = 0; h2 < 2; h2++) {
            int row = bm + w * 16 + (lane >> 2) + h2 * 8;
            int col = ni * 8 + (lane & 3) * 2;
            atomicAdd(&T[(size_t)row * RR + col],     acc[ni][h2 * 2 + 0]);
            atomicAdd(&T[(size_t)row * RR + col + 1], acc[ni][h2 * 2 + 1]);
        }
}

// ---------------- fused gate+up GEMM: fp16 1-combo dual-output ----------------
// A = x1 fp16 single; B0 = w_gate; B1 = w_up (both fp16 single).
// x3 = relu(A@B0 + bias0 + T0@L0^T) * (A@B1 + bias1 + T1@L1^T) -> fp16 single
__global__ __launch_bounds__(256, 1)
void gemm_gateup(const __half* __restrict__ A,
                 const __half* __restrict__ B0, const __half* __restrict__ B1,
                 const __half* __restrict__ T0h, const __half* __restrict__ T0l,
                 const __half* __restrict__ T1h, const __half* __restrict__ T1l,
                 const __half* __restrict__ L0h, const __half* __restrict__ L0l,
                 const __half* __restrict__ L1h, const __half* __restrict__ L1l,
                 const float* __restrict__ bias0, const float* __restrict__ bias1,
                 __half* __restrict__ X3,
                 int N, int K)
{
    extern __shared__ char dsm[];
    const uint32_t sb = smem_u32(dsm);
    const int tid = threadIdx.x, lane = tid & 31, wid = tid >> 5;
    const int wm = wid >> 2, wn = wid & 3;           // 2 x 4 warps; warp tile 64m x 32n
    const int bm = blockIdx.y * 128, bn = blockIdx.x * 128;

    float acc[2][4][4][4];
#pragma unroll
    for (int o = 0; o < 2; o++)
#pragma unroll
        for (int a = 0; a < 4; a++)
#pragma unroll
            for (int b = 0; b < 4; b++)
#pragma unroll
                for (int c = 0; c < 4; c++) acc[o][a][b][c] = 0.f;

    auto load_stage = [&](int st, int k0) {
        uint32_t s0 = sb + (uint32_t)st * GSTG;
#pragma unroll
        for (int j = 0; j < 2; j++) {                 // A: 512 chunks of 16B
            int c = tid + j * 256;
            int row = c >> 2;
            CPA(s0 + (uint32_t)(row * 80 + (c & 3) * 16),
                A + (size_t)(bm + row) * K + k0 + (c & 3) * 8);
        }
#pragma unroll
        for (int j = 0; j < 4; j++) {                 // B0 + B1: 1024 chunks
            int c = tid + j * 256;
            int wsel = c >> 9, idx = c & 511;
            int row = idx >> 2;
            const __half* src = (wsel ? B1 : B0) + (size_t)(bn + row) * K + k0 + (idx & 3) * 8;
            CPA(s0 + 10240 + (uint32_t)(wsel * 10240 + row * 80 + (idx & 3) * 16), src);
        }
    };

    const int ar = lane & 15;
    const int koff = (lane >> 4) * 8;

    auto compute_ks = [&](uint32_t s0, int kbase) {
        const int kc = kbase + koff;
        uint32_t ah[4][4], b0[2][4], b1[2][4];
#pragma unroll
        for (int mi = 0; mi < 4; mi++)
            LDSM4(ah[mi], s0 + (uint32_t)((wm * 64 + mi * 16 + ar) * ASTRIDE + kc) * 2);
#pragma unroll
        for (int nb = 0; nb < 2; nb++) {
            LDSM4(b0[nb], s0 + 10240 + (uint32_t)((wn * 32 + nb * 16 + ar) * ASTRIDE + kc) * 2);
            LDSM4(b1[nb], s0 + 20480 + (uint32_t)((wn * 32 + nb * 16 + ar) * ASTRIDE + kc) * 2);
        }
#pragma unroll
        for (int mi = 0; mi < 4; mi++)
#pragma unroll
            for (int ni = 0; ni < 4; ni++) {
                MMA16816H(acc[0][mi][ni], ah[mi], b0[ni >> 1][ni & 1], b0[ni >> 1][(ni & 1) + 2]);
                MMA16816H(acc[1][mi][ni], ah[mi], b1[ni >> 1][ni & 1], b1[ni >> 1][(ni & 1) + 2]);
            }
    };

    const int KC = K / 32;
    load_stage(0, 0); CPC();
    load_stage(1, 32); CPC();

    for (int c = 0; c < KC; c++) {
        if (c + 1 < KC) { CPW(1); } else { CPW(0); }
        __syncthreads();
        if (c + 2 < KC) { load_stage((c + 2) % 3, (c + 2) * 32); CPC(); }
        uint32_t s0 = sb + (uint32_t)(c % 3) * GSTG;
        compute_ks(s0, 0);
        compute_ks(s0, 16);
    }

    // ---- LoRA k16 (T h/l x L h/l, 3 combos) using 8 of the 9 10KB regions ----
    // regions: 0=T0h 1=T0l 2=T1h 3=T1l 4=L0h 5=L0l 6=L1h 7=L1l
    __syncthreads();
    {
        int row = tid >> 1, hf = tid & 1;
        uint32_t d = (uint32_t)(row * 80 + hf * 16);
        size_t gt = (size_t)(bm + row) * RR + hf * 8;
        size_t gl = (size_t)(bn + row) * RR + hf * 8;
        *(uint4*)(dsm + 0 * 10240 + d) = *(const uint4*)(T0h + gt);
        *(uint4*)(dsm + 1 * 10240 + d) = *(const uint4*)(T0l + gt);
        *(uint4*)(dsm + 2 * 10240 + d) = *(const uint4*)(T1h + gt);
        *(uint4*)(dsm + 3 * 10240 + d) = *(const uint4*)(T1l + gt);
        *(uint4*)(dsm + 4 * 10240 + d) = *(const uint4*)(L0h + gl);
        *(uint4*)(dsm + 5 * 10240 + d) = *(const uint4*)(L0l + gl);
        *(uint4*)(dsm + 6 * 10240 + d) = *(const uint4*)(L1h + gl);
        *(uint4*)(dsm + 7 * 10240 + d) = *(const uint4*)(L1l + gl);
        __syncthreads();
#pragma unroll
        for (int o = 0; o < 2; o++) {
            uint32_t ah[4][4], al[4][4], bh[2][4], bl[2][4];
#pragma unroll
            for (int mi = 0; mi < 4; mi++) {
                uint32_t aoff = (uint32_t)((wm * 64 + mi * 16 + ar) * ASTRIDE + koff) * 2;
                LDSM4(ah[mi], sb + (2 * o + 0) * 10240 + aoff);
                LDSM4(al[mi], sb + (2 * o + 1) * 10240 + aoff);
            }
#pragma unroll
            for (int nb = 0; nb < 2; nb++) {
                uint32_t boff = (uint32_t)((wn * 32 + nb * 16 + ar) * ASTRIDE + koff) * 2;
                LDSM4(bh[nb], sb + (4 + 2 * o) * 10240 + boff);
                LDSM4(bl[nb], sb + (5 + 2 * o) * 10240 + boff);
            }
#pragma unroll
            for (int mi = 0; mi < 4; mi++)
#pragma unroll
                for (int ni = 0; ni < 4; ni++) {
                    MMA16816H(acc[o][mi][ni], ah[mi], bh[ni >> 1][ni & 1], bh[ni >> 1][(ni & 1) + 2]);
                    MMA16816H(acc[o][mi][ni], ah[mi], bl[ni >> 1][ni & 1], bl[ni >> 1][(ni & 1) + 2]);
                    MMA16816H(acc[o][mi][ni], al[mi], bh[ni >> 1][ni & 1], bh[ni >> 1][(ni & 1) + 2]);
                }
        }
    }

    // ---- epilogue: x3 = relu(y_g)*y_u as fp16 single ----
#pragma unroll
    for (int mi = 0; mi < 4; mi++) {
        int r0 = bm + wm * 64 + mi * 16 + (lane >> 2);
#pragma unroll
        for (int ni = 0; ni < 4; ni++) {
            int cl = wn * 32 + ni * 8 + (lane & 3) * 2;
            float bg0 = bias0[bn + cl], bg1 = bias0[bn + cl + 1];
            float bu0 = bias1[bn + cl], bu1 = bias1[bn + cl + 1];
#pragma unroll
            for (int h2 = 0; h2 < 2; h2++) {
                int r = r0 + h2 * 8;
                float g0 = acc[0][mi][ni][h2 * 2 + 0] + bg0;
                float g1 = acc[0][mi][ni][h2 * 2 + 1] + bg1;
                float u0 = acc[1][mi][ni][h2 * 2 + 0] + bu0;
                float u1 = acc[1][mi][ni][h2 * 2 + 1] + bu1;
                float v0 = fmaxf(g0, 0.f) * u0;
                float v1 = fmaxf(g1, 0.f) * u1;
                *(__half2*)(X3 + (size_t)r * N + bn + cl) =
                    __halves2half2(__float2half_rn(v0), __float2half_rn(v1));
            }
        }
    }
}

// ---------------- down GEMM: fp16 1-combo + LoRA ----------------
__global__ __launch_bounds__(256, 1)
void gemm_down(const __half* __restrict__ A,
               const __half* __restrict__ B,
               const __half* __restrict__ Th, const __half* __restrict__ Tl,
               const __half* __restrict__ Lh, const __half* __restrict__ Ll,
               const float* __restrict__ bias,
               float* __restrict__ C,
               int N, int K)
{
    extern __shared__ char dsm[];
    const uint32_t sb = smem_u32(dsm);
    const int tid = threadIdx.x, lane = tid & 31, wid = tid >> 5;
    const int wm = wid >> 2, wn = wid & 3;
    const int bm = blockIdx.y * 128, bn = blockIdx.x * 128;

    float acc[4][4][4];
#pragma unroll
    for (int a = 0; a < 4; a++)
#pragma unroll
        for (int b = 0; b < 4; b++)
#pragma unroll
            for (int c = 0; c < 4; c++) acc[a][b][c] = 0.f;

    auto load_stage = [&](int st, int k0) {
        uint32_t s0 = sb + (uint32_t)st * DSTG;
#pragma unroll
        for (int j = 0; j < 2; j++) {                 // A: 512 chunks
            int c = tid + j * 256;
            int row = c >> 2;
            CPA(s0 + (uint32_t)(row * 80 + (c & 3) * 16),
                A + (size_t)(bm + row) * K + k0 + (c & 3) * 8);
        }
#pragma unroll
        for (int j = 0; j < 2; j++) {                 // B: 512 chunks
            int c = tid + j * 256;
            int row = c >> 2;
            CPA(s0 + 10240 + (uint32_t)(row * 80 + (c & 3) * 16),
                B + (size_t)(bn + row) * K + k0 + (c & 3) * 8);
        }
    };

    const int ar = lane & 15;
    const int koff = (lane >> 4) * 8;

    auto compute_ks = [&](uint32_t s0, int kbase) {
        const int kc = kbase + koff;
        uint32_t ah[4][4], bb[2][4];
#pragma unroll
        for (int mi = 0; mi < 4; mi++)
            LDSM4(ah[mi], s0 + (uint32_t)((wm * 64 + mi * 16 + ar) * ASTRIDE + kc) * 2);
#pragma unroll
        for (int nb = 0; nb < 2; nb++)
            LDSM4(bb[nb], s0 + 10240 + (uint32_t)((wn * 32 + nb * 16 + ar) * ASTRIDE + kc) * 2);
#pragma unroll
        for (int mi = 0; mi < 4; mi++)
#pragma unroll
            for (int ni = 0; ni < 4; ni++)
                MMA16816H(acc[mi][ni], ah[mi], bb[ni >> 1][ni & 1], bb[ni >> 1][(ni & 1) + 2]);
    };

    const int KC = K / 32;
    load_stage(0, 0); CPC();
    load_stage(1, 32); CPC();

    for (int c = 0; c < KC; c++) {
        if (c + 1 < KC) { CPW(1); } else { CPW(0); }
        __syncthreads();
        if (c + 2 < KC) { load_stage((c + 2) % 3, (c + 2) * 32); CPC(); }
        uint32_t s0 = sb + (uint32_t)(c % 3) * DSTG;
        compute_ks(s0, 0);
        compute_ks(s0, 16);
    }

    // ---- LoRA k16 (T h/l x L h/l, 3 combos); regions: 0=A0(Th) 1=B0(Lh) 2=A1(Tl) 3=B1(Ll) ----
    __syncthreads();
    {
        int row = tid >> 1, hf = tid & 1;
        uint32_t d = (uint32_t)(row * 80 + hf * 16);
        size_t gt = (size_t)(bm + row) * RR + hf * 8;
        size_t gl = (size_t)(bn + row) * RR + hf * 8;
        *(uint4*)(dsm + 0 * 10240 + d) = *(const uint4*)(Th + gt);
        *(uint4*)(dsm + 2 * 10240 + d) = *(const uint4*)(Tl + gt);
        *(uint4*)(dsm + 1 * 10240 + d) = *(const uint4*)(Lh + gl);
        *(uint4*)(dsm + 3 * 10240 + d) = *(const uint4*)(Ll + gl);
        __syncthreads();

        uint32_t ah[4][4], al[4][4], bh[2][4], bl[2][4];
#pragma unroll
        for (int mi = 0; mi < 4; mi++) {
            uint32_t aoff = (uint32_t)((wm * 64 + mi * 16 + ar) * ASTRIDE + koff) * 2;
            LDSM4(ah[mi], sb + 0 * 10240 + aoff);
            LDSM4(al[mi], sb + 2 * 10240 + aoff);
        }
#pragma unroll
        for (int nb = 0; nb < 2; nb++) {
            uint32_t boff = (uint32_t)((wn * 32 + nb * 16 + ar) * ASTRIDE + koff) * 2;
            LDSM4(bh[nb], sb + 1 * 10240 + boff);
            LDSM4(bl[nb], sb + 3 * 10240 + boff);
        }
#pragma unroll
        for (int mi = 0; mi < 4; mi++)
#pragma unroll
            for (int ni = 0; ni < 4; ni++) {
                MMA16816H(acc[mi][ni], ah[mi], bh[ni >> 1][ni & 1], bh[ni >> 1][(ni & 1) + 2]);
                MMA16816H(acc[mi][ni], ah[mi], bl[ni >> 1][ni & 1], bl[ni >> 1][(ni & 1) + 2]);
                MMA16816H(acc[mi][ni], al[mi], bh[ni >> 1][ni & 1], bh[ni >> 1][(ni & 1) + 2]);
            }
    }

    // ---- epilogue ----
#pragma unroll
    for (int mi = 0; mi < 4; mi++) {
        int r0 = bm + wm * 64 + mi * 16 + (lane >> 2);
#pragma unroll
        for (int ni = 0; ni < 4; ni++) {
            int cl = wn * 32 + ni * 8 + (lane & 3) * 2;
            float b0 = bias[bn + cl], b1 = bias[bn + cl + 1];
#pragma unroll
            for (int h2 = 0; h2 < 2; h2++) {
                int r = r0 + h2 * 8;
                size_t off = (size_t)r * N + bn + cl;
                *(float2*)(C + off) = make_float2(acc[mi][ni][h2 * 2 + 0] + b0,
                                                  acc[mi][ni][h2 * 2 + 1] + b1);
            }
        }
    }
}

// ---------------- launcher ----------------
extern "C" void kernel_launch(void* const* d_in, const int* in_sizes, int n_in,
                              void* d_out, int out_size)
{
    const float* x1     = (const float*)d_in[0];
    const float* w_gate = (const float*)d_in[1];
    const float* b_gate = (const float*)d_in[2];
    const float* wga    = (const float*)d_in[3];
    const float* wgb    = (const float*)d_in[4];
    const float* w_up   = (const float*)d_in[5];
    const float* b_up   = (const float*)d_in[6];
    const float* wua    = (const float*)d_in[7];
    const float* wub    = (const float*)d_in[8];
    const float* w_down = (const float*)d_in[9];
    const float* b_down = (const float*)d_in[10];
    const float* wda    = (const float*)d_in[11];
    const float* wdb    = (const float*)d_in[12];
    float* out = (float*)d_out;

#define SYM(p, s) void* p; cudaGetSymbolAddress(&p, s)
    SYM(x1q, g_x1q); SYM(x3q, g_x3q);
    SYM(wgT, g_wgT); SYM(wuT, g_wuT); SYM(wdT, g_wdT);
    SYM(lgh, g_lgh); SYM(lgl, g_lgl); SYM(luh, g_luh); SYM(lul, g_lul);
    SYM(ldh, g_ldh); SYM(ldl, g_ldl);
    SYM(tgh, g_tgh); SYM(tgl, g_tgl); SYM(tuh, g_tuh); SYM(tul, g_tul);
    SYM(tdh, g_tdh); SYM(tdl, g_tdl);
    SYM(gaTh, g_gaTh); SYM(gaTl, g_gaTl); SYM(uaTh, g_uaTh); SYM(uaTl, g_uaTl);
    SYM(daTh, g_daTh); SYM(daTl, g_daTl);
    SYM(Tgf, g_Tgf); SYM(Tuf, g_Tuf); SYM(Tdf, g_Tdf);
#undef SYM
#define HF(p) ((__half*)(p))
#define F32(p) ((float*)(p))

    cudaFuncSetAttribute(gemm_gateup, cudaFuncAttributeMaxDynamicSharedMemorySize, GATEUP_SMEM);
    cudaFuncSetAttribute(gemm_down,   cudaFuncAttributeMaxDynamicSharedMemorySize, DOWN_SMEM);

    // conversions / transposes
    convert_f16<<<(int)((size_t)MTOK * DDIM / 1024), 256>>>(x1, (size_t)MTOK * DDIM, HF(x1q));
    transpose_f16<<<dim3(FDIM / 32, DDIM / 32), dim3(32, 8)>>>(w_gate, DDIM, FDIM, HF(wgT));
    transpose_f16<<<dim3(FDIM / 32, DDIM / 32), dim3(32, 8)>>>(w_up,   DDIM, FDIM, HF(wuT));
    transpose_f16<<<dim3(DDIM / 32, FDIM / 32), dim3(32, 8)>>>(w_down, FDIM, DDIM, HF(wdT));
    lb_transpose_f16<<<FDIM / 256, 256>>>(wgb, FDIM, HF(lgh), HF(lgl));
    lb_transpose_f16<<<FDIM / 256, 256>>>(wub, FDIM, HF(luh), HF(lul));
    lb_transpose_f16<<<DDIM / 256, 256>>>(wdb, DDIM, HF(ldh), HF(ldl));
    at_transpose_f16<<<DDIM / 256, 256>>>(wga, DDIM, HF(gaTh), HF(gaTl));
    at_transpose_f16<<<DDIM / 256, 256>>>(wua, DDIM, HF(uaTh), HF(uaTl));
    at_transpose_f16<<<FDIM / 256, 256>>>(wda, FDIM, HF(daTh), HF(daTl));
    zero_t<<<(MTOK * RR) / 256, 256>>>(F32(Tgf), F32(Tuf), F32(Tdf));

    // LoRA-A gate + up
    lora_gemm<<<dim3(2, MTOK / 128), 256>>>(HF(x1q), HF(gaTh), HF(gaTl), F32(Tgf), DDIM, DDIM / 2);
    lora_gemm<<<dim3(2, MTOK / 128), 256>>>(HF(x1q), HF(uaTh), HF(uaTl), F32(Tuf), DDIM, DDIM / 2);
    convert_hl_f16<<<(MTOK * RR) / 1024, 256>>>(F32(Tgf), MTOK * RR, HF(tgh), HF(tgl));
    convert_hl_f16<<<(MTOK * RR) / 1024, 256>>>(F32(Tuf), MTOK * RR, HF(tuh), HF(tul));

    // fused gate+up (1-combo dual-output) -> x3 fp16 single
    gemm_gateup<<<dim3(FDIM / 128, MTOK / 128), 256, GATEUP_SMEM>>>(
        HF(x1q), HF(wgT), HF(wuT),
        HF(tgh), HF(tgl), HF(tuh), HF(tul),
        HF(lgh), HF(lgl), HF(luh), HF(lul),
        b_gate, b_up,
        HF(x3q), FDIM, DDIM);

    // LoRA-A down
    lora_gemm<<<dim3(4, MTOK / 128), 256>>>(HF(x3q), HF(daTh), HF(daTl), F32(Tdf), FDIM, FDIM / 4);
    convert_hl_f16<<<(MTOK * RR) / 1024, 256>>>(F32(Tdf), MTOK * RR, HF(tdh), HF(tdl));

    // down GEMM (1-combo) -> out
    gemm_down<<<dim3(DDIM / 128, MTOK / 128), 256, DOWN_SMEM>>>(
        HF(x3q), HF(wdT),
        HF(tdh), HF(tdl), HF(ldh), HF(ldl),
        b_down, out, DDIM, FDIM);
}